// round 4
// baseline (speedup 1.0000x reference)
#include <cuda_runtime.h>
#include <cfloat>
#include <math.h>

// ---------------- problem constants ----------------
#define BB    4
#define NN    2048
#define KNB   21
#define CIN   64
#define CO    256
#define HEADS 7
#define WCH   64
#define FUSC  (HEADS*WCH)          /* 448 */
#define MTOT  (BB*NN)              /* 8192 */
#define RTOT  (MTOT*KNB)           /* 172032 */
#define EPSB  1e-5f

// ---------------- scratch (device globals; allocation-free) ----------------
__device__ int    g_idx[RTOT];                       // KNN indices
__device__ float  g_ft[MTOT*CIN];                    // f transposed  [B*N,64]
__device__ float  g_gin[RTOT*128];                   // gathered feat_in [R,128]
__device__ float  g_act[(size_t)RTOT*CO];            // pre-BN geo|fea  [R,256]
__device__ float  g_featv[MTOT*CO];                  // feature_
__device__ float  g_x[MTOT*CO];
__device__ float  g_q[MTOT*CO];
__device__ float  g_k[MTOT*CO];
__device__ float  g_v[MTOT*CO];
__device__ float  g_S[(size_t)BB*HEADS*NN*NN];       // attention scores
__device__ float  g_O[MTOT*FUSC];                    // attention output concat
__device__ float  g_fp[MTOT*CO];                     // gemm temp (fus pre / mlp pre)
__device__ float  g_f2[MTOT*CO];                     // feature__ (residual)
__device__ float  g_y[MTOT*CO];                      // layernorm out
__device__ double g_part[128*2*CO];                  // BN block partials
__device__ float  g_msc[6*2*CO];                     // per-stage mean/istd

// =====================================================================
// KNN: one block per query point; iterative argmin selection (21x)
// =====================================================================
__global__ void knn_kernel(const float* __restrict__ xyz)
{
    __shared__ float d2s[NN];
    __shared__ float rv[256];
    __shared__ int   ri[256];
    int m = blockIdx.x;
    int b = m >> 11;
    int t = threadIdx.x;
    const float* base = xyz + (size_t)(b << 11) * 3;

    float qx = xyz[m*3+0], qy = xyz[m*3+1], qz = xyz[m*3+2];
    float sqq = qx*qx + qy*qy + qz*qz;

    for (int j = t; j < NN; j += 256) {
        float px = base[j*3+0], py = base[j*3+1], pz = base[j*3+2];
        float sqp = px*px + py*py + pz*pz;
        float dot = qx*px + qy*py + qz*pz;
        d2s[j] = sqq + sqp - 2.0f*dot;
    }
    __syncthreads();

    for (int it = 0; it < KNB; it++) {
        float bv = FLT_MAX; int bi = 0x3fffffff;
        for (int j = t; j < NN; j += 256) {
            float v = d2s[j];
            if (v < bv) { bv = v; bi = j; }   // ascending scan: strict < keeps lowest idx
        }
        rv[t] = bv; ri[t] = bi;
        __syncthreads();
        for (int s = 128; s; s >>= 1) {
            if (t < s) {
                float ov = rv[t+s]; int oi = ri[t+s];
                if (ov < rv[t] || (ov == rv[t] && oi < ri[t])) { rv[t] = ov; ri[t] = oi; }
            }
            __syncthreads();
        }
        if (t == 0) { g_idx[(size_t)m*KNB + it] = ri[0]; d2s[ri[0]] = FLT_MAX; }
        __syncthreads();
    }
}

// =====================================================================
// transpose f [B,Cin,N] -> ft [B*N, Cin]
// =====================================================================
__global__ void transpose_f(const float* __restrict__ f)
{
    __shared__ float tile[32][33];
    int b  = blockIdx.z;
    int n0 = blockIdx.x * 32;
    int c0 = blockIdx.y * 32;
    int tx = threadIdx.x, ty = threadIdx.y;   // 32 x 8
#pragma unroll
    for (int i = 0; i < 32; i += 8)
        tile[ty+i][tx] = f[((size_t)b*CIN + c0 + ty + i)*NN + n0 + tx];
    __syncthreads();
#pragma unroll
    for (int i = 0; i < 32; i += 8)
        g_ft[((size_t)b*NN + n0 + ty + i)*CIN + c0 + tx] = tile[tx][ty+i];
}

// =====================================================================
// geo branch pre-activation: g_act[r, 0..127]
// =====================================================================
__global__ void geo_pre(const float* __restrict__ xyz, const float* __restrict__ Wg)
{
    int m = blockIdx.x;           // point
    int c = threadIdx.x;          // out channel (128)
    int b = m >> 11;
    float w0 = Wg[c*6+0], w1 = Wg[c*6+1], w2 = Wg[c*6+2];
    float w3 = Wg[c*6+3], w4 = Wg[c*6+4], w5 = Wg[c*6+5];
    float cx = xyz[m*3+0], cy = xyz[m*3+1], cz = xyz[m*3+2];
    float base = w0*cx + w1*cy + w2*cz;
    for (int k = 0; k < KNB; k++) {
        int nb = g_idx[(size_t)m*KNB + k];
        const float* pp = xyz + (size_t)((b << 11) + nb)*3;
        float dx = pp[0]-cx, dy = pp[1]-cy, dz = pp[2]-cz;
        g_act[((size_t)m*KNB + k)*CO + c] = base + w3*dx + w4*dy + w5*dz;
    }
}

// =====================================================================
// gather feat_in [R,128] = [ft[neighbor] | ft[center]]
// =====================================================================
__global__ void gather_feat()
{
    size_t r = (size_t)blockIdx.x * 2 + (threadIdx.x >> 7);
    int c = threadIdx.x & 127;
    size_t m = r / KNB;
    int b = (int)(m >> 11);
    float v;
    if (c < 64) {
        int nb = g_idx[r];
        v = g_ft[((size_t)(b << 11) + nb)*CIN + c];
    } else {
        v = g_ft[m*CIN + (c - 64)];
    }
    g_gin[r*128 + c] = v;
}

// =====================================================================
// Tiled SGEMM: C[m,n] = sum_k A[m,k] * B(k,n)
//   BT=true : B is [Ncol,K] row-major (weights / K^T)
//   BT=false: B is [K,Ncol] row-major
// 64x64 tile, BK=16, 256 threads, 4x4 micro-tile. Batched via blockIdx.z.
// All dims assumed multiples of tile sizes (checked at call sites).
// =====================================================================
#define BM 64
#define BN 64
#define BK 16

template<bool BT>
__global__ void sgemm_kernel(const float* __restrict__ A, const float* __restrict__ B,
                             float* __restrict__ C,
                             int M, int Ncol, int K, int lda, int ldb, int ldc,
                             long sAb, long sAh, long sBb, long sBh,
                             long sCb, long sCh, int hdiv)
{
    int z  = blockIdx.z;
    int zb = z / hdiv, zh = z - zb*hdiv;
    A += (size_t)zb*sAb + (size_t)zh*sAh;
    B += (size_t)zb*sBb + (size_t)zh*sBh;
    C += (size_t)zb*sCb + (size_t)zh*sCh;

    __shared__ __align__(16) float As[BK][BM+4];
    __shared__ __align__(16) float Bs[BK][BN+4];

    int tid = threadIdx.x;
    int tx = tid & 15, ty = tid >> 4;
    int m0 = blockIdx.y * BM;
    int n0 = blockIdx.x * BN;

    int arow = tid >> 2;          // 0..63
    int akq  = (tid & 3) * 4;     // k sub-offset

    float acc[4][4];
#pragma unroll
    for (int i = 0; i < 4; i++)
#pragma unroll
        for (int j = 0; j < 4; j++) acc[i][j] = 0.0f;

    for (int k0 = 0; k0 < K; k0 += BK) {
        float4 av = *(const float4*)(A + (size_t)(m0 + arow)*lda + k0 + akq);
        As[akq+0][arow] = av.x;
        As[akq+1][arow] = av.y;
        As[akq+2][arow] = av.z;
        As[akq+3][arow] = av.w;
        if (BT) {
            float4 bv = *(const float4*)(B + (size_t)(n0 + arow)*ldb + k0 + akq);
            Bs[akq+0][arow] = bv.x;
            Bs[akq+1][arow] = bv.y;
            Bs[akq+2][arow] = bv.z;
            Bs[akq+3][arow] = bv.w;
        } else {
            int bk  = tid >> 4;          // 0..15
            int bnq = (tid & 15) * 4;    // 0..60
            float4 bv = *(const float4*)(B + (size_t)(k0 + bk)*ldb + n0 + bnq);
            *(float4*)&Bs[bk][bnq] = bv;
        }
        __syncthreads();
#pragma unroll
        for (int kk = 0; kk < BK; kk++) {
            float4 a4 = *(const float4*)&As[kk][tx*4];
            float4 b4 = *(const float4*)&Bs[kk][ty*4];
            float a[4] = {a4.x, a4.y, a4.z, a4.w};
            float bb[4] = {b4.x, b4.y, b4.z, b4.w};
#pragma unroll
            for (int i = 0; i < 4; i++)
#pragma unroll
                for (int j = 0; j < 4; j++)
                    acc[i][j] = fmaf(bb[i], a[j], acc[i][j]);
        }
        __syncthreads();
    }

#pragma unroll
    for (int j = 0; j < 4; j++) {
        int m = m0 + tx*4 + j;
        float4 o = make_float4(acc[0][j], acc[1][j], acc[2][j], acc[3][j]);
        *(float4*)(C + (size_t)m*ldc + n0 + ty*4) = o;
    }
}

// =====================================================================
// BN statistics: two-pass, deterministic (double partials + serial combine)
// X is [rows, 256]; msc gets mean[0..255], istd[256..511]
// =====================================================================
__global__ void bn_stats_partial(const float* __restrict__ X, long rows)
{
    int c = threadIdx.x;                      // 256 channels
    long per = (rows + gridDim.x - 1) / gridDim.x;
    long r0 = (long)blockIdx.x * per;
    long r1 = r0 + per; if (r1 > rows) r1 = rows;
    double s = 0.0, s2 = 0.0;
    for (long r = r0; r < r1; r++) {
        float v = X[r*CO + c];
        s  += (double)v;
        s2 += (double)v * (double)v;
    }
    g_part[((size_t)blockIdx.x*2 + 0)*CO + c] = s;
    g_part[((size_t)blockIdx.x*2 + 1)*CO + c] = s2;
}

__global__ void bn_stats_final(int nblocks, long rows, float* msc)
{
    int c = threadIdx.x;
    double s = 0.0, s2 = 0.0;
    for (int i = 0; i < nblocks; i++) {
        s  += g_part[((size_t)i*2 + 0)*CO + c];
        s2 += g_part[((size_t)i*2 + 1)*CO + c];
    }
    double mean = s / (double)rows;
    double var  = s2 / (double)rows - mean*mean;
    msc[c]      = (float)mean;
    msc[CO + c] = (float)(1.0 / sqrt(var + (double)EPSB));
}

// =====================================================================
// branch apply: BN(geo|fea) + relu + maxpool over K  -> feature_
// =====================================================================
__global__ void branch_apply(const float* msc,
                             const float* __restrict__ g_geo, const float* __restrict__ b_geo,
                             const float* __restrict__ g_fea, const float* __restrict__ b_fea)
{
    int m = blockIdx.x;
    int c = threadIdx.x;
    float mean = msc[c], istd = msc[CO + c];
    float ga = (c < 128) ? g_geo[c] : g_fea[c - 128];
    float be = (c < 128) ? b_geo[c] : b_fea[c - 128];
    float sc = istd * ga;
    float best = -FLT_MAX;
    const float* base = g_act + (size_t)m*KNB*CO + c;
#pragma unroll 3
    for (int k = 0; k < KNB; k++) {
        float zv = base[(size_t)k*CO];
        float y = (zv - mean) * sc + be;
        y = fmaxf(y, 0.0f);
        best = fmaxf(best, y);
    }
    g_featv[(size_t)m*CO + c] = best;
}

// =====================================================================
// generic BN apply: out = [relu]((in-mean)*istd*g + b) [+ res]
// =====================================================================
__global__ void bn_apply(const float* __restrict__ in, float* __restrict__ out,
                         const float* msc,
                         const float* __restrict__ gamma, const float* __restrict__ beta,
                         const float* __restrict__ res, int do_relu)
{
    size_t i = (size_t)blockIdx.x * blockDim.x + threadIdx.x;
    int c = (int)(i & (CO-1));
    float y = (in[i] - msc[c]) * msc[CO + c] * gamma[c] + beta[c];
    if (do_relu) y = fmaxf(y, 0.0f);
    if (res) y += res[i];
    out[i] = y;
}

// =====================================================================
// softmax over rows of 2048 (in place)
// =====================================================================
__global__ void softmax_kernel(float* __restrict__ S)
{
    size_t row = blockIdx.x;
    float* p = S + row * NN;
    int t = threadIdx.x;
    __shared__ float red[256];

    float mx = -FLT_MAX;
    for (int j = t; j < NN; j += 256) mx = fmaxf(mx, p[j]);
    red[t] = mx; __syncthreads();
    for (int s = 128; s; s >>= 1) { if (t < s) red[t] = fmaxf(red[t], red[t+s]); __syncthreads(); }
    mx = red[0]; __syncthreads();

    float sum = 0.0f;
    for (int j = t; j < NN; j += 256) { float e = expf(p[j] - mx); p[j] = e; sum += e; }
    red[t] = sum; __syncthreads();
    for (int s = 128; s; s >>= 1) { if (t < s) red[t] += red[t+s]; __syncthreads(); }
    float inv = 1.0f / red[0];

    for (int j = t; j < NN; j += 256) p[j] *= inv;
}

// =====================================================================
// LayerNorm over channels (256) per row
// =====================================================================
__global__ void layernorm_kernel(const float* __restrict__ X, float* __restrict__ Y,
                                 const float* __restrict__ g, const float* __restrict__ b)
{
    int m = blockIdx.x, c = threadIdx.x;
    __shared__ float red[256];
    float v = X[(size_t)m*CO + c];
    red[c] = v; __syncthreads();
    for (int s = 128; s; s >>= 1) { if (c < s) red[c] += red[c+s]; __syncthreads(); }
    float mean = red[0] * (1.0f/CO); __syncthreads();
    float d = v - mean;
    red[c] = d*d; __syncthreads();
    for (int s = 128; s; s >>= 1) { if (c < s) red[c] += red[c+s]; __syncthreads(); }
    float var = red[0] * (1.0f/CO);
    Y[(size_t)m*CO + c] = d * rsqrtf(var + EPSB) * g[c] + b[c];
}

// =====================================================================
// final: out[b,c,n] = f2 + mlp_pre + bias  (transposed write)
// =====================================================================
__global__ void final_out(const float* __restrict__ bias, float* __restrict__ out)
{
    __shared__ float tile[32][33];
    int b  = blockIdx.z;
    int n0 = blockIdx.x * 32;
    int c0 = blockIdx.y * 32;
    int tx = threadIdx.x, ty = threadIdx.y;   // 32 x 8
#pragma unroll
    for (int i = 0; i < 32; i += 8) {
        int n = n0 + ty + i, c = c0 + tx;
        size_t src = ((size_t)b*NN + n)*CO + c;
        tile[ty+i][tx] = g_f2[src] + g_fp[src] + bias[c];
    }
    __syncthreads();
#pragma unroll
    for (int i = 0; i < 32; i += 8) {
        int c = c0 + ty + i, n = n0 + tx;
        out[((size_t)b*CO + c)*NN + n] = tile[tx][ty+i];
    }
}

// =====================================================================
// host side
// =====================================================================
static void run_bn(const float* X, long rows, float* msc, int nblocks)
{
    bn_stats_partial<<<nblocks, 256>>>(X, rows);
    bn_stats_final<<<1, 256>>>(nblocks, rows, msc);
}

extern "C" void kernel_launch(void* const* d_in, const int* in_sizes, int n_in,
                              void* d_out, int out_size)
{
    const float* xyz    = (const float*)d_in[0];
    const float* f      = (const float*)d_in[1];
    const float* W_geo  = (const float*)d_in[2];
    const float* gg     = (const float*)d_in[3];
    const float* bg     = (const float*)d_in[4];
    const float* W_feat = (const float*)d_in[5];
    const float* gf     = (const float*)d_in[6];
    const float* bf     = (const float*)d_in[7];
    const float* g_bn   = (const float*)d_in[8];
    const float* b_bn   = (const float*)d_in[9];
    const float* W_q    = (const float*)d_in[10];
    const float* gq     = (const float*)d_in[11];
    const float* bq     = (const float*)d_in[12];
    const float* W_k    = (const float*)d_in[13];
    const float* gk     = (const float*)d_in[14];
    const float* bk     = (const float*)d_in[15];
    const float* W_v    = (const float*)d_in[16];
    const float* gv     = (const float*)d_in[17];
    const float* bv     = (const float*)d_in[18];
    const float* W_fus  = (const float*)d_in[19];
    /* d_in[20] bias_fus: cancels inside BN (pure mean shift) */
    const float* gfu    = (const float*)d_in[21];
    const float* bfu    = (const float*)d_in[22];
    const float* g_ln   = (const float*)d_in[23];
    const float* b_ln   = (const float*)d_in[24];
    const float* W_mlp  = (const float*)d_in[25];
    const float* b_mlp  = (const float*)d_in[26];
    float* out = (float*)d_out;

    float *p_ft, *p_gin, *p_act, *p_featv, *p_x, *p_q, *p_k, *p_v;
    float *p_S, *p_O, *p_fp, *p_f2, *p_y, *p_msc;
    cudaGetSymbolAddress((void**)&p_ft,    g_ft);
    cudaGetSymbolAddress((void**)&p_gin,   g_gin);
    cudaGetSymbolAddress((void**)&p_act,   g_act);
    cudaGetSymbolAddress((void**)&p_featv, g_featv);
    cudaGetSymbolAddress((void**)&p_x,     g_x);
    cudaGetSymbolAddress((void**)&p_q,     g_q);
    cudaGetSymbolAddress((void**)&p_k,     g_k);
    cudaGetSymbolAddress((void**)&p_v,     g_v);
    cudaGetSymbolAddress((void**)&p_S,     g_S);
    cudaGetSymbolAddress((void**)&p_O,     g_O);
    cudaGetSymbolAddress((void**)&p_fp,    g_fp);
    cudaGetSymbolAddress((void**)&p_f2,    g_f2);
    cudaGetSymbolAddress((void**)&p_y,     g_y);
    cudaGetSymbolAddress((void**)&p_msc,   g_msc);

    // ---- 1. KNN + transpose + gathers ----
    knn_kernel<<<MTOT, 256>>>(xyz);
    transpose_f<<<dim3(NN/32, CIN/32, BB), dim3(32,8)>>>(f);
    geo_pre<<<MTOT, 128>>>(xyz, W_geo);
    gather_feat<<<RTOT/2, 256>>>();

    // ---- 2. feat-branch GEMM: [R,128] x W_feat^T -> g_act[:,128:256]
    sgemm_kernel<true><<<dim3(128/BN, RTOT/BM, 1), 256>>>(
        p_gin, W_feat, p_act + 128, RTOT, 128, 128, 128, 128, CO,
        0,0,0,0,0,0, 1);

    // ---- 3. branch BN + relu + maxpool -> feature_
    run_bn(p_act, RTOT, p_msc + 0*512, 128);
    branch_apply<<<MTOT, 256>>>(p_msc + 0*512, gg, bg, gf, bf);

    // ---- 4. BatchNorm1d -> x
    run_bn(p_featv, MTOT, p_msc + 1*512, 32);
    bn_apply<<<MTOT, 256>>>(p_featv, p_x, p_msc + 1*512, g_bn, b_bn, nullptr, 0);

    // ---- 5. q/k/v = relu(bn(x @ W^T))
    sgemm_kernel<true><<<dim3(CO/BN, MTOT/BM, 1), 256>>>(p_x, W_q, p_q,
        MTOT, CO, CO, CO, CO, CO, 0,0,0,0,0,0, 1);
    sgemm_kernel<true><<<dim3(CO/BN, MTOT/BM, 1), 256>>>(p_x, W_k, p_k,
        MTOT, CO, CO, CO, CO, CO, 0,0,0,0,0,0, 1);
    sgemm_kernel<true><<<dim3(CO/BN, MTOT/BM, 1), 256>>>(p_x, W_v, p_v,
        MTOT, CO, CO, CO, CO, CO, 0,0,0,0,0,0, 1);
    run_bn(p_q, MTOT, p_msc + 2*512, 32);
    bn_apply<<<MTOT, 256>>>(p_q, p_q, p_msc + 2*512, gq, bq, nullptr, 1);
    run_bn(p_k, MTOT, p_msc + 3*512, 32);
    bn_apply<<<MTOT, 256>>>(p_k, p_k, p_msc + 3*512, gk, bk, nullptr, 1);
    run_bn(p_v, MTOT, p_msc + 4*512, 32);
    bn_apply<<<MTOT, 256>>>(p_v, p_v, p_msc + 4*512, gv, bv, nullptr, 1);

    // ---- 6. attention: S = qh kh^T  (28 batched 2048x2048x64)
    const long NN2 = (long)NN * NN;
    sgemm_kernel<true><<<dim3(NN/BN, NN/BM, BB*HEADS), 256>>>(
        p_q, p_k, p_S, NN, NN, WCH, CO, CO, NN,
        (long)NN*CO, 32L, (long)NN*CO, 32L, HEADS*NN2, NN2, HEADS);

    softmax_kernel<<<BB*HEADS*NN, 256>>>(p_S);

    // ---- 7. O = A @ vh  (28 batched 2048x64x2048), concat into [M,448]
    sgemm_kernel<false><<<dim3(WCH/BN, NN/BM, BB*HEADS), 256>>>(
        p_S, p_v, p_O, NN, WCH, NN, NN, CO, FUSC,
        HEADS*NN2, NN2, (long)NN*CO, 32L, (long)NN*FUSC, (long)WCH, HEADS);

    // ---- 8. fus = relu(bn(O @ W_fus^T)) + feature_  -> feature__
    sgemm_kernel<true><<<dim3(CO/BN, MTOT/BM, 1), 256>>>(p_O, W_fus, p_fp,
        MTOT, CO, FUSC, FUSC, FUSC, CO, 0,0,0,0,0,0, 1);
    run_bn(p_fp, MTOT, p_msc + 5*512, 32);
    bn_apply<<<MTOT, 256>>>(p_fp, p_f2, p_msc + 5*512, gfu, bfu, p_featv, 1);

    // ---- 9. layernorm + mlp + residual + transpose out
    layernorm_kernel<<<MTOT, 256>>>(p_f2, p_y, g_ln, b_ln);
    sgemm_kernel<true><<<dim3(CO/BN, MTOT/BM, 1), 256>>>(p_y, W_mlp, p_fp,
        MTOT, CO, CO, CO, CO, CO, 0,0,0,0,0,0, 1);
    final_out<<<dim3(NN/32, CO/32, BB), dim3(32,8)>>>(b_mlp, out);

    (void)in_sizes; (void)n_in; (void)out_size;
}

// round 6
// speedup vs baseline: 1.3690x; 1.3690x over previous
#include <cuda_runtime.h>
#include <cuda_bf16.h>
#include <cfloat>
#include <math.h>
#include <cstdint>

// tcgen05 is arch-SPECIFIC: only legal under sm_103a feature target.
// The harness also assembles a generic compute_103 pass, so gate all
// tcgen05 device code and give that pass a correct SIMT fallback body.
#if defined(__CUDA_ARCH__) && defined(__CUDA_ARCH_FEAT_SM103_ALL)
#define HAS_TC 1
#else
#define HAS_TC 0
#endif

// ---------------- problem constants ----------------
#define BB    4
#define NN    2048
#define KNB   21
#define CIN   64
#define CO    256
#define HEADS 7
#define WCH   64
#define FUSC  (HEADS*WCH)          /* 448 */
#define MTOT  (BB*NN)              /* 8192 */
#define RTOT  (MTOT*KNB)           /* 172032 */
#define EPSB  1e-5f

// ---------------- scratch (device globals; allocation-free) ----------------
__device__ int    g_idx[RTOT];
__device__ float  g_ft[MTOT*CIN];
__device__ float  g_gin[RTOT*128];
__device__ float  g_act[(size_t)RTOT*CO];
__device__ float  g_featv[MTOT*CO];
__device__ float  g_x[MTOT*CO];
__device__ float  g_q[MTOT*CO];
__device__ float  g_k[MTOT*CO];
__device__ float  g_v[MTOT*CO];
__device__ float  g_S[(size_t)BB*HEADS*NN*NN];
__device__ float  g_O[MTOT*FUSC];
__device__ float  g_fp[MTOT*CO];
__device__ float  g_f2[MTOT*CO];
__device__ float  g_y[MTOT*CO];
__device__ double g_part[128*2*CO];
__device__ float  g_msc[6*2*CO];
// bf16 split operands for tensor-core attention
__device__ __nv_bfloat16 g_qh[MTOT*CO];
__device__ __nv_bfloat16 g_ql[MTOT*CO];
__device__ __nv_bfloat16 g_kh[MTOT*CO];
__device__ __nv_bfloat16 g_kl[MTOT*CO];
__device__ __nv_bfloat16 g_vth[(size_t)BB*HEADS*WCH*NN];   // v transposed per head [z][c][m]
__device__ __nv_bfloat16 g_vtl[(size_t)BB*HEADS*WCH*NN];

// ---------------- ptx helpers ----------------
__device__ __forceinline__ uint32_t smem_u32(const void* p) {
    uint32_t a;
    asm("{ .reg .u64 t; cvta.to.shared.u64 t, %1; cvt.u32.u64 %0, t; }" : "=r"(a) : "l"(p));
    return a;
}
__device__ __forceinline__ uint32_t swz(uint32_t o) { return o ^ ((o >> 3) & 0x70); }

#if HAS_TC
__device__ __forceinline__ uint32_t elect_one_pred() {
    uint32_t pred;
    asm volatile("{\n\t.reg .pred p;\n\telect.sync _|p, 0xFFFFFFFF;\n\tselp.b32 %0, 1, 0, p;\n\t}" : "=r"(pred));
    return pred;
}

#define MBARRIER_INIT(addr, cnt) \
    asm volatile("mbarrier.init.shared.b64 [%0], %1;" :: "r"((uint32_t)(addr)), "r"((uint32_t)(cnt)) : "memory")

#define MBARRIER_WAIT_PARITY(mbar_smem_addr, phase_parity) do { \
    uint32_t _mbar = (uint32_t)(mbar_smem_addr); \
    uint32_t _parity = (uint32_t)(phase_parity); \
    uint32_t _done; \
    asm volatile("{\n\t.reg .pred p;\n\t" \
        "mbarrier.try_wait.parity.acquire.cta.shared::cta.b64 p, [%1], %2;\n\t" \
        "selp.b32 %0, 1, 0, p;\n\t}" : "=r"(_done) : "r"(_mbar), "r"(_parity) : "memory"); \
    if (!_done) { \
        asm volatile("{\n\t.reg .pred P1;\n\t" \
            "WAIT_LOOP_%=:\n\t" \
            "mbarrier.try_wait.parity.acquire.cta.shared::cta.b64 P1, [%0], %1, 0x989680;\n\t" \
            "@P1 bra.uni WAIT_DONE_%=;\n\t" \
            "bra.uni WAIT_LOOP_%=;\n\t" \
            "WAIT_DONE_%=:\n\t}" :: "r"(_mbar), "r"(_parity) : "memory"); \
    } \
} while(0)

#define TCGEN05_ALLOC(sm, n) \
    asm volatile("tcgen05.alloc.cta_group::1.sync.aligned.shared::cta.b32 [%0], %1;" \
                 :: "r"((uint32_t)(sm)), "r"((uint32_t)(n)) : "memory")
#define TCGEN05_RELINQ() \
    asm volatile("tcgen05.relinquish_alloc_permit.cta_group::1.sync.aligned;")
#define TCGEN05_DEALLOC(t, n) \
    asm volatile("tcgen05.dealloc.cta_group::1.sync.aligned.b32 %0, %1;" :: "r"(t), "r"(n))
#define TCGEN05_COMMIT(mbar) \
    asm volatile("tcgen05.commit.cta_group::1.mbarrier::arrive::one.shared::cluster.b64 [%0];" \
                 :: "r"((uint32_t)(mbar)) : "memory")
#define TCGEN05_FENCE_AFTER()  asm volatile("tcgen05.fence::after_thread_sync;" ::: "memory")
#define TCGEN05_FENCE_BEFORE() asm volatile("tcgen05.fence::before_thread_sync;" ::: "memory")
#define TCGEN05_WAIT_LD()      asm volatile("tcgen05.wait::ld.sync.aligned;" ::: "memory")
#define FENCE_ASYNC_SHARED()   asm volatile("fence.proxy.async.shared::cta;" ::: "memory")

#define TCGEN05_LD_X32(r, addr) \
    asm volatile("tcgen05.ld.sync.aligned.32x32b.x32.b32 " \
        "{%0, %1, %2, %3, %4, %5, %6, %7, %8, %9, %10, %11, %12, %13, %14, %15, " \
        " %16, %17, %18, %19, %20, %21, %22, %23, %24, %25, %26, %27, %28, %29, %30, %31}, [%32];" \
        : "=r"((r)[0]),  "=r"((r)[1]),  "=r"((r)[2]),  "=r"((r)[3]), \
          "=r"((r)[4]),  "=r"((r)[5]),  "=r"((r)[6]),  "=r"((r)[7]), \
          "=r"((r)[8]),  "=r"((r)[9]),  "=r"((r)[10]), "=r"((r)[11]), \
          "=r"((r)[12]), "=r"((r)[13]), "=r"((r)[14]), "=r"((r)[15]), \
          "=r"((r)[16]), "=r"((r)[17]), "=r"((r)[18]), "=r"((r)[19]), \
          "=r"((r)[20]), "=r"((r)[21]), "=r"((r)[22]), "=r"((r)[23]), \
          "=r"((r)[24]), "=r"((r)[25]), "=r"((r)[26]), "=r"((r)[27]), \
          "=r"((r)[28]), "=r"((r)[29]), "=r"((r)[30]), "=r"((r)[31]) \
        : "r"(addr))

// SW128 K-major smem descriptor (LBO=1, SBO=64, version=1)
static __device__ __forceinline__ uint64_t make_desc(uint32_t addr) {
    const uint64_t base =
        (uint64_t(2) << 61) | (uint64_t(1) << 46) | (uint64_t(64) << 32) | (uint64_t(1) << 16);
    return base | ((uint64_t)(addr >> 4) & 0x3FFF);
}

__device__ __forceinline__ void mma_f16_ss(uint32_t d, uint64_t a, uint64_t b,
                                           uint32_t idesc, uint32_t en) {
    asm volatile(
        "{\n\t.reg .pred p;\n\tsetp.ne.u32 p, %5, 0;\n\t"
        "tcgen05.mma.cta_group::1.kind::f16 [%0], %1, %2, %3, {%4, %4, %4, %4}, p;\n\t}"
        :: "r"(d), "l"(a), "l"(b), "r"(idesc), "r"(0u), "r"(en) : "memory");
}

// idesc: F32 accum, BF16 x BF16, K-major both
#define IDESC_N128 ((1u<<4)|(1u<<7)|(1u<<10)|((128u/8)<<17)|((128u/16)<<24))
#define IDESC_N64  ((1u<<4)|(1u<<7)|(1u<<10)|(( 64u/8)<<17)|((128u/16)<<24))
#endif // HAS_TC

__device__ __forceinline__ uint32_t bpackh(__nv_bfloat16 a, __nv_bfloat16 b) {
    __nv_bfloat162 t = __halves2bfloat162(a, b);
    return *reinterpret_cast<uint32_t*>(&t);
}

// =====================================================================
// KNN
// =====================================================================
__global__ void knn_kernel(const float* __restrict__ xyz)
{
    __shared__ float d2s[NN];
    __shared__ float rv[256];
    __shared__ int   ri[256];
    int m = blockIdx.x;
    int b = m >> 11;
    int t = threadIdx.x;
    const float* base = xyz + (size_t)(b << 11) * 3;

    float qx = xyz[m*3+0], qy = xyz[m*3+1], qz = xyz[m*3+2];
    float sqq = qx*qx + qy*qy + qz*qz;

    for (int j = t; j < NN; j += 256) {
        float px = base[j*3+0], py = base[j*3+1], pz = base[j*3+2];
        float sqp = px*px + py*py + pz*pz;
        float dot = qx*px + qy*py + qz*pz;
        d2s[j] = sqq + sqp - 2.0f*dot;
    }
    __syncthreads();

    for (int it = 0; it < KNB; it++) {
        float bv = FLT_MAX; int bi = 0x3fffffff;
        for (int j = t; j < NN; j += 256) {
            float v = d2s[j];
            if (v < bv) { bv = v; bi = j; }
        }
        rv[t] = bv; ri[t] = bi;
        __syncthreads();
        for (int s = 128; s; s >>= 1) {
            if (t < s) {
                float ov = rv[t+s]; int oi = ri[t+s];
                if (ov < rv[t] || (ov == rv[t] && oi < ri[t])) { rv[t] = ov; ri[t] = oi; }
            }
            __syncthreads();
        }
        if (t == 0) { g_idx[(size_t)m*KNB + it] = ri[0]; d2s[ri[0]] = FLT_MAX; }
        __syncthreads();
    }
}

// =====================================================================
// transpose f
// =====================================================================
__global__ void transpose_f(const float* __restrict__ f)
{
    __shared__ float tile[32][33];
    int b  = blockIdx.z;
    int n0 = blockIdx.x * 32;
    int c0 = blockIdx.y * 32;
    int tx = threadIdx.x, ty = threadIdx.y;
#pragma unroll
    for (int i = 0; i < 32; i += 8)
        tile[ty+i][tx] = f[((size_t)b*CIN + c0 + ty + i)*NN + n0 + tx];
    __syncthreads();
#pragma unroll
    for (int i = 0; i < 32; i += 8)
        g_ft[((size_t)b*NN + n0 + ty + i)*CIN + c0 + tx] = tile[tx][ty+i];
}

// =====================================================================
// geo branch pre-activation
// =====================================================================
__global__ void geo_pre(const float* __restrict__ xyz, const float* __restrict__ Wg)
{
    int m = blockIdx.x;
    int c = threadIdx.x;
    int b = m >> 11;
    float w0 = Wg[c*6+0], w1 = Wg[c*6+1], w2 = Wg[c*6+2];
    float w3 = Wg[c*6+3], w4 = Wg[c*6+4], w5 = Wg[c*6+5];
    float cx = xyz[m*3+0], cy = xyz[m*3+1], cz = xyz[m*3+2];
    float base = w0*cx + w1*cy + w2*cz;
    for (int k = 0; k < KNB; k++) {
        int nb = g_idx[(size_t)m*KNB + k];
        const float* pp = xyz + (size_t)((b << 11) + nb)*3;
        float dx = pp[0]-cx, dy = pp[1]-cy, dz = pp[2]-cz;
        g_act[((size_t)m*KNB + k)*CO + c] = base + w3*dx + w4*dy + w5*dz;
    }
}

// =====================================================================
// gather feat_in
// =====================================================================
__global__ void gather_feat()
{
    size_t r = (size_t)blockIdx.x * 2 + (threadIdx.x >> 7);
    int c = threadIdx.x & 127;
    size_t m = r / KNB;
    int b = (int)(m >> 11);
    float v;
    if (c < 64) {
        int nb = g_idx[r];
        v = g_ft[((size_t)(b << 11) + nb)*CIN + c];
    } else {
        v = g_ft[m*CIN + (c - 64)];
    }
    g_gin[r*128 + c] = v;
}

// =====================================================================
// SIMT SGEMM (dense small GEMMs; weights as B[N,K])
// =====================================================================
#define BM 64
#define BN 64
#define BK 16

__global__ void sgemm_bt(const float* __restrict__ A, const float* __restrict__ B,
                         float* __restrict__ C, int K, int lda, int ldb, int ldc)
{
    __shared__ __align__(16) float As[BK][BM+4];
    __shared__ __align__(16) float Bs[BK][BN+4];

    int tid = threadIdx.x;
    int tx = tid & 15, ty = tid >> 4;
    int m0 = blockIdx.y * BM;
    int n0 = blockIdx.x * BN;

    int arow = tid >> 2;
    int akq  = (tid & 3) * 4;

    float acc[4][4];
#pragma unroll
    for (int i = 0; i < 4; i++)
#pragma unroll
        for (int j = 0; j < 4; j++) acc[i][j] = 0.0f;

    for (int k0 = 0; k0 < K; k0 += BK) {
        float4 av = *(const float4*)(A + (size_t)(m0 + arow)*lda + k0 + akq);
        As[akq+0][arow] = av.x; As[akq+1][arow] = av.y;
        As[akq+2][arow] = av.z; As[akq+3][arow] = av.w;
        float4 bv = *(const float4*)(B + (size_t)(n0 + arow)*ldb + k0 + akq);
        Bs[akq+0][arow] = bv.x; Bs[akq+1][arow] = bv.y;
        Bs[akq+2][arow] = bv.z; Bs[akq+3][arow] = bv.w;
        __syncthreads();
#pragma unroll
        for (int kk = 0; kk < BK; kk++) {
            float4 a4 = *(const float4*)&As[kk][tx*4];
            float4 b4 = *(const float4*)&Bs[kk][ty*4];
            float a[4] = {a4.x, a4.y, a4.z, a4.w};
            float bb[4] = {b4.x, b4.y, b4.z, b4.w};
#pragma unroll
            for (int i = 0; i < 4; i++)
#pragma unroll
                for (int j = 0; j < 4; j++)
                    acc[i][j] = fmaf(bb[i], a[j], acc[i][j]);
        }
        __syncthreads();
    }
#pragma unroll
    for (int j = 0; j < 4; j++) {
        int m = m0 + tx*4 + j;
        float4 o = make_float4(acc[0][j], acc[1][j], acc[2][j], acc[3][j]);
        *(float4*)(C + (size_t)m*ldc + n0 + ty*4) = o;
    }
}

// =====================================================================
// BN stats (deterministic two-pass)
// =====================================================================
__global__ void bn_stats_partial(const float* __restrict__ X, long rows)
{
    int c = threadIdx.x;
    long per = (rows + gridDim.x - 1) / gridDim.x;
    long r0 = (long)blockIdx.x * per;
    long r1 = r0 + per; if (r1 > rows) r1 = rows;
    double s = 0.0, s2 = 0.0;
    for (long r = r0; r < r1; r++) {
        float v = X[r*CO + c];
        s  += (double)v;
        s2 += (double)v * (double)v;
    }
    g_part[((size_t)blockIdx.x*2 + 0)*CO + c] = s;
    g_part[((size_t)blockIdx.x*2 + 1)*CO + c] = s2;
}

__global__ void bn_stats_final(int nblocks, long rows, float* msc)
{
    int c = threadIdx.x;
    double s = 0.0, s2 = 0.0;
    for (int i = 0; i < nblocks; i++) {
        s  += g_part[((size_t)i*2 + 0)*CO + c];
        s2 += g_part[((size_t)i*2 + 1)*CO + c];
    }
    double mean = s / (double)rows;
    double var  = s2 / (double)rows - mean*mean;
    msc[c]      = (float)mean;
    msc[CO + c] = (float)(1.0 / sqrt(var + (double)EPSB));
}

// =====================================================================
// branch BN + relu + maxpool
// =====================================================================
__global__ void branch_apply(const float* msc,
                             const float* __restrict__ g_geo, const float* __restrict__ b_geo,
                             const float* __restrict__ g_fea, const float* __restrict__ b_fea)
{
    int m = blockIdx.x;
    int c = threadIdx.x;
    float mean = msc[c], istd = msc[CO + c];
    float ga = (c < 128) ? g_geo[c] : g_fea[c - 128];
    float be = (c < 128) ? b_geo[c] : b_fea[c - 128];
    float sc = istd * ga;
    float best = -FLT_MAX;
    const float* base = g_act + (size_t)m*KNB*CO + c;
#pragma unroll 3
    for (int k = 0; k < KNB; k++) {
        float zv = base[(size_t)k*CO];
        float y = (zv - mean) * sc + be;
        y = fmaxf(y, 0.0f);
        best = fmaxf(best, y);
    }
    g_featv[(size_t)m*CO + c] = best;
}

// =====================================================================
// generic BN apply
// =====================================================================
__global__ void bn_apply(const float* __restrict__ in, float* __restrict__ out,
                         const float* msc,
                         const float* __restrict__ gamma, const float* __restrict__ beta,
                         const float* __restrict__ res, int do_relu)
{
    size_t i = (size_t)blockIdx.x * blockDim.x + threadIdx.x;
    int c = (int)(i & (CO-1));
    float y = (in[i] - msc[c]) * msc[CO + c] * gamma[c] + beta[c];
    if (do_relu) y = fmaxf(y, 0.0f);
    if (res) y += res[i];
    out[i] = y;
}

// =====================================================================
// fp32 -> bf16 hi/lo split (elementwise)
// =====================================================================
__global__ void split2(const float* __restrict__ x,
                       __nv_bfloat16* __restrict__ h, __nv_bfloat16* __restrict__ l)
{
    int i = blockIdx.x * 256 + threadIdx.x;
    float v = x[i];
    __nv_bfloat16 hb = __float2bfloat16(v);
    h[i] = hb;
    l[i] = __float2bfloat16(v - __bfloat162float(hb));
}

// =====================================================================
// v -> per-head transposed bf16 split: vt[z][c][m]
// =====================================================================
__global__ void vt_convert()
{
    __shared__ float tile[32][33];
    int z  = blockIdx.z;
    int b  = z / HEADS, h = z - b*HEADS;
    int m0 = blockIdx.x * 32;
    int c0 = blockIdx.y * 32;
    int tx = threadIdx.x, ty = threadIdx.y;   // 32 x 8
#pragma unroll
    for (int i = 0; i < 32; i += 8)
        tile[ty+i][tx] = g_v[((size_t)(b*NN) + m0 + ty + i)*CO + h*32 + c0 + tx];
    __syncthreads();
#pragma unroll
    for (int i = 0; i < 32; i += 8) {
        int c = c0 + ty + i, m = m0 + tx;
        float v = tile[tx][ty+i];
        __nv_bfloat16 hb = __float2bfloat16(v);
        size_t o = (size_t)z*WCH*NN + (size_t)c*NN + m;
        g_vth[o] = hb;
        g_vtl[o] = __float2bfloat16(v - __bfloat162float(hb));
    }
}

// =====================================================================
// Tensor-core QK^T: S[z][m,n] = sum_k q[m,k]*k[n,k], 3-term bf16 split
// grid (16,16,28), 128 threads. dyn smem: 1024 pad + 4x16KB tiles + ctrl
// =====================================================================
#define QK_SMEM (1024 + 4*16384 + 64)

__global__ void __launch_bounds__(128, 1)
attn_qk(float* __restrict__ S)
{
#if HAS_TC
    extern __shared__ char sm[];
    uint32_t raw = smem_u32(sm);
    uint32_t base = (raw + 1023) & ~1023u;
    char* sb = sm + (base - raw);
    uint32_t ctrl = base + 65536;            // tmem ptr
    uint32_t mbar = ctrl + 8;

    int t = threadIdx.x;
    int z = blockIdx.z;
    int b = z / HEADS, h = z - b*HEADS;
    int m0 = blockIdx.y * 128, n0 = blockIdx.x * 128;

    if (t == 0) MBARRIER_INIT(mbar, 1);
    if (t < 32) { TCGEN05_ALLOC(ctrl, 128); TCGEN05_RELINQ(); }
    __syncthreads();
    uint32_t tmem;
    asm volatile("ld.shared.b32 %0, [%1];" : "=r"(tmem) : "r"(ctrl));

    const __nv_bfloat16* pAh = g_qh + ((size_t)(b*NN) + m0)*CO + h*32;
    const __nv_bfloat16* pAl = g_ql + ((size_t)(b*NN) + m0)*CO + h*32;
    const __nv_bfloat16* pBh = g_kh + ((size_t)(b*NN) + n0)*CO + h*32;
    const __nv_bfloat16* pBl = g_kl + ((size_t)(b*NN) + n0)*CO + h*32;

    int rb = t >> 4, kq = t & 15;
#pragma unroll
    for (int i = 0; i < 16; i++) {
        int r = rb + i*8;
        uint32_t so = swz((uint32_t)(r*128 + kq*8));
        *(uint2*)(sb + 0*16384 + so) = *(const uint2*)(pAh + (size_t)r*CO + kq*4);
        *(uint2*)(sb + 1*16384 + so) = *(const uint2*)(pAl + (size_t)r*CO + kq*4);
        *(uint2*)(sb + 2*16384 + so) = *(const uint2*)(pBh + (size_t)r*CO + kq*4);
        *(uint2*)(sb + 3*16384 + so) = *(const uint2*)(pBl + (size_t)r*CO + kq*4);
    }
    __syncthreads();

    if (t < 32) {
        if (elect_one_pred()) {
            FENCE_ASYNC_SHARED();
            uint64_t dAh = make_desc(base + 0*16384);
            uint64_t dAl = make_desc(base + 1*16384);
            uint64_t dBh = make_desc(base + 2*16384);
            uint64_t dBl = make_desc(base + 3*16384);
            bool first = true;
#pragma unroll
            for (int kc = 0; kc < 4; kc++) {
                uint64_t off = kc*2;
                mma_f16_ss(tmem, dAh+off, dBh+off, IDESC_N128, first ? 0u : 1u);
                first = false;
                mma_f16_ss(tmem, dAh+off, dBl+off, IDESC_N128, 1u);
                mma_f16_ss(tmem, dAl+off, dBh+off, IDESC_N128, 1u);
            }
            TCGEN05_COMMIT(mbar);
        }
    }
    MBARRIER_WAIT_PARITY(mbar, 0);
    TCGEN05_FENCE_AFTER();

    int wid = t >> 5, lane = t & 31;
    float* Srow = S + (size_t)z*NN*NN + (size_t)(m0 + wid*32 + lane)*NN + n0;
#pragma unroll
    for (int g = 0; g < 4; g++) {
        uint32_t r[32];
        TCGEN05_LD_X32(r, tmem + g*32);
        TCGEN05_WAIT_LD();
        TCGEN05_FENCE_BEFORE();
#pragma unroll
        for (int j = 0; j < 8; j++) {
            float4 o = make_float4(__uint_as_float(r[j*4+0]), __uint_as_float(r[j*4+1]),
                                   __uint_as_float(r[j*4+2]), __uint_as_float(r[j*4+3]));
            *(float4*)(Srow + g*32 + j*4) = o;
        }
    }
    __syncthreads();
    if (t < 32) TCGEN05_DEALLOC(tmem, 128);
#else
    // SIMT fallback (generic compute_103 pass; correct, slow)
    int t = threadIdx.x;
    int z = blockIdx.z;
    int b = z / HEADS, h = z - b*HEADS;
    int m0 = blockIdx.y * 128, n0 = blockIdx.x * 128;
    int m = m0 + t;
    const float* qp = g_q + ((size_t)(b*NN) + m)*CO + h*32;
    for (int n = 0; n < 128; n++) {
        const float* kp = g_k + ((size_t)(b*NN) + n0 + n)*CO + h*32;
        float acc = 0.0f;
        for (int k = 0; k < 64; k++) acc = fmaf(qp[k], kp[k], acc);
        S[(size_t)z*NN*NN + (size_t)m*NN + n0 + n] = acc;
    }
#endif
}

// =====================================================================
// softmax: single load/store pass, row of 2048, 8 regs/thread
// =====================================================================
__global__ void softmax_kernel(float* __restrict__ S)
{
    size_t row = blockIdx.x;
    float* p = S + row * NN;
    int t = threadIdx.x;
    __shared__ float red[256];

    float4 a = ((float4*)p)[t];
    float4 c = ((float4*)p)[t + 256];

    float mx = fmaxf(fmaxf(fmaxf(a.x,a.y),fmaxf(a.z,a.w)),
                     fmaxf(fmaxf(c.x,c.y),fmaxf(c.z,c.w)));
    red[t] = mx; __syncthreads();
    for (int s = 128; s; s >>= 1) { if (t < s) red[t] = fmaxf(red[t], red[t+s]); __syncthreads(); }
    mx = red[0]; __syncthreads();

    a.x = __expf(a.x - mx); a.y = __expf(a.y - mx); a.z = __expf(a.z - mx); a.w = __expf(a.w - mx);
    c.x = __expf(c.x - mx); c.y = __expf(c.y - mx); c.z = __expf(c.z - mx); c.w = __expf(c.w - mx);
    float sum = a.x+a.y+a.z+a.w + c.x+c.y+c.z+c.w;
    red[t] = sum; __syncthreads();
    for (int s = 128; s; s >>= 1) { if (t < s) red[t] += red[t+s]; __syncthreads(); }
    float inv = 1.0f / red[0];

    a.x *= inv; a.y *= inv; a.z *= inv; a.w *= inv;
    c.x *= inv; c.y *= inv; c.z *= inv; c.w *= inv;
    ((float4*)p)[t] = a;
    ((float4*)p)[t + 256] = c;
}

// =====================================================================
// Tensor-core A·V: O[z][m, c] = sum_k S[m,k]*vt[c,k], 3-term bf16 split
// grid (16, 28): x = m-tile, y = z. 128 threads.
// =====================================================================
#define AV_SMEM (1024 + 2*16384 + 2*8192 + 64)

__global__ void __launch_bounds__(128, 1)
attn_av(const float* __restrict__ S)
{
#if HAS_TC
    extern __shared__ char sm[];
    uint32_t raw = smem_u32(sm);
    uint32_t base = (raw + 1023) & ~1023u;
    char* sb = sm + (base - raw);
    uint32_t off_Ah = 0, off_Al = 16384, off_Bh = 32768, off_Bl = 40960;
    uint32_t ctrl = base + 49152;
    uint32_t mbar = ctrl + 8;

    int t = threadIdx.x;
    int z = blockIdx.y;
    int b = z / HEADS, h = z - b*HEADS;
    int m0 = blockIdx.x * 128;

    if (t == 0) MBARRIER_INIT(mbar, 1);
    if (t < 32) { TCGEN05_ALLOC(ctrl, 64); TCGEN05_RELINQ(); }
    __syncthreads();
    uint32_t tmem;
    asm volatile("ld.shared.b32 %0, [%1];" : "=r"(tmem) : "r"(ctrl));

    const float* Sp = S + (size_t)z*NN*NN + (size_t)m0*NN;
    const __nv_bfloat16* Vh = g_vth + (size_t)z*WCH*NN;
    const __nv_bfloat16* Vl = g_vtl + (size_t)z*WCH*NN;

    uint64_t dAh = make_desc(base + off_Ah);
    uint64_t dAl = make_desc(base + off_Al);
    uint64_t dBh = make_desc(base + off_Bh);
    uint64_t dBl = make_desc(base + off_Bl);

    int rb = t >> 4, kq = t & 15;

    for (int kc = 0; kc < 32; kc++) {
        if (kc > 0) MBARRIER_WAIT_PARITY(mbar, (kc-1) & 1);

        // A: S chunk [128 rows x 64 k] fp32 -> bf16 hi/lo split
#pragma unroll
        for (int i = 0; i < 16; i++) {
            int r = rb + i*8;
            float4 v = *(const float4*)(Sp + (size_t)r*NN + kc*64 + kq*4);
            __nv_bfloat16 h0 = __float2bfloat16(v.x);
            __nv_bfloat16 h1 = __float2bfloat16(v.y);
            __nv_bfloat16 h2 = __float2bfloat16(v.z);
            __nv_bfloat16 h3 = __float2bfloat16(v.w);
            __nv_bfloat16 l0 = __float2bfloat16(v.x - __bfloat162float(h0));
            __nv_bfloat16 l1 = __float2bfloat16(v.y - __bfloat162float(h1));
            __nv_bfloat16 l2 = __float2bfloat16(v.z - __bfloat162float(h2));
            __nv_bfloat16 l3 = __float2bfloat16(v.w - __bfloat162float(h3));
            uint32_t so = swz((uint32_t)(r*128 + kq*8));
            *(uint2*)(sb + off_Ah + so) = make_uint2(bpackh(h0,h1), bpackh(h2,h3));
            *(uint2*)(sb + off_Al + so) = make_uint2(bpackh(l0,l1), bpackh(l2,l3));
        }
        // B: vt chunk [64 rows x 64 k] bf16 copy
#pragma unroll
        for (int i = 0; i < 8; i++) {
            int r = rb + i*8;
            uint32_t so = swz((uint32_t)(r*128 + kq*8));
            *(uint2*)(sb + off_Bh + so) = *(const uint2*)(Vh + (size_t)r*NN + kc*64 + kq*4);
            *(uint2*)(sb + off_Bl + so) = *(const uint2*)(Vl + (size_t)r*NN + kc*64 + kq*4);
        }
        __syncthreads();

        if (t < 32) {
            if (elect_one_pred()) {
                FENCE_ASYNC_SHARED();
#pragma unroll
                for (int ks = 0; ks < 4; ks++) {
                    uint64_t o = ks*2;
                    mma_f16_ss(tmem, dAh+o, dBh+o, IDESC_N64, (kc > 0 || ks > 0) ? 1u : 0u);
                    mma_f16_ss(tmem, dAh+o, dBl+o, IDESC_N64, 1u);
                    mma_f16_ss(tmem, dAl+o, dBh+o, IDESC_N64, 1u);
                }
                TCGEN05_COMMIT(mbar);
            }
        }
    }
    MBARRIER_WAIT_PARITY(mbar, 1);   // (32-1)&1
    TCGEN05_FENCE_AFTER();

    int wid = t >> 5, lane = t & 31;
    float* Orow = g_O + (size_t)(b*NN + m0 + wid*32 + lane)*FUSC + h*64;
#pragma unroll
    for (int g = 0; g < 2; g++) {
        uint32_t r[32];
        TCGEN05_LD_X32(r, tmem + g*32);
        TCGEN05_WAIT_LD();
        TCGEN05_FENCE_BEFORE();
#pragma unroll
        for (int j = 0; j < 8; j++) {
            float4 o = make_float4(__uint_as_float(r[j*4+0]), __uint_as_float(r[j*4+1]),
                                   __uint_as_float(r[j*4+2]), __uint_as_float(r[j*4+3]));
            *(float4*)(Orow + g*32 + j*4) = o;
        }
    }
    __syncthreads();
    if (t < 32) TCGEN05_DEALLOC(tmem, 64);
#else
    // SIMT fallback (generic compute_103 pass; correct, slow)
    int t = threadIdx.x;
    int z = blockIdx.y;
    int b = z / HEADS, h = z - b*HEADS;
    int m0 = blockIdx.x * 128;
    int m = m0 + t;
    const float* Sp = S + (size_t)z*NN*NN + (size_t)m*NN;
    for (int c = 0; c < 64; c++) {
        const float* vp = g_v + (size_t)(b*NN)*CO + h*32 + c;
        float acc = 0.0f;
        for (int k = 0; k < NN; k++) acc = fmaf(Sp[k], vp[(size_t)k*CO], acc);
        g_O[(size_t)(b*NN + m)*FUSC + h*64 + c] = acc;
    }
#endif
}

// =====================================================================
// LayerNorm
// =====================================================================
__global__ void layernorm_kernel(const float* __restrict__ X, float* __restrict__ Y,
                                 const float* __restrict__ g, const float* __restrict__ b)
{
    int m = blockIdx.x, c = threadIdx.x;
    __shared__ float red[256];
    float v = X[(size_t)m*CO + c];
    red[c] = v; __syncthreads();
    for (int s = 128; s; s >>= 1) { if (c < s) red[c] += red[c+s]; __syncthreads(); }
    float mean = red[0] * (1.0f/CO); __syncthreads();
    float d = v - mean;
    red[c] = d*d; __syncthreads();
    for (int s = 128; s; s >>= 1) { if (c < s) red[c] += red[c+s]; __syncthreads(); }
    float var = red[0] * (1.0f/CO);
    Y[(size_t)m*CO + c] = d * rsqrtf(var + EPSB) * g[c] + b[c];
}

// =====================================================================
// final output (transposed)
// =====================================================================
__global__ void final_out(const float* __restrict__ bias, float* __restrict__ out)
{
    __shared__ float tile[32][33];
    int b  = blockIdx.z;
    int n0 = blockIdx.x * 32;
    int c0 = blockIdx.y * 32;
    int tx = threadIdx.x, ty = threadIdx.y;
#pragma unroll
    for (int i = 0; i < 32; i += 8) {
        int n = n0 + ty + i, c = c0 + tx;
        size_t src = ((size_t)b*NN + n)*CO + c;
        tile[ty+i][tx] = g_f2[src] + g_fp[src] + bias[c];
    }
    __syncthreads();
#pragma unroll
    for (int i = 0; i < 32; i += 8) {
        int c = c0 + ty + i, n = n0 + tx;
        out[((size_t)b*CO + c)*NN + n] = tile[tx][ty+i];
    }
}

// =====================================================================
// host
// =====================================================================
static void run_bn(const float* X, long rows, float* msc, int nblocks)
{
    bn_stats_partial<<<nblocks, 256>>>(X, rows);
    bn_stats_final<<<1, 256>>>(nblocks, rows, msc);
}

extern "C" void kernel_launch(void* const* d_in, const int* in_sizes, int n_in,
                              void* d_out, int out_size)
{
    const float* xyz    = (const float*)d_in[0];
    const float* f      = (const float*)d_in[1];
    const float* W_geo  = (const float*)d_in[2];
    const float* gg     = (const float*)d_in[3];
    const float* bg     = (const float*)d_in[4];
    const float* W_feat = (const float*)d_in[5];
    const float* gf     = (const float*)d_in[6];
    const float* bf     = (const float*)d_in[7];
    const float* g_bn   = (const float*)d_in[8];
    const float* b_bn   = (const float*)d_in[9];
    const float* W_q    = (const float*)d_in[10];
    const float* gq     = (const float*)d_in[11];
    const float* bq     = (const float*)d_in[12];
    const float* W_k    = (const float*)d_in[13];
    const float* gk     = (const float*)d_in[14];
    const float* bk     = (const float*)d_in[15];
    const float* W_v    = (const float*)d_in[16];
    const float* gv     = (const float*)d_in[17];
    const float* bv     = (const float*)d_in[18];
    const float* W_fus  = (const float*)d_in[19];
    /* d_in[20] bias_fus: cancels inside BN */
    const float* gfu    = (const float*)d_in[21];
    const float* bfu    = (const float*)d_in[22];
    const float* g_ln   = (const float*)d_in[23];
    const float* b_ln   = (const float*)d_in[24];
    const float* W_mlp  = (const float*)d_in[25];
    const float* b_mlp  = (const float*)d_in[26];
    float* out = (float*)d_out;

    float *p_gin, *p_act, *p_featv, *p_x, *p_q, *p_k, *p_v;
    float *p_S, *p_O, *p_fp, *p_f2, *p_y, *p_msc;
    __nv_bfloat16 *p_qh, *p_ql, *p_kh, *p_kl;
    cudaGetSymbolAddress((void**)&p_gin,   g_gin);
    cudaGetSymbolAddress((void**)&p_act,   g_act);
    cudaGetSymbolAddress((void**)&p_featv, g_featv);
    cudaGetSymbolAddress((void**)&p_x,     g_x);
    cudaGetSymbolAddress((void**)&p_q,     g_q);
    cudaGetSymbolAddress((void**)&p_k,     g_k);
    cudaGetSymbolAddress((void**)&p_v,     g_v);
    cudaGetSymbolAddress((void**)&p_S,     g_S);
    cudaGetSymbolAddress((void**)&p_O,     g_O);
    cudaGetSymbolAddress((void**)&p_fp,    g_fp);
    cudaGetSymbolAddress((void**)&p_f2,    g_f2);
    cudaGetSymbolAddress((void**)&p_y,     g_y);
    cudaGetSymbolAddress((void**)&p_msc,   g_msc);
    cudaGetSymbolAddress((void**)&p_qh,    g_qh);
    cudaGetSymbolAddress((void**)&p_ql,    g_ql);
    cudaGetSymbolAddress((void**)&p_kh,    g_kh);
    cudaGetSymbolAddress((void**)&p_kl,    g_kl);

    cudaFuncSetAttribute(attn_qk, cudaFuncAttributeMaxDynamicSharedMemorySize, QK_SMEM);
    cudaFuncSetAttribute(attn_av, cudaFuncAttributeMaxDynamicSharedMemorySize, AV_SMEM);

    // ---- 1. KNN + transpose + gathers
    knn_kernel<<<MTOT, 256>>>(xyz);
    transpose_f<<<dim3(NN/32, CIN/32, BB), dim3(32,8)>>>(f);
    geo_pre<<<MTOT, 128>>>(xyz, W_geo);
    gather_feat<<<RTOT/2, 256>>>();

    // ---- 2. feat GEMM
    sgemm_bt<<<dim3(128/BN, RTOT/BM), 256>>>(p_gin, W_feat, p_act + 128, 128, 128, 128, CO);

    // ---- 3. branch BN + maxpool
    run_bn(p_act, RTOT, p_msc + 0*512, 128);
    branch_apply<<<MTOT, 256>>>(p_msc + 0*512, gg, bg, gf, bf);

    // ---- 4. BatchNorm1d
    run_bn(p_featv, MTOT, p_msc + 1*512, 32);
    bn_apply<<<MTOT, 256>>>(p_featv, p_x, p_msc + 1*512, g_bn, b_bn, nullptr, 0);

    // ---- 5. q/k/v
    sgemm_bt<<<dim3(CO/BN, MTOT/BM), 256>>>(p_x, W_q, p_q, CO, CO, CO, CO);
    sgemm_bt<<<dim3(CO/BN, MTOT/BM), 256>>>(p_x, W_k, p_k, CO, CO, CO, CO);
    sgemm_bt<<<dim3(CO/BN, MTOT/BM), 256>>>(p_x, W_v, p_v, CO, CO, CO, CO);
    run_bn(p_q, MTOT, p_msc + 2*512, 32);
    bn_apply<<<MTOT, 256>>>(p_q, p_q, p_msc + 2*512, gq, bq, nullptr, 1);
    run_bn(p_k, MTOT, p_msc + 3*512, 32);
    bn_apply<<<MTOT, 256>>>(p_k, p_k, p_msc + 3*512, gk, bk, nullptr, 1);
    run_bn(p_v, MTOT, p_msc + 4*512, 32);
    bn_apply<<<MTOT, 256>>>(p_v, p_v, p_msc + 4*512, gv, bv, nullptr, 1);

    // ---- 5b. bf16 splits for tensor-core attention
    split2<<<MTOT*CO/256, 256>>>(p_q, p_qh, p_ql);
    split2<<<MTOT*CO/256, 256>>>(p_k, p_kh, p_kl);
    vt_convert<<<dim3(NN/32, 2, BB*HEADS), dim3(32,8)>>>();

    // ---- 6. attention (tcgen05)
    attn_qk<<<dim3(16, 16, BB*HEADS), 128, QK_SMEM>>>(p_S);
    softmax_kernel<<<BB*HEADS*NN, 256>>>(p_S);
    attn_av<<<dim3(16, BB*HEADS), 128, AV_SMEM>>>(p_S);

    // ---- 7. fus + residual
    sgemm_bt<<<dim3(CO/BN, MTOT/BM), 256>>>(p_O, W_fus, p_fp, FUSC, FUSC, FUSC, CO);
    run_bn(p_fp, MTOT, p_msc + 5*512, 32);
    bn_apply<<<MTOT, 256>>>(p_fp, p_f2, p_msc + 5*512, gfu, bfu, p_featv, 1);

    // ---- 8. layernorm + mlp + out
    layernorm_kernel<<<MTOT, 256>>>(p_f2, p_y, g_ln, b_ln);
    sgemm_bt<<<dim3(CO/BN, MTOT/BM), 256>>>(p_y, W_mlp, p_fp, CO, CO, CO, CO);
    final_out<<<dim3(NN/32, CO/32, BB), dim3(32,8)>>>(b_mlp, out);

    (void)in_sizes; (void)n_in; (void)out_size;
}

// round 7
// speedup vs baseline: 1.5623x; 1.1412x over previous
#include <cuda_runtime.h>
#include <cuda_bf16.h>
#include <cfloat>
#include <math.h>
#include <cstdint>

// tcgen05 is arch-SPECIFIC: only legal under sm_103a feature target.
// The harness also assembles a generic compute_103 pass, so gate all
// tcgen05 device code and give that pass a correct SIMT fallback body.
#if defined(__CUDA_ARCH__) && defined(__CUDA_ARCH_FEAT_SM103_ALL)
#define HAS_TC 1
#else
#define HAS_TC 0
#endif

// ---------------- problem constants ----------------
#define BB    4
#define NN    2048
#define KNB   21
#define CIN   64
#define CO    256
#define HEADS 7
#define WCH   64
#define FUSC  (HEADS*WCH)          /* 448 */
#define MTOT  (BB*NN)              /* 8192 */
#define RTOT  (MTOT*KNB)           /* 172032 */
#define EPSB  1e-5f

// ---------------- scratch (device globals; allocation-free) ----------------
__device__ int    g_idx[RTOT];
__device__ float  g_ft[MTOT*CIN];
__device__ float  g_act[(size_t)RTOT*CO];
__device__ float  g_featv[MTOT*CO];
__device__ float  g_q[MTOT*CO];
__device__ float  g_k[MTOT*CO];
__device__ float  g_v[MTOT*CO];
__device__ float  g_S[(size_t)BB*HEADS*NN*NN];
__device__ float  g_rowstat[BB*HEADS*NN*2];
__device__ float  g_fp[MTOT*CO];
__device__ float  g_f2[MTOT*CO];
__device__ double g_part[128*2*CO];
__device__ float  g_msc[6*2*CO];
// bf16 hi/lo split operands for tensor-core GEMMs
__device__ __nv_bfloat16 g_ginh[(size_t)RTOT*128], g_ginl[(size_t)RTOT*128];
__device__ __nv_bfloat16 g_xh[MTOT*CO],  g_xl[MTOT*CO];
__device__ __nv_bfloat16 g_qh[MTOT*CO],  g_ql[MTOT*CO];
__device__ __nv_bfloat16 g_kh[MTOT*CO],  g_kl[MTOT*CO];
__device__ __nv_bfloat16 g_yh[MTOT*CO],  g_yl[MTOT*CO];
__device__ __nv_bfloat16 g_Oh[MTOT*FUSC], g_Ol[MTOT*FUSC];
__device__ __nv_bfloat16 g_vth[(size_t)BB*HEADS*WCH*NN], g_vtl[(size_t)BB*HEADS*WCH*NN];
// weight splits
__device__ __nv_bfloat16 g_wfh[128*128],  g_wfl[128*128];
__device__ __nv_bfloat16 g_wqh[CO*CO],    g_wql[CO*CO];
__device__ __nv_bfloat16 g_wkh[CO*CO],    g_wkl[CO*CO];
__device__ __nv_bfloat16 g_wvh[CO*CO],    g_wvl[CO*CO];
__device__ __nv_bfloat16 g_wfush[CO*FUSC],g_wfusl[CO*FUSC];
__device__ __nv_bfloat16 g_wmh[CO*CO],    g_wml[CO*CO];

// ---------------- ptx helpers ----------------
__device__ __forceinline__ uint32_t smem_u32(const void* p) {
    uint32_t a;
    asm("{ .reg .u64 t; cvta.to.shared.u64 t, %1; cvt.u32.u64 %0, t; }" : "=r"(a) : "l"(p));
    return a;
}
__device__ __forceinline__ uint32_t swz(uint32_t o) { return o ^ ((o >> 3) & 0x70); }

#if HAS_TC
__device__ __forceinline__ uint32_t elect_one_pred() {
    uint32_t pred;
    asm volatile("{\n\t.reg .pred p;\n\telect.sync _|p, 0xFFFFFFFF;\n\tselp.b32 %0, 1, 0, p;\n\t}" : "=r"(pred));
    return pred;
}

#define MBARRIER_INIT(addr, cnt) \
    asm volatile("mbarrier.init.shared.b64 [%0], %1;" :: "r"((uint32_t)(addr)), "r"((uint32_t)(cnt)) : "memory")

#define MBARRIER_WAIT_PARITY(mbar_smem_addr, phase_parity) do { \
    uint32_t _mbar = (uint32_t)(mbar_smem_addr); \
    uint32_t _parity = (uint32_t)(phase_parity); \
    uint32_t _done; \
    asm volatile("{\n\t.reg .pred p;\n\t" \
        "mbarrier.try_wait.parity.acquire.cta.shared::cta.b64 p, [%1], %2;\n\t" \
        "selp.b32 %0, 1, 0, p;\n\t}" : "=r"(_done) : "r"(_mbar), "r"(_parity) : "memory"); \
    if (!_done) { \
        asm volatile("{\n\t.reg .pred P1;\n\t" \
            "WAIT_LOOP_%=:\n\t" \
            "mbarrier.try_wait.parity.acquire.cta.shared::cta.b64 P1, [%0], %1, 0x989680;\n\t" \
            "@P1 bra.uni WAIT_DONE_%=;\n\t" \
            "bra.uni WAIT_LOOP_%=;\n\t" \
            "WAIT_DONE_%=:\n\t}" :: "r"(_mbar), "r"(_parity) : "memory"); \
    } \
} while(0)

#define TCGEN05_ALLOC(sm, n) \
    asm volatile("tcgen05.alloc.cta_group::1.sync.aligned.shared::cta.b32 [%0], %1;" \
                 :: "r"((uint32_t)(sm)), "r"((uint32_t)(n)) : "memory")
#define TCGEN05_RELINQ() \
    asm volatile("tcgen05.relinquish_alloc_permit.cta_group::1.sync.aligned;")
#define TCGEN05_DEALLOC(t, n) \
    asm volatile("tcgen05.dealloc.cta_group::1.sync.aligned.b32 %0, %1;" :: "r"(t), "r"(n))
#define TCGEN05_COMMIT(mbar) \
    asm volatile("tcgen05.commit.cta_group::1.mbarrier::arrive::one.shared::cluster.b64 [%0];" \
                 :: "r"((uint32_t)(mbar)) : "memory")
#define TCGEN05_FENCE_AFTER()  asm volatile("tcgen05.fence::after_thread_sync;" ::: "memory")
#define TCGEN05_FENCE_BEFORE() asm volatile("tcgen05.fence::before_thread_sync;" ::: "memory")
#define TCGEN05_WAIT_LD()      asm volatile("tcgen05.wait::ld.sync.aligned;" ::: "memory")
#define FENCE_ASYNC_SHARED()   asm volatile("fence.proxy.async.shared::cta;" ::: "memory")

#define TCGEN05_LD_X32(r, addr) \
    asm volatile("tcgen05.ld.sync.aligned.32x32b.x32.b32 " \
        "{%0, %1, %2, %3, %4, %5, %6, %7, %8, %9, %10, %11, %12, %13, %14, %15, " \
        " %16, %17, %18, %19, %20, %21, %22, %23, %24, %25, %26, %27, %28, %29, %30, %31}, [%32];" \
        : "=r"((r)[0]),  "=r"((r)[1]),  "=r"((r)[2]),  "=r"((r)[3]), \
          "=r"((r)[4]),  "=r"((r)[5]),  "=r"((r)[6]),  "=r"((r)[7]), \
          "=r"((r)[8]),  "=r"((r)[9]),  "=r"((r)[10]), "=r"((r)[11]), \
          "=r"((r)[12]), "=r"((r)[13]), "=r"((r)[14]), "=r"((r)[15]), \
          "=r"((r)[16]), "=r"((r)[17]), "=r"((r)[18]), "=r"((r)[19]), \
          "=r"((r)[20]), "=r"((r)[21]), "=r"((r)[22]), "=r"((r)[23]), \
          "=r"((r)[24]), "=r"((r)[25]), "=r"((r)[26]), "=r"((r)[27]), \
          "=r"((r)[28]), "=r"((r)[29]), "=r"((r)[30]), "=r"((r)[31]) \
        : "r"(addr))

// SW128 K-major smem descriptor (LBO=1, SBO=64, version=1)
static __device__ __forceinline__ uint64_t make_desc(uint32_t addr) {
    const uint64_t base =
        (uint64_t(2) << 61) | (uint64_t(1) << 46) | (uint64_t(64) << 32) | (uint64_t(1) << 16);
    return base | ((uint64_t)(addr >> 4) & 0x3FFF);
}

__device__ __forceinline__ void mma_f16_ss(uint32_t d, uint64_t a, uint64_t b,
                                           uint32_t idesc, uint32_t en) {
    asm volatile(
        "{\n\t.reg .pred p;\n\tsetp.ne.u32 p, %5, 0;\n\t"
        "tcgen05.mma.cta_group::1.kind::f16 [%0], %1, %2, %3, {%4, %4, %4, %4}, p;\n\t}"
        :: "r"(d), "l"(a), "l"(b), "r"(idesc), "r"(0u), "r"(en) : "memory");
}

// idesc: F32 accum, BF16 x BF16, K-major both
#define IDESC_N128 ((1u<<4)|(1u<<7)|(1u<<10)|((128u/8)<<17)|((128u/16)<<24))
#define IDESC_N64  ((1u<<4)|(1u<<7)|(1u<<10)|(( 64u/8)<<17)|((128u/16)<<24))
#endif // HAS_TC

__device__ __forceinline__ uint32_t bpackh(__nv_bfloat16 a, __nv_bfloat16 b) {
    __nv_bfloat162 t = __halves2bfloat162(a, b);
    return *reinterpret_cast<uint32_t*>(&t);
}

// =====================================================================
// KNN
// =====================================================================
__global__ void knn_kernel(const float* __restrict__ xyz)
{
    __shared__ float d2s[NN];
    __shared__ float rv[256];
    __shared__ int   ri[256];
    int m = blockIdx.x;
    int b = m >> 11;
    int t = threadIdx.x;
    const float* base = xyz + (size_t)(b << 11) * 3;

    float qx = xyz[m*3+0], qy = xyz[m*3+1], qz = xyz[m*3+2];
    float sqq = qx*qx + qy*qy + qz*qz;

    for (int j = t; j < NN; j += 256) {
        float px = base[j*3+0], py = base[j*3+1], pz = base[j*3+2];
        float sqp = px*px + py*py + pz*pz;
        float dot = qx*px + qy*py + qz*pz;
        d2s[j] = sqq + sqp - 2.0f*dot;
    }
    __syncthreads();

    for (int it = 0; it < KNB; it++) {
        float bv = FLT_MAX; int bi = 0x3fffffff;
        for (int j = t; j < NN; j += 256) {
            float v = d2s[j];
            if (v < bv) { bv = v; bi = j; }
        }
        rv[t] = bv; ri[t] = bi;
        __syncthreads();
        for (int s = 128; s; s >>= 1) {
            if (t < s) {
                float ov = rv[t+s]; int oi = ri[t+s];
                if (ov < rv[t] || (ov == rv[t] && oi < ri[t])) { rv[t] = ov; ri[t] = oi; }
            }
            __syncthreads();
        }
        if (t == 0) { g_idx[(size_t)m*KNB + it] = ri[0]; d2s[ri[0]] = FLT_MAX; }
        __syncthreads();
    }
}

// =====================================================================
// transpose f
// =====================================================================
__global__ void transpose_f(const float* __restrict__ f)
{
    __shared__ float tile[32][33];
    int b  = blockIdx.z;
    int n0 = blockIdx.x * 32;
    int c0 = blockIdx.y * 32;
    int tx = threadIdx.x, ty = threadIdx.y;
#pragma unroll
    for (int i = 0; i < 32; i += 8)
        tile[ty+i][tx] = f[((size_t)b*CIN + c0 + ty + i)*NN + n0 + tx];
    __syncthreads();
#pragma unroll
    for (int i = 0; i < 32; i += 8)
        g_ft[((size_t)b*NN + n0 + ty + i)*CIN + c0 + tx] = tile[tx][ty+i];
}

// =====================================================================
// geo branch pre-activation
// =====================================================================
__global__ void geo_pre(const float* __restrict__ xyz, const float* __restrict__ Wg)
{
    int m = blockIdx.x;
    int c = threadIdx.x;
    int b = m >> 11;
    float w0 = Wg[c*6+0], w1 = Wg[c*6+1], w2 = Wg[c*6+2];
    float w3 = Wg[c*6+3], w4 = Wg[c*6+4], w5 = Wg[c*6+5];
    float cx = xyz[m*3+0], cy = xyz[m*3+1], cz = xyz[m*3+2];
    float base = w0*cx + w1*cy + w2*cz;
    for (int k = 0; k < KNB; k++) {
        int nb = g_idx[(size_t)m*KNB + k];
        const float* pp = xyz + (size_t)((b << 11) + nb)*3;
        float dx = pp[0]-cx, dy = pp[1]-cy, dz = pp[2]-cz;
        g_act[((size_t)m*KNB + k)*CO + c] = base + w3*dx + w4*dy + w5*dz;
    }
}

// =====================================================================
// gather feat_in -> bf16 hi/lo split directly
// =====================================================================
__global__ void gather_feat()
{
    size_t r = (size_t)blockIdx.x * 2 + (threadIdx.x >> 7);
    int c = threadIdx.x & 127;
    size_t m = r / KNB;
    int b = (int)(m >> 11);
    float v;
    if (c < 64) {
        int nb = g_idx[r];
        v = g_ft[((size_t)(b << 11) + nb)*CIN + c];
    } else {
        v = g_ft[m*CIN + (c - 64)];
    }
    __nv_bfloat16 hb = __float2bfloat16(v);
    g_ginh[r*128 + c] = hb;
    g_ginl[r*128 + c] = __float2bfloat16(v - __bfloat162float(hb));
}

// =====================================================================
// Generic tensor-core GEMM: C[m,n] = sum_k A[m,k]*B[n,k]
// A,B pre-split bf16 hi/lo (3-term). Tile 128x128, K chunks of 64.
// grid (Ncol/128, M/128), 128 threads.
// =====================================================================
#define TG_SMEM (1024 + 4*16384 + 64)

__global__ void __launch_bounds__(128, 1)
tgemm(const __nv_bfloat16* __restrict__ Ah, const __nv_bfloat16* __restrict__ Al,
      const __nv_bfloat16* __restrict__ Bh, const __nv_bfloat16* __restrict__ Bl,
      float* __restrict__ C, int lda, int ldb, int ldc, int nkc)
{
#if HAS_TC
    extern __shared__ char sm[];
    uint32_t raw = smem_u32(sm);
    uint32_t base = (raw + 1023) & ~1023u;
    char* sb = sm + (base - raw);
    uint32_t ctrl = base + 65536;
    uint32_t mbar = ctrl + 8;

    int t = threadIdx.x;
    int m0 = blockIdx.y * 128, n0 = blockIdx.x * 128;

    if (t == 0) MBARRIER_INIT(mbar, 1);
    if (t < 32) { TCGEN05_ALLOC(ctrl, 128); TCGEN05_RELINQ(); }
    __syncthreads();
    uint32_t tmem;
    asm volatile("ld.shared.b32 %0, [%1];" : "=r"(tmem) : "r"(ctrl));

    Ah += (size_t)m0 * lda; Al += (size_t)m0 * lda;
    Bh += (size_t)n0 * ldb; Bl += (size_t)n0 * ldb;

    uint64_t dAh = make_desc(base + 0*16384);
    uint64_t dAl = make_desc(base + 1*16384);
    uint64_t dBh = make_desc(base + 2*16384);
    uint64_t dBl = make_desc(base + 3*16384);

    int rb = t >> 4, kq = t & 15;

    for (int kc = 0; kc < nkc; kc++) {
        if (kc > 0) MBARRIER_WAIT_PARITY(mbar, (kc-1) & 1);
        int k0 = kc*64;
#pragma unroll
        for (int i = 0; i < 16; i++) {
            int r = rb + i*8;
            uint32_t so = swz((uint32_t)(r*128 + kq*8));
            *(uint2*)(sb + 0*16384 + so) = *(const uint2*)(Ah + (size_t)r*lda + k0 + kq*4);
            *(uint2*)(sb + 1*16384 + so) = *(const uint2*)(Al + (size_t)r*lda + k0 + kq*4);
            *(uint2*)(sb + 2*16384 + so) = *(const uint2*)(Bh + (size_t)r*ldb + k0 + kq*4);
            *(uint2*)(sb + 3*16384 + so) = *(const uint2*)(Bl + (size_t)r*ldb + k0 + kq*4);
        }
        __syncthreads();
        if (t < 32) {
            if (elect_one_pred()) {
                FENCE_ASYNC_SHARED();
#pragma unroll
                for (int ks = 0; ks < 4; ks++) {
                    uint64_t o = ks*2;
                    mma_f16_ss(tmem, dAh+o, dBh+o, IDESC_N128, (kc > 0 || ks > 0) ? 1u : 0u);
                    mma_f16_ss(tmem, dAh+o, dBl+o, IDESC_N128, 1u);
                    mma_f16_ss(tmem, dAl+o, dBh+o, IDESC_N128, 1u);
                }
                TCGEN05_COMMIT(mbar);
            }
        }
    }
    MBARRIER_WAIT_PARITY(mbar, (nkc-1) & 1);
    TCGEN05_FENCE_AFTER();

    int wid = t >> 5, lane = t & 31;
    float* Crow = C + (size_t)(m0 + wid*32 + lane)*ldc + n0;
#pragma unroll
    for (int g = 0; g < 4; g++) {
        uint32_t r[32];
        TCGEN05_LD_X32(r, tmem + g*32);
        TCGEN05_WAIT_LD();
        TCGEN05_FENCE_BEFORE();
#pragma unroll
        for (int j = 0; j < 8; j++)
            *(float4*)(Crow + g*32 + j*4) = make_float4(
                __uint_as_float(r[j*4+0]), __uint_as_float(r[j*4+1]),
                __uint_as_float(r[j*4+2]), __uint_as_float(r[j*4+3]));
    }
    __syncthreads();
    if (t < 32) TCGEN05_DEALLOC(tmem, 128);
#else
    // SIMT fallback (generic compute_103 pass; correct, never runs on GB300)
    int t = threadIdx.x;
    int m = blockIdx.y*128 + t;
    int n0 = blockIdx.x*128;
    for (int n = 0; n < 128; n++) {
        float acc = 0.0f;
        for (int k = 0; k < nkc*64; k++) {
            float a = __bfloat162float(Ah[(size_t)m*lda+k]) + __bfloat162float(Al[(size_t)m*lda+k]);
            float b = __bfloat162float(Bh[(size_t)(n0+n)*ldb+k]) + __bfloat162float(Bl[(size_t)(n0+n)*ldb+k]);
            acc = fmaf(a, b, acc);
        }
        C[(size_t)m*ldc + n0 + n] = acc;
    }
#endif
}

// =====================================================================
// BN stats (deterministic two-pass)
// =====================================================================
__global__ void bn_stats_partial(const float* __restrict__ X, long rows)
{
    int c = threadIdx.x;
    long per = (rows + gridDim.x - 1) / gridDim.x;
    long r0 = (long)blockIdx.x * per;
    long r1 = r0 + per; if (r1 > rows) r1 = rows;
    double s = 0.0, s2 = 0.0;
    for (long r = r0; r < r1; r++) {
        float v = X[r*CO + c];
        s  += (double)v;
        s2 += (double)v * (double)v;
    }
    g_part[((size_t)blockIdx.x*2 + 0)*CO + c] = s;
    g_part[((size_t)blockIdx.x*2 + 1)*CO + c] = s2;
}

__global__ void bn_stats_final(int nblocks, long rows, float* msc)
{
    int c = threadIdx.x;
    double s = 0.0, s2 = 0.0;
    for (int i = 0; i < nblocks; i++) {
        s  += g_part[((size_t)i*2 + 0)*CO + c];
        s2 += g_part[((size_t)i*2 + 1)*CO + c];
    }
    double mean = s / (double)rows;
    double var  = s2 / (double)rows - mean*mean;
    msc[c]      = (float)mean;
    msc[CO + c] = (float)(1.0 / sqrt(var + (double)EPSB));
}

// =====================================================================
// branch BN + relu + maxpool
// =====================================================================
__global__ void branch_apply(const float* msc,
                             const float* __restrict__ g_geo, const float* __restrict__ b_geo,
                             const float* __restrict__ g_fea, const float* __restrict__ b_fea)
{
    int m = blockIdx.x;
    int c = threadIdx.x;
    float mean = msc[c], istd = msc[CO + c];
    float ga = (c < 128) ? g_geo[c] : g_fea[c - 128];
    float be = (c < 128) ? b_geo[c] : b_fea[c - 128];
    float sc = istd * ga;
    float best = -FLT_MAX;
    const float* base = g_act + (size_t)m*KNB*CO + c;
#pragma unroll 3
    for (int k = 0; k < KNB; k++) {
        float zv = base[(size_t)k*CO];
        float y = (zv - mean) * sc + be;
        y = fmaxf(y, 0.0f);
        best = fmaxf(best, y);
    }
    g_featv[(size_t)m*CO + c] = best;
}

// =====================================================================
// BN apply -> fp32 out (optional relu, optional residual)
// =====================================================================
__global__ void bn_apply(const float* __restrict__ in, float* __restrict__ out,
                         const float* msc,
                         const float* __restrict__ gamma, const float* __restrict__ beta,
                         const float* __restrict__ res, int do_relu)
{
    size_t i = (size_t)blockIdx.x * blockDim.x + threadIdx.x;
    int c = (int)(i & (CO-1));
    float y = (in[i] - msc[c]) * msc[CO + c] * gamma[c] + beta[c];
    if (do_relu) y = fmaxf(y, 0.0f);
    if (res) y += res[i];
    out[i] = y;
}

// =====================================================================
// BN apply -> bf16 hi/lo split out (optional relu)
// =====================================================================
__global__ void bn_apply_split(const float* __restrict__ in,
                               const float* msc,
                               const float* __restrict__ gamma, const float* __restrict__ beta,
                               int do_relu,
                               __nv_bfloat16* __restrict__ oh, __nv_bfloat16* __restrict__ ol)
{
    size_t i = (size_t)blockIdx.x * blockDim.x + threadIdx.x;
    int c = (int)(i & (CO-1));
    float y = (in[i] - msc[c]) * msc[CO + c] * gamma[c] + beta[c];
    if (do_relu) y = fmaxf(y, 0.0f);
    __nv_bfloat16 hb = __float2bfloat16(y);
    oh[i] = hb;
    ol[i] = __float2bfloat16(y - __bfloat162float(hb));
}

// =====================================================================
// fp32 -> bf16 hi/lo split (weights)
// =====================================================================
__global__ void split2(const float* __restrict__ x,
                       __nv_bfloat16* __restrict__ h, __nv_bfloat16* __restrict__ l)
{
    int i = blockIdx.x * 256 + threadIdx.x;
    float v = x[i];
    __nv_bfloat16 hb = __float2bfloat16(v);
    h[i] = hb;
    l[i] = __float2bfloat16(v - __bfloat162float(hb));
}

// =====================================================================
// v -> per-head transposed bf16 split: vt[z][c][m]
// =====================================================================
__global__ void vt_convert()
{
    __shared__ float tile[32][33];
    int z  = blockIdx.z;
    int b  = z / HEADS, h = z - b*HEADS;
    int m0 = blockIdx.x * 32;
    int c0 = blockIdx.y * 32;
    int tx = threadIdx.x, ty = threadIdx.y;   // 32 x 8
#pragma unroll
    for (int i = 0; i < 32; i += 8)
        tile[ty+i][tx] = g_v[((size_t)(b*NN) + m0 + ty + i)*CO + h*32 + c0 + tx];
    __syncthreads();
#pragma unroll
    for (int i = 0; i < 32; i += 8) {
        int c = c0 + ty + i, m = m0 + tx;
        float v = tile[tx][ty+i];
        __nv_bfloat16 hb = __float2bfloat16(v);
        size_t o = (size_t)z*WCH*NN + (size_t)c*NN + m;
        g_vth[o] = hb;
        g_vtl[o] = __float2bfloat16(v - __bfloat162float(hb));
    }
}

// =====================================================================
// Tensor-core QK^T: S[z][m,n], 3-term bf16 split. grid (16,16,28)
// =====================================================================
#define QK_SMEM (1024 + 4*16384 + 64)

__global__ void __launch_bounds__(128, 1)
attn_qk(float* __restrict__ S)
{
#if HAS_TC
    extern __shared__ char sm[];
    uint32_t raw = smem_u32(sm);
    uint32_t base = (raw + 1023) & ~1023u;
    char* sb = sm + (base - raw);
    uint32_t ctrl = base + 65536;
    uint32_t mbar = ctrl + 8;

    int t = threadIdx.x;
    int z = blockIdx.z;
    int b = z / HEADS, h = z - b*HEADS;
    int m0 = blockIdx.y * 128, n0 = blockIdx.x * 128;

    if (t == 0) MBARRIER_INIT(mbar, 1);
    if (t < 32) { TCGEN05_ALLOC(ctrl, 128); TCGEN05_RELINQ(); }
    __syncthreads();
    uint32_t tmem;
    asm volatile("ld.shared.b32 %0, [%1];" : "=r"(tmem) : "r"(ctrl));

    const __nv_bfloat16* pAh = g_qh + ((size_t)(b*NN) + m0)*CO + h*32;
    const __nv_bfloat16* pAl = g_ql + ((size_t)(b*NN) + m0)*CO + h*32;
    const __nv_bfloat16* pBh = g_kh + ((size_t)(b*NN) + n0)*CO + h*32;
    const __nv_bfloat16* pBl = g_kl + ((size_t)(b*NN) + n0)*CO + h*32;

    int rb = t >> 4, kq = t & 15;
#pragma unroll
    for (int i = 0; i < 16; i++) {
        int r = rb + i*8;
        uint32_t so = swz((uint32_t)(r*128 + kq*8));
        *(uint2*)(sb + 0*16384 + so) = *(const uint2*)(pAh + (size_t)r*CO + kq*4);
        *(uint2*)(sb + 1*16384 + so) = *(const uint2*)(pAl + (size_t)r*CO + kq*4);
        *(uint2*)(sb + 2*16384 + so) = *(const uint2*)(pBh + (size_t)r*CO + kq*4);
        *(uint2*)(sb + 3*16384 + so) = *(const uint2*)(pBl + (size_t)r*CO + kq*4);
    }
    __syncthreads();

    if (t < 32) {
        if (elect_one_pred()) {
            FENCE_ASYNC_SHARED();
            uint64_t dAh = make_desc(base + 0*16384);
            uint64_t dAl = make_desc(base + 1*16384);
            uint64_t dBh = make_desc(base + 2*16384);
            uint64_t dBl = make_desc(base + 3*16384);
            bool first = true;
#pragma unroll
            for (int kc = 0; kc < 4; kc++) {
                uint64_t off = kc*2;
                mma_f16_ss(tmem, dAh+off, dBh+off, IDESC_N128, first ? 0u : 1u);
                first = false;
                mma_f16_ss(tmem, dAh+off, dBl+off, IDESC_N128, 1u);
                mma_f16_ss(tmem, dAl+off, dBh+off, IDESC_N128, 1u);
            }
            TCGEN05_COMMIT(mbar);
        }
    }
    MBARRIER_WAIT_PARITY(mbar, 0);
    TCGEN05_FENCE_AFTER();

    int wid = t >> 5, lane = t & 31;
    float* Srow = S + (size_t)z*NN*NN + (size_t)(m0 + wid*32 + lane)*NN + n0;
#pragma unroll
    for (int g = 0; g < 4; g++) {
        uint32_t r[32];
        TCGEN05_LD_X32(r, tmem + g*32);
        TCGEN05_WAIT_LD();
        TCGEN05_FENCE_BEFORE();
#pragma unroll
        for (int j = 0; j < 8; j++) {
            *(float4*)(Srow + g*32 + j*4) = make_float4(
                __uint_as_float(r[j*4+0]), __uint_as_float(r[j*4+1]),
                __uint_as_float(r[j*4+2]), __uint_as_float(r[j*4+3]));
        }
    }
    __syncthreads();
    if (t < 32) TCGEN05_DEALLOC(tmem, 128);
#else
    int t = threadIdx.x;
    int z = blockIdx.z;
    int b = z / HEADS, h = z - b*HEADS;
    int m0 = blockIdx.y * 128, n0 = blockIdx.x * 128;
    int m = m0 + t;
    const float* qp = g_q + ((size_t)(b*NN) + m)*CO + h*32;
    for (int n = 0; n < 128; n++) {
        const float* kp = g_k + ((size_t)(b*NN) + n0 + n)*CO + h*32;
        float acc = 0.0f;
        for (int k = 0; k < 64; k++) acc = fmaf(qp[k], kp[k], acc);
        S[(size_t)z*NN*NN + (size_t)m*NN + n0 + n] = acc;
    }
#endif
}

// =====================================================================
// softmax stats: single read pass; per row writes [max, 1/sum(exp)]
// =====================================================================
__global__ void softmax_stats(const float* __restrict__ S, float* __restrict__ stat)
{
    size_t row = blockIdx.x;
    const float* p = S + row * NN;
    int t = threadIdx.x;
    __shared__ float red[256];

    float4 a = ((const float4*)p)[t];
    float4 c = ((const float4*)p)[t + 256];

    float mx = fmaxf(fmaxf(fmaxf(a.x,a.y),fmaxf(a.z,a.w)),
                     fmaxf(fmaxf(c.x,c.y),fmaxf(c.z,c.w)));
    red[t] = mx; __syncthreads();
    for (int s = 128; s; s >>= 1) { if (t < s) red[t] = fmaxf(red[t], red[t+s]); __syncthreads(); }
    mx = red[0]; __syncthreads();

    float sum = __expf(a.x-mx)+__expf(a.y-mx)+__expf(a.z-mx)+__expf(a.w-mx)
              + __expf(c.x-mx)+__expf(c.y-mx)+__expf(c.z-mx)+__expf(c.w-mx);
    red[t] = sum; __syncthreads();
    for (int s = 128; s; s >>= 1) { if (t < s) red[t] += red[t+s]; __syncthreads(); }
    if (t == 0) { stat[row*2] = mx; stat[row*2+1] = 1.0f / red[0]; }
}

// =====================================================================
// Tensor-core A·V with inline softmax apply; epilogue -> bf16 split O
// grid (16, 28): x = m-tile, y = z. 128 threads.
// =====================================================================
#define AV_SMEM (1024 + 49152 + 64 + 1024)

__global__ void __launch_bounds__(128, 1)
attn_av(const float* __restrict__ S, const float* __restrict__ stat)
{
#if HAS_TC
    extern __shared__ char sm[];
    uint32_t raw = smem_u32(sm);
    uint32_t base = (raw + 1023) & ~1023u;
    char* sb = sm + (base - raw);
    uint32_t off_Ah = 0, off_Al = 16384, off_Bh = 32768, off_Bl = 40960;
    uint32_t ctrl = base + 49152;
    uint32_t mbar = ctrl + 8;
    float* sst = (float*)(sb + 49216);   // 128 rows x {max, inv}

    int t = threadIdx.x;
    int z = blockIdx.y;
    int b = z / HEADS, h = z - b*HEADS;
    int m0 = blockIdx.x * 128;

    if (t == 0) MBARRIER_INIT(mbar, 1);
    if (t < 32) { TCGEN05_ALLOC(ctrl, 64); TCGEN05_RELINQ(); }
    for (int i = t; i < 256; i += 128)
        sst[i] = stat[(size_t)(z*NN + m0)*2 + i];
    __syncthreads();
    uint32_t tmem;
    asm volatile("ld.shared.b32 %0, [%1];" : "=r"(tmem) : "r"(ctrl));

    const float* Sp = S + (size_t)z*NN*NN + (size_t)m0*NN;
    const __nv_bfloat16* Vh = g_vth + (size_t)z*WCH*NN;
    const __nv_bfloat16* Vl = g_vtl + (size_t)z*WCH*NN;

    uint64_t dAh = make_desc(base + off_Ah);
    uint64_t dAl = make_desc(base + off_Al);
    uint64_t dBh = make_desc(base + off_Bh);
    uint64_t dBl = make_desc(base + off_Bl);

    int rb = t >> 4, kq = t & 15;

    for (int kc = 0; kc < 32; kc++) {
        if (kc > 0) MBARRIER_WAIT_PARITY(mbar, (kc-1) & 1);

        // A: S chunk [128 x 64], softmax applied inline, fp32 -> bf16 hi/lo
#pragma unroll
        for (int i = 0; i < 16; i++) {
            int r = rb + i*8;
            float mxr = sst[r*2], invr = sst[r*2+1];
            float4 v = *(const float4*)(Sp + (size_t)r*NN + kc*64 + kq*4);
            v.x = __expf(v.x - mxr) * invr;
            v.y = __expf(v.y - mxr) * invr;
            v.z = __expf(v.z - mxr) * invr;
            v.w = __expf(v.w - mxr) * invr;
            __nv_bfloat16 h0 = __float2bfloat16(v.x);
            __nv_bfloat16 h1 = __float2bfloat16(v.y);
            __nv_bfloat16 h2 = __float2bfloat16(v.z);
            __nv_bfloat16 h3 = __float2bfloat16(v.w);
            __nv_bfloat16 l0 = __float2bfloat16(v.x - __bfloat162float(h0));
            __nv_bfloat16 l1 = __float2bfloat16(v.y - __bfloat162float(h1));
            __nv_bfloat16 l2 = __float2bfloat16(v.z - __bfloat162float(h2));
            __nv_bfloat16 l3 = __float2bfloat16(v.w - __bfloat162float(h3));
            uint32_t so = swz((uint32_t)(r*128 + kq*8));
            *(uint2*)(sb + off_Ah + so) = make_uint2(bpackh(h0,h1), bpackh(h2,h3));
            *(uint2*)(sb + off_Al + so) = make_uint2(bpackh(l0,l1), bpackh(l2,l3));
        }
        // B: vt chunk [64 x 64] bf16 copy
#pragma unroll
        for (int i = 0; i < 8; i++) {
            int r = rb + i*8;
            uint32_t so = swz((uint32_t)(r*128 + kq*8));
            *(uint2*)(sb + off_Bh + so) = *(const uint2*)(Vh + (size_t)r*NN + kc*64 + kq*4);
            *(uint2*)(sb + off_Bl + so) = *(const uint2*)(Vl + (size_t)r*NN + kc*64 + kq*4);
        }
        __syncthreads();

        if (t < 32) {
            if (elect_one_pred()) {
                FENCE_ASYNC_SHARED();
#pragma unroll
                for (int ks = 0; ks < 4; ks++) {
                    uint64_t o = ks*2;
                    mma_f16_ss(tmem, dAh+o, dBh+o, IDESC_N64, (kc > 0 || ks > 0) ? 1u : 0u);
                    mma_f16_ss(tmem, dAh+o, dBl+o, IDESC_N64, 1u);
                    mma_f16_ss(tmem, dAl+o, dBh+o, IDESC_N64, 1u);
                }
                TCGEN05_COMMIT(mbar);
            }
        }
    }
    MBARRIER_WAIT_PARITY(mbar, 1);   // (32-1)&1
    TCGEN05_FENCE_AFTER();

    int wid = t >> 5, lane = t & 31;
    size_t rbase = (size_t)(b*NN + m0 + wid*32 + lane)*FUSC + h*64;
#pragma unroll
    for (int g = 0; g < 2; g++) {
        uint32_t r[32];
        TCGEN05_LD_X32(r, tmem + g*32);
        TCGEN05_WAIT_LD();
        TCGEN05_FENCE_BEFORE();
#pragma unroll
        for (int j = 0; j < 8; j++) {
            float v0 = __uint_as_float(r[j*4+0]);
            float v1 = __uint_as_float(r[j*4+1]);
            float v2 = __uint_as_float(r[j*4+2]);
            float v3 = __uint_as_float(r[j*4+3]);
            __nv_bfloat16 h0 = __float2bfloat16(v0);
            __nv_bfloat16 h1 = __float2bfloat16(v1);
            __nv_bfloat16 h2 = __float2bfloat16(v2);
            __nv_bfloat16 h3 = __float2bfloat16(v3);
            *(uint2*)(g_Oh + rbase + g*32 + j*4) =
                make_uint2(bpackh(h0,h1), bpackh(h2,h3));
            *(uint2*)(g_Ol + rbase + g*32 + j*4) = make_uint2(
                bpackh(__float2bfloat16(v0 - __bfloat162float(h0)),
                       __float2bfloat16(v1 - __bfloat162float(h1))),
                bpackh(__float2bfloat16(v2 - __bfloat162float(h2)),
                       __float2bfloat16(v3 - __bfloat162float(h3))));
        }
    }
    __syncthreads();
    if (t < 32) TCGEN05_DEALLOC(tmem, 64);
#else
    int t = threadIdx.x;
    int z = blockIdx.y;
    int b = z / HEADS, h = z - b*HEADS;
    int m0 = blockIdx.x * 128;
    int m = m0 + t;
    const float* Sp = S + (size_t)z*NN*NN + (size_t)m*NN;
    float mxr = stat[(size_t)(z*NN + m)*2], invr = stat[(size_t)(z*NN + m)*2+1];
    for (int c = 0; c < 64; c++) {
        const float* vp = g_v + (size_t)(b*NN)*CO + h*32 + c;
        float acc = 0.0f;
        for (int k = 0; k < NN; k++)
            acc = fmaf(__expf(Sp[k]-mxr)*invr, vp[(size_t)k*CO], acc);
        size_t o = (size_t)(b*NN + m)*FUSC + h*64 + c;
        __nv_bfloat16 hb = __float2bfloat16(acc);
        g_Oh[o] = hb;
        g_Ol[o] = __float2bfloat16(acc - __bfloat162float(hb));
    }
#endif
}

// =====================================================================
// LayerNorm -> bf16 hi/lo split out
// =====================================================================
__global__ void layernorm_kernel(const float* __restrict__ X,
                                 const float* __restrict__ g, const float* __restrict__ b)
{
    int m = blockIdx.x, c = threadIdx.x;
    __shared__ float red[256];
    float v = X[(size_t)m*CO + c];
    red[c] = v; __syncthreads();
    for (int s = 128; s; s >>= 1) { if (c < s) red[c] += red[c+s]; __syncthreads(); }
    float mean = red[0] * (1.0f/CO); __syncthreads();
    float d = v - mean;
    red[c] = d*d; __syncthreads();
    for (int s = 128; s; s >>= 1) { if (c < s) red[c] += red[c+s]; __syncthreads(); }
    float var = red[0] * (1.0f/CO);
    float y = d * rsqrtf(var + EPSB) * g[c] + b[c];
    __nv_bfloat16 hb = __float2bfloat16(y);
    size_t i = (size_t)m*CO + c;
    g_yh[i] = hb;
    g_yl[i] = __float2bfloat16(y - __bfloat162float(hb));
}

// =====================================================================
// final output (transposed)
// =====================================================================
__global__ void final_out(const float* __restrict__ bias, float* __restrict__ out)
{
    __shared__ float tile[32][33];
    int b  = blockIdx.z;
    int n0 = blockIdx.x * 32;
    int c0 = blockIdx.y * 32;
    int tx = threadIdx.x, ty = threadIdx.y;
#pragma unroll
    for (int i = 0; i < 32; i += 8) {
        int n = n0 + ty + i, c = c0 + tx;
        size_t src = ((size_t)b*NN + n)*CO + c;
        tile[ty+i][tx] = g_f2[src] + g_fp[src] + bias[c];
    }
    __syncthreads();
#pragma unroll
    for (int i = 0; i < 32; i += 8) {
        int c = c0 + ty + i, n = n0 + tx;
        out[((size_t)b*CO + c)*NN + n] = tile[tx][ty+i];
    }
}

// =====================================================================
// host
// =====================================================================
static void run_bn(const float* X, long rows, float* msc, int nblocks)
{
    bn_stats_partial<<<nblocks, 256>>>(X, rows);
    bn_stats_final<<<1, 256>>>(nblocks, rows, msc);
}

extern "C" void kernel_launch(void* const* d_in, const int* in_sizes, int n_in,
                              void* d_out, int out_size)
{
    const float* xyz    = (const float*)d_in[0];
    const float* f      = (const float*)d_in[1];
    const float* W_geo  = (const float*)d_in[2];
    const float* gg     = (const float*)d_in[3];
    const float* bg     = (const float*)d_in[4];
    const float* W_feat = (const float*)d_in[5];
    const float* gf     = (const float*)d_in[6];
    const float* bf     = (const float*)d_in[7];
    const float* g_bn   = (const float*)d_in[8];
    const float* b_bn   = (const float*)d_in[9];
    const float* W_q    = (const float*)d_in[10];
    const float* gq     = (const float*)d_in[11];
    const float* bq     = (const float*)d_in[12];
    const float* W_k    = (const float*)d_in[13];
    const float* gk     = (const float*)d_in[14];
    const float* bk     = (const float*)d_in[15];
    const float* W_v    = (const float*)d_in[16];
    const float* gv     = (const float*)d_in[17];
    const float* bv     = (const float*)d_in[18];
    const float* W_fus  = (const float*)d_in[19];
    /* d_in[20] bias_fus: cancels inside BN */
    const float* gfu    = (const float*)d_in[21];
    const float* bfu    = (const float*)d_in[22];
    const float* g_ln   = (const float*)d_in[23];
    const float* b_ln   = (const float*)d_in[24];
    const float* W_mlp  = (const float*)d_in[25];
    const float* b_mlp  = (const float*)d_in[26];
    float* out = (float*)d_out;

    float *p_act, *p_featv, *p_q, *p_k, *p_v, *p_S, *p_stat, *p_fp, *p_f2, *p_msc;
    __nv_bfloat16 *p_ginh, *p_ginl, *p_xh, *p_xl, *p_qh, *p_ql, *p_kh, *p_kl;
    __nv_bfloat16 *p_yh, *p_yl, *p_Oh, *p_Ol;
    __nv_bfloat16 *p_wfh, *p_wfl, *p_wqh, *p_wql, *p_wkh, *p_wkl, *p_wvh, *p_wvl;
    __nv_bfloat16 *p_wfush, *p_wfusl, *p_wmh, *p_wml;
    cudaGetSymbolAddress((void**)&p_act,   g_act);
    cudaGetSymbolAddress((void**)&p_featv, g_featv);
    cudaGetSymbolAddress((void**)&p_q,     g_q);
    cudaGetSymbolAddress((void**)&p_k,     g_k);
    cudaGetSymbolAddress((void**)&p_v,     g_v);
    cudaGetSymbolAddress((void**)&p_S,     g_S);
    cudaGetSymbolAddress((void**)&p_stat,  g_rowstat);
    cudaGetSymbolAddress((void**)&p_fp,    g_fp);
    cudaGetSymbolAddress((void**)&p_f2,    g_f2);
    cudaGetSymbolAddress((void**)&p_msc,   g_msc);
    cudaGetSymbolAddress((void**)&p_ginh,  g_ginh);
    cudaGetSymbolAddress((void**)&p_ginl,  g_ginl);
    cudaGetSymbolAddress((void**)&p_xh,    g_xh);
    cudaGetSymbolAddress((void**)&p_xl,    g_xl);
    cudaGetSymbolAddress((void**)&p_qh,    g_qh);
    cudaGetSymbolAddress((void**)&p_ql,    g_ql);
    cudaGetSymbolAddress((void**)&p_kh,    g_kh);
    cudaGetSymbolAddress((void**)&p_kl,    g_kl);
    cudaGetSymbolAddress((void**)&p_yh,    g_yh);
    cudaGetSymbolAddress((void**)&p_yl,    g_yl);
    cudaGetSymbolAddress((void**)&p_Oh,    g_Oh);
    cudaGetSymbolAddress((void**)&p_Ol,    g_Ol);
    cudaGetSymbolAddress((void**)&p_wfh,   g_wfh);
    cudaGetSymbolAddress((void**)&p_wfl,   g_wfl);
    cudaGetSymbolAddress((void**)&p_wqh,   g_wqh);
    cudaGetSymbolAddress((void**)&p_wql,   g_wql);
    cudaGetSymbolAddress((void**)&p_wkh,   g_wkh);
    cudaGetSymbolAddress((void**)&p_wkl,   g_wkl);
    cudaGetSymbolAddress((void**)&p_wvh,   g_wvh);
    cudaGetSymbolAddress((void**)&p_wvl,   g_wvl);
    cudaGetSymbolAddress((void**)&p_wfush, g_wfush);
    cudaGetSymbolAddress((void**)&p_wfusl, g_wfusl);
    cudaGetSymbolAddress((void**)&p_wmh,   g_wmh);
    cudaGetSymbolAddress((void**)&p_wml,   g_wml);

    cudaFuncSetAttribute(attn_qk, cudaFuncAttributeMaxDynamicSharedMemorySize, QK_SMEM);
    cudaFuncSetAttribute(attn_av, cudaFuncAttributeMaxDynamicSharedMemorySize, AV_SMEM);
    cudaFuncSetAttribute(tgemm,   cudaFuncAttributeMaxDynamicSharedMemorySize, TG_SMEM);

    // ---- 0. weight bf16 splits (independent)
    split2<<<128*128/256, 256>>>(W_feat, p_wfh, p_wfl);
    split2<<<CO*CO/256, 256>>>(W_q, p_wqh, p_wql);
    split2<<<CO*CO/256, 256>>>(W_k, p_wkh, p_wkl);
    split2<<<CO*CO/256, 256>>>(W_v, p_wvh, p_wvl);
    split2<<<CO*FUSC/256, 256>>>(W_fus, p_wfush, p_wfusl);
    split2<<<CO*CO/256, 256>>>(W_mlp, p_wmh, p_wml);

    // ---- 1. KNN + transpose + gathers
    knn_kernel<<<MTOT, 256>>>(xyz);
    transpose_f<<<dim3(NN/32, CIN/32, BB), dim3(32,8)>>>(f);
    geo_pre<<<MTOT, 128>>>(xyz, W_geo);
    gather_feat<<<RTOT/2, 256>>>();

    // ---- 2. feat GEMM (tensor): [RTOT,128] x W_feat^T -> g_act[:,128:]
    tgemm<<<dim3(1, RTOT/128), 128, TG_SMEM>>>(p_ginh, p_ginl, p_wfh, p_wfl,
                                               p_act + 128, 128, 128, CO, 2);

    // ---- 3. branch BN + maxpool
    run_bn(p_act, RTOT, p_msc + 0*512, 128);
    branch_apply<<<MTOT, 256>>>(p_msc + 0*512, gg, bg, gf, bf);

    // ---- 4. BatchNorm1d -> x (bf16 split only)
    run_bn(p_featv, MTOT, p_msc + 1*512, 32);
    bn_apply_split<<<MTOT, 256>>>(p_featv, p_msc + 1*512, g_bn, b_bn, 0, p_xh, p_xl);

    // ---- 5. q/k/v (tensor GEMMs) + BN
    tgemm<<<dim3(2, MTOT/128), 128, TG_SMEM>>>(p_xh, p_xl, p_wqh, p_wql, p_q, CO, CO, CO, 4);
    tgemm<<<dim3(2, MTOT/128), 128, TG_SMEM>>>(p_xh, p_xl, p_wkh, p_wkl, p_k, CO, CO, CO, 4);
    tgemm<<<dim3(2, MTOT/128), 128, TG_SMEM>>>(p_xh, p_xl, p_wvh, p_wvl, p_v, CO, CO, CO, 4);
    run_bn(p_q, MTOT, p_msc + 2*512, 32);
    bn_apply_split<<<MTOT, 256>>>(p_q, p_msc + 2*512, gq, bq, 1, p_qh, p_ql);
    run_bn(p_k, MTOT, p_msc + 3*512, 32);
    bn_apply_split<<<MTOT, 256>>>(p_k, p_msc + 3*512, gk, bk, 1, p_kh, p_kl);
    run_bn(p_v, MTOT, p_msc + 4*512, 32);
    bn_apply<<<MTOT, 256>>>(p_v, p_v, p_msc + 4*512, gv, bv, nullptr, 1);
    vt_convert<<<dim3(NN/32, 2, BB*HEADS), dim3(32,8)>>>();

    // ---- 6. attention (tcgen05) with folded softmax
    attn_qk<<<dim3(16, 16, BB*HEADS), 128, QK_SMEM>>>(p_S);
    softmax_stats<<<BB*HEADS*NN, 256>>>(p_S, p_stat);
    attn_av<<<dim3(16, BB*HEADS), 128, AV_SMEM>>>(p_S, p_stat);

    // ---- 7. fus (tensor) + BN + residual
    tgemm<<<dim3(2, MTOT/128), 128, TG_SMEM>>>(p_Oh, p_Ol, p_wfush, p_wfusl,
                                               p_fp, FUSC, FUSC, CO, 7);
    run_bn(p_fp, MTOT, p_msc + 5*512, 32);
    bn_apply<<<MTOT, 256>>>(p_fp, p_f2, p_msc + 5*512, gfu, bfu, p_featv, 1);

    // ---- 8. layernorm + mlp (tensor) + out
    layernorm_kernel<<<MTOT, 256>>>(p_f2, g_ln, b_ln);
    tgemm<<<dim3(2, MTOT/128), 128, TG_SMEM>>>(p_yh, p_yl, p_wmh, p_wml, p_fp, CO, CO, CO, 4);
    final_out<<<dim3(NN/32, CO/32, BB), dim3(32,8)>>>(b_mlp, out);

    (void)in_sizes; (void)n_in; (void)out_size;
}

// round 8
// speedup vs baseline: 2.3971x; 1.5344x over previous
#include <cuda_runtime.h>
#include <cuda_bf16.h>
#include <cfloat>
#include <math.h>
#include <cstdint>

#if defined(__CUDA_ARCH__) && defined(__CUDA_ARCH_FEAT_SM103_ALL)
#define HAS_TC 1
#else
#define HAS_TC 0
#endif

// ---------------- problem constants ----------------
#define BB    4
#define NN    2048
#define KNB   21
#define CIN   64
#define CO    256
#define HEADS 7
#define WCH   64
#define FUSC  (HEADS*WCH)          /* 448 */
#define MTOT  (BB*NN)              /* 8192 */
#define RTOT  (MTOT*KNB)           /* 172032 */
#define EPSB  1e-5f

// ---------------- scratch ----------------
__device__ int    g_idx[RTOT];
__device__ float  g_ft[MTOT*CIN];
__device__ float  g_act[(size_t)RTOT*CO];
__device__ float  g_featv[MTOT*CO];
__device__ float  g_q[MTOT*CO];
__device__ float  g_k[MTOT*CO];
__device__ float  g_v[MTOT*CO];
__device__ float  g_S[(size_t)BB*HEADS*NN*NN];
__device__ float  g_tstat[(size_t)BB*HEADS*NN*32*2];   // per-row, per-64col-tile {max,sum}
__device__ float  g_rowstat[BB*HEADS*NN*2];
__device__ float  g_fp[MTOT*CO];
__device__ float  g_f2[MTOT*CO];
__device__ float  g_partf[256*2*CO];
__device__ float  g_msc[6*2*CO];
// bf16 hi/lo splits
__device__ __nv_bfloat16 g_ginh[(size_t)RTOT*128], g_ginl[(size_t)RTOT*128];
__device__ __nv_bfloat16 g_xh[MTOT*CO],  g_xl[MTOT*CO];
__device__ __nv_bfloat16 g_qh[MTOT*CO],  g_ql[MTOT*CO];
__device__ __nv_bfloat16 g_kh[MTOT*CO],  g_kl[MTOT*CO];
__device__ __nv_bfloat16 g_yh[MTOT*CO],  g_yl[MTOT*CO];
__device__ __nv_bfloat16 g_Oh[MTOT*FUSC], g_Ol[MTOT*FUSC];
__device__ __nv_bfloat16 g_vth[(size_t)BB*HEADS*WCH*NN], g_vtl[(size_t)BB*HEADS*WCH*NN];
__device__ __nv_bfloat16 g_wfh[128*128],  g_wfl[128*128];
__device__ __nv_bfloat16 g_wqh[CO*CO],    g_wql[CO*CO];
__device__ __nv_bfloat16 g_wkh[CO*CO],    g_wkl[CO*CO];
__device__ __nv_bfloat16 g_wvh[CO*CO],    g_wvl[CO*CO];
__device__ __nv_bfloat16 g_wfush[CO*FUSC],g_wfusl[CO*FUSC];
__device__ __nv_bfloat16 g_wmh[CO*CO],    g_wml[CO*CO];

// ---------------- helpers ----------------
__device__ __forceinline__ uint32_t smem_u32(const void* p) {
    uint32_t a;
    asm("{ .reg .u64 t; cvta.to.shared.u64 t, %1; cvt.u32.u64 %0, t; }" : "=r"(a) : "l"(p));
    return a;
}
__device__ __forceinline__ uint32_t swz(uint32_t o) { return o ^ ((o >> 3) & 0x70); }
__device__ __forceinline__ uint32_t bpackh(__nv_bfloat16 a, __nv_bfloat16 b) {
    __nv_bfloat162 t = __halves2bfloat162(a, b);
    return *reinterpret_cast<uint32_t*>(&t);
}

#if HAS_TC
__device__ __forceinline__ uint32_t elect_one_pred() {
    uint32_t pred;
    asm volatile("{\n\t.reg .pred p;\n\telect.sync _|p, 0xFFFFFFFF;\n\tselp.b32 %0, 1, 0, p;\n\t}" : "=r"(pred));
    return pred;
}

#define MBARRIER_INIT(addr, cnt) \
    asm volatile("mbarrier.init.shared.b64 [%0], %1;" :: "r"((uint32_t)(addr)), "r"((uint32_t)(cnt)) : "memory")

#define MBARRIER_WAIT_PARITY(mbar_smem_addr, phase_parity) do { \
    uint32_t _mbar = (uint32_t)(mbar_smem_addr); \
    uint32_t _parity = (uint32_t)(phase_parity); \
    uint32_t _done; \
    asm volatile("{\n\t.reg .pred p;\n\t" \
        "mbarrier.try_wait.parity.acquire.cta.shared::cta.b64 p, [%1], %2;\n\t" \
        "selp.b32 %0, 1, 0, p;\n\t}" : "=r"(_done) : "r"(_mbar), "r"(_parity) : "memory"); \
    if (!_done) { \
        asm volatile("{\n\t.reg .pred P1;\n\t" \
            "WAIT_LOOP_%=:\n\t" \
            "mbarrier.try_wait.parity.acquire.cta.shared::cta.b64 P1, [%0], %1, 0x989680;\n\t" \
            "@P1 bra.uni WAIT_DONE_%=;\n\t" \
            "bra.uni WAIT_LOOP_%=;\n\t" \
            "WAIT_DONE_%=:\n\t}" :: "r"(_mbar), "r"(_parity) : "memory"); \
    } \
} while(0)

#define TCGEN05_ALLOC(sm, n) \
    asm volatile("tcgen05.alloc.cta_group::1.sync.aligned.shared::cta.b32 [%0], %1;" \
                 :: "r"((uint32_t)(sm)), "r"((uint32_t)(n)) : "memory")
#define TCGEN05_RELINQ() \
    asm volatile("tcgen05.relinquish_alloc_permit.cta_group::1.sync.aligned;")
#define TCGEN05_DEALLOC(t, n) \
    asm volatile("tcgen05.dealloc.cta_group::1.sync.aligned.b32 %0, %1;" :: "r"(t), "r"(n))
#define TCGEN05_COMMIT(mbar) \
    asm volatile("tcgen05.commit.cta_group::1.mbarrier::arrive::one.shared::cluster.b64 [%0];" \
                 :: "r"((uint32_t)(mbar)) : "memory")
#define TCGEN05_FENCE_AFTER()  asm volatile("tcgen05.fence::after_thread_sync;" ::: "memory")
#define TCGEN05_FENCE_BEFORE() asm volatile("tcgen05.fence::before_thread_sync;" ::: "memory")
#define TCGEN05_WAIT_LD()      asm volatile("tcgen05.wait::ld.sync.aligned;" ::: "memory")
#define FENCE_ASYNC_SHARED()   asm volatile("fence.proxy.async.shared::cta;" ::: "memory")

#define TCGEN05_LD_X32(r, addr) \
    asm volatile("tcgen05.ld.sync.aligned.32x32b.x32.b32 " \
        "{%0, %1, %2, %3, %4, %5, %6, %7, %8, %9, %10, %11, %12, %13, %14, %15, " \
        " %16, %17, %18, %19, %20, %21, %22, %23, %24, %25, %26, %27, %28, %29, %30, %31}, [%32];" \
        : "=r"((r)[0]),  "=r"((r)[1]),  "=r"((r)[2]),  "=r"((r)[3]), \
          "=r"((r)[4]),  "=r"((r)[5]),  "=r"((r)[6]),  "=r"((r)[7]), \
          "=r"((r)[8]),  "=r"((r)[9]),  "=r"((r)[10]), "=r"((r)[11]), \
          "=r"((r)[12]), "=r"((r)[13]), "=r"((r)[14]), "=r"((r)[15]), \
          "=r"((r)[16]), "=r"((r)[17]), "=r"((r)[18]), "=r"((r)[19]), \
          "=r"((r)[20]), "=r"((r)[21]), "=r"((r)[22]), "=r"((r)[23]), \
          "=r"((r)[24]), "=r"((r)[25]), "=r"((r)[26]), "=r"((r)[27]), \
          "=r"((r)[28]), "=r"((r)[29]), "=r"((r)[30]), "=r"((r)[31]) \
        : "r"(addr))

static __device__ __forceinline__ uint64_t make_desc(uint32_t addr) {
    const uint64_t base =
        (uint64_t(2) << 61) | (uint64_t(1) << 46) | (uint64_t(64) << 32) | (uint64_t(1) << 16);
    return base | ((uint64_t)(addr >> 4) & 0x3FFF);
}

__device__ __forceinline__ void mma_f16_ss(uint32_t d, uint64_t a, uint64_t b,
                                           uint32_t idesc, uint32_t en) {
    asm volatile(
        "{\n\t.reg .pred p;\n\tsetp.ne.u32 p, %5, 0;\n\t"
        "tcgen05.mma.cta_group::1.kind::f16 [%0], %1, %2, %3, {%4, %4, %4, %4}, p;\n\t}"
        :: "r"(d), "l"(a), "l"(b), "r"(idesc), "r"(0u), "r"(en) : "memory");
}

#define IDESC_N128 ((1u<<4)|(1u<<7)|(1u<<10)|((128u/8)<<17)|((128u/16)<<24))
#define IDESC_N64  ((1u<<4)|(1u<<7)|(1u<<10)|(( 64u/8)<<17)|((128u/16)<<24))

// ---- shared tensor-GEMM core: 128x128 out, K chunks of 64, 256 threads ----
__device__ __forceinline__ void tgemm_core(char* sb, uint32_t base,
    const __nv_bfloat16* __restrict__ Ah, const __nv_bfloat16* __restrict__ Al,
    const __nv_bfloat16* __restrict__ Bh, const __nv_bfloat16* __restrict__ Bl,
    float* __restrict__ C, int lda, int ldb, int ldc, int nkc, int m0, int n0)
{
    uint32_t ctrl = base + 65536;
    uint32_t mbar = ctrl + 8;
    int t = threadIdx.x;

    if (t == 0) MBARRIER_INIT(mbar, 1);
    if (t < 32) { TCGEN05_ALLOC(ctrl, 128); TCGEN05_RELINQ(); }
    __syncthreads();
    uint32_t tmem;
    asm volatile("ld.shared.b32 %0, [%1];" : "=r"(tmem) : "r"(ctrl));

    Ah += (size_t)m0 * lda; Al += (size_t)m0 * lda;
    Bh += (size_t)n0 * ldb; Bl += (size_t)n0 * ldb;

    uint64_t dAh = make_desc(base + 0*16384);
    uint64_t dAl = make_desc(base + 1*16384);
    uint64_t dBh = make_desc(base + 2*16384);
    uint64_t dBl = make_desc(base + 3*16384);

    int rb = t >> 4, kq = t & 15;

    for (int kc = 0; kc < nkc; kc++) {
        if (kc > 0) MBARRIER_WAIT_PARITY(mbar, (kc-1) & 1);
        int k0 = kc*64;
#pragma unroll
        for (int i = 0; i < 8; i++) {
            int r = rb + i*16;
            uint32_t so = swz((uint32_t)(r*128 + kq*8));
            *(uint2*)(sb + 0*16384 + so) = *(const uint2*)(Ah + (size_t)r*lda + k0 + kq*4);
            *(uint2*)(sb + 1*16384 + so) = *(const uint2*)(Al + (size_t)r*lda + k0 + kq*4);
            *(uint2*)(sb + 2*16384 + so) = *(const uint2*)(Bh + (size_t)r*ldb + k0 + kq*4);
            *(uint2*)(sb + 3*16384 + so) = *(const uint2*)(Bl + (size_t)r*ldb + k0 + kq*4);
        }
        __syncthreads();
        if (t < 32) {
            if (elect_one_pred()) {
                FENCE_ASYNC_SHARED();
#pragma unroll
                for (int ks = 0; ks < 4; ks++) {
                    uint64_t o = ks*2;
                    mma_f16_ss(tmem, dAh+o, dBh+o, IDESC_N128, (kc > 0 || ks > 0) ? 1u : 0u);
                    mma_f16_ss(tmem, dAh+o, dBl+o, IDESC_N128, 1u);
                    mma_f16_ss(tmem, dAl+o, dBh+o, IDESC_N128, 1u);
                }
                TCGEN05_COMMIT(mbar);
            }
        }
    }
    MBARRIER_WAIT_PARITY(mbar, (nkc-1) & 1);
    TCGEN05_FENCE_AFTER();

    int w = t >> 5, lane = t & 31;
    int sub = w & 3, half = w >> 2;
    float* Crow = C + (size_t)(m0 + sub*32 + lane)*ldc + n0;
#pragma unroll
    for (int gi = 0; gi < 2; gi++) {
        int g = half*2 + gi;
        uint32_t r[32];
        TCGEN05_LD_X32(r, tmem + g*32);
        TCGEN05_WAIT_LD();
        TCGEN05_FENCE_BEFORE();
#pragma unroll
        for (int j = 0; j < 8; j++)
            *(float4*)(Crow + g*32 + j*4) = make_float4(
                __uint_as_float(r[j*4+0]), __uint_as_float(r[j*4+1]),
                __uint_as_float(r[j*4+2]), __uint_as_float(r[j*4+3]));
    }
    __syncthreads();
    if (t < 32) TCGEN05_DEALLOC(tmem, 128);
}
#else
// SIMT fallback core (generic compute_103 pass; never runs on GB300)
__device__ __forceinline__ void tgemm_core_simt(
    const __nv_bfloat16* Ah, const __nv_bfloat16* Al,
    const __nv_bfloat16* Bh, const __nv_bfloat16* Bl,
    float* C, int lda, int ldb, int ldc, int nkc, int m0, int n0)
{
    int t = threadIdx.x;
    int m = m0 + (t >> 1);
    int nb = (t & 1) * 64;
    for (int n = nb; n < nb + 64; n++) {
        float acc = 0.0f;
        for (int k = 0; k < nkc*64; k++) {
            float a = __bfloat162float(Ah[(size_t)m*lda+k]) + __bfloat162float(Al[(size_t)m*lda+k]);
            float b = __bfloat162float(Bh[(size_t)(n0+n)*ldb+k]) + __bfloat162float(Bl[(size_t)(n0+n)*ldb+k]);
            acc = fmaf(a, b, acc);
        }
        C[(size_t)m*ldc + n0 + n] = acc;
    }
}
#endif // HAS_TC

#define TG_SMEM (1024 + 4*16384 + 64)

// =====================================================================
// KNN
// =====================================================================
__global__ void knn_kernel(const float* __restrict__ xyz)
{
    __shared__ float d2s[NN];
    __shared__ float rv[256];
    __shared__ int   ri[256];
    int m = blockIdx.x;
    int b = m >> 11;
    int t = threadIdx.x;
    const float* base = xyz + (size_t)(b << 11) * 3;

    float qx = xyz[m*3+0], qy = xyz[m*3+1], qz = xyz[m*3+2];
    float sqq = qx*qx + qy*qy + qz*qz;

    for (int j = t; j < NN; j += 256) {
        float px = base[j*3+0], py = base[j*3+1], pz = base[j*3+2];
        float sqp = px*px + py*py + pz*pz;
        float dot = qx*px + qy*py + qz*pz;
        d2s[j] = sqq + sqp - 2.0f*dot;
    }
    __syncthreads();

    for (int it = 0; it < KNB; it++) {
        float bv = FLT_MAX; int bi = 0x3fffffff;
        for (int j = t; j < NN; j += 256) {
            float v = d2s[j];
            if (v < bv) { bv = v; bi = j; }
        }
        rv[t] = bv; ri[t] = bi;
        __syncthreads();
        for (int s = 128; s; s >>= 1) {
            if (t < s) {
                float ov = rv[t+s]; int oi = ri[t+s];
                if (ov < rv[t] || (ov == rv[t] && oi < ri[t])) { rv[t] = ov; ri[t] = oi; }
            }
            __syncthreads();
        }
        if (t == 0) { g_idx[(size_t)m*KNB + it] = ri[0]; d2s[ri[0]] = FLT_MAX; }
        __syncthreads();
    }
}

// =====================================================================
// transpose f
// =====================================================================
__global__ void transpose_f(const float* __restrict__ f)
{
    __shared__ float tile[32][33];
    int b  = blockIdx.z;
    int n0 = blockIdx.x * 32;
    int c0 = blockIdx.y * 32;
    int tx = threadIdx.x, ty = threadIdx.y;
#pragma unroll
    for (int i = 0; i < 32; i += 8)
        tile[ty+i][tx] = f[((size_t)b*CIN + c0 + ty + i)*NN + n0 + tx];
    __syncthreads();
#pragma unroll
    for (int i = 0; i < 32; i += 8)
        g_ft[((size_t)b*NN + n0 + ty + i)*CIN + c0 + tx] = tile[tx][ty+i];
}

// =====================================================================
// geo branch pre-activation
// =====================================================================
__global__ void geo_pre(const float* __restrict__ xyz, const float* __restrict__ Wg)
{
    int m = blockIdx.x;
    int c = threadIdx.x;
    int b = m >> 11;
    float w0 = Wg[c*6+0], w1 = Wg[c*6+1], w2 = Wg[c*6+2];
    float w3 = Wg[c*6+3], w4 = Wg[c*6+4], w5 = Wg[c*6+5];
    float cx = xyz[m*3+0], cy = xyz[m*3+1], cz = xyz[m*3+2];
    float base = w0*cx + w1*cy + w2*cz;
    for (int k = 0; k < KNB; k++) {
        int nb = g_idx[(size_t)m*KNB + k];
        const float* pp = xyz + (size_t)((b << 11) + nb)*3;
        float dx = pp[0]-cx, dy = pp[1]-cy, dz = pp[2]-cz;
        g_act[((size_t)m*KNB + k)*CO + c] = base + w3*dx + w4*dy + w5*dz;
    }
}

// =====================================================================
// gather feat_in -> bf16 split (vectorized, 32-bit index math)
// =====================================================================
__global__ void gather_feat()
{
    uint32_t tid = blockIdx.x*256u + threadIdx.x;  // RTOT*32 threads
    uint32_t r = tid >> 5;
    uint32_t c4 = (tid & 31u) * 4u;
    uint32_t m = r / KNB;
    uint32_t b = m >> 11;
    float4 v;
    if (c4 < 64u) {
        uint32_t nb = (uint32_t)g_idx[r];
        v = *(const float4*)(g_ft + (size_t)((b << 11) + nb)*CIN + c4);
    } else {
        v = *(const float4*)(g_ft + (size_t)m*CIN + (c4 - 64u));
    }
    __nv_bfloat16 h0 = __float2bfloat16(v.x);
    __nv_bfloat16 h1 = __float2bfloat16(v.y);
    __nv_bfloat16 h2 = __float2bfloat16(v.z);
    __nv_bfloat16 h3 = __float2bfloat16(v.w);
    size_t o = (size_t)r*128 + c4;
    *(uint2*)(g_ginh + o) = make_uint2(bpackh(h0,h1), bpackh(h2,h3));
    *(uint2*)(g_ginl + o) = make_uint2(
        bpackh(__float2bfloat16(v.x - __bfloat162float(h0)),
               __float2bfloat16(v.y - __bfloat162float(h1))),
        bpackh(__float2bfloat16(v.z - __bfloat162float(h2)),
               __float2bfloat16(v.w - __bfloat162float(h3))));
}

// =====================================================================
// tensor GEMM wrappers
// =====================================================================
__global__ void __launch_bounds__(256, 1)
tgemm(const __nv_bfloat16* __restrict__ Ah, const __nv_bfloat16* __restrict__ Al,
      const __nv_bfloat16* __restrict__ Bh, const __nv_bfloat16* __restrict__ Bl,
      float* __restrict__ C, int lda, int ldb, int ldc, int nkc)
{
#if HAS_TC
    extern __shared__ char sm[];
    uint32_t raw = smem_u32(sm);
    uint32_t base = (raw + 1023) & ~1023u;
    tgemm_core(sm + (base - raw), base, Ah, Al, Bh, Bl, C, lda, ldb, ldc, nkc,
               blockIdx.y*128, blockIdx.x*128);
#else
    tgemm_core_simt(Ah, Al, Bh, Bl, C, lda, ldb, ldc, nkc, blockIdx.y*128, blockIdx.x*128);
#endif
}

__global__ void __launch_bounds__(256, 1)
qkv_gemm()
{
    int z = blockIdx.z;
    const __nv_bfloat16* Bh = (z==0) ? g_wqh : (z==1) ? g_wkh : g_wvh;
    const __nv_bfloat16* Bl = (z==0) ? g_wql : (z==1) ? g_wkl : g_wvl;
    float* C = (z==0) ? g_q : (z==1) ? g_k : g_v;
#if HAS_TC
    extern __shared__ char sm[];
    uint32_t raw = smem_u32(sm);
    uint32_t base = (raw + 1023) & ~1023u;
    tgemm_core(sm + (base - raw), base, g_xh, g_xl, Bh, Bl, C, CO, CO, CO, 4,
               blockIdx.y*128, blockIdx.x*128);
#else
    tgemm_core_simt(g_xh, g_xl, Bh, Bl, C, CO, CO, CO, 4, blockIdx.y*128, blockIdx.x*128);
#endif
}

// =====================================================================
// BN stats: fp32 partials (4 accumulators, fixed order), double combine
// =====================================================================
__device__ __forceinline__ void bn_partial_region(const float* X, long rows,
                                                  int nblk, int blk, int region)
{
    int c = threadIdx.x;
    long per = (rows + nblk - 1) / nblk;
    long r0 = (long)blk * per;
    long r1 = r0 + per; if (r1 > rows) r1 = rows;
    float a0=0,a1=0,a2=0,a3=0, q0=0,q1=0,q2=0,q3=0;
    long r = r0;
    for (; r + 4 <= r1; r += 4) {
        float v0 = X[(r+0)*CO + c], v1 = X[(r+1)*CO + c];
        float v2 = X[(r+2)*CO + c], v3 = X[(r+3)*CO + c];
        a0 += v0; q0 = fmaf(v0,v0,q0);
        a1 += v1; q1 = fmaf(v1,v1,q1);
        a2 += v2; q2 = fmaf(v2,v2,q2);
        a3 += v3; q3 = fmaf(v3,v3,q3);
    }
    for (; r < r1; r++) { float v = X[r*CO + c]; a0 += v; q0 = fmaf(v,v,q0); }
    g_partf[((size_t)region*2 + 0)*CO + c] = (a0+a1) + (a2+a3);
    g_partf[((size_t)region*2 + 1)*CO + c] = (q0+q1) + (q2+q3);
}

__global__ void bn_stats_partial(const float* __restrict__ X, long rows)
{
    bn_partial_region(X, rows, gridDim.x, blockIdx.x, blockIdx.x);
}

__global__ void bn_stats_final(int nblocks, long rows, float* msc)
{
    int c = threadIdx.x;
    double s = 0.0, s2 = 0.0;
    for (int i = 0; i < nblocks; i++) {
        s  += (double)g_partf[((size_t)i*2 + 0)*CO + c];
        s2 += (double)g_partf[((size_t)i*2 + 1)*CO + c];
    }
    double mean = s / (double)rows;
    double var  = s2 / (double)rows - mean*mean;
    msc[c]      = (float)mean;
    msc[CO + c] = (float)(1.0 / sqrt(var + (double)EPSB));
}

// merged q/k/v stats: grid (64,3); regions y*64+x
__global__ void bn_stats_qkv()
{
    const float* X = (blockIdx.y==0) ? g_q : (blockIdx.y==1) ? g_k : g_v;
    bn_partial_region(X, MTOT, 64, blockIdx.x, blockIdx.y*64 + blockIdx.x);
}
__global__ void bn_final_qkv(float* msc)
{
    int y = blockIdx.x;   // 0..2
    int c = threadIdx.x;
    double s = 0.0, s2 = 0.0;
    for (int i = y*64; i < y*64 + 64; i++) {
        s  += (double)g_partf[((size_t)i*2 + 0)*CO + c];
        s2 += (double)g_partf[((size_t)i*2 + 1)*CO + c];
    }
    double mean = s / (double)MTOT;
    double var  = s2 / (double)MTOT - mean*mean;
    msc[(2+y)*512 + c]      = (float)mean;
    msc[(2+y)*512 + CO + c] = (float)(1.0 / sqrt(var + (double)EPSB));
}

// =====================================================================
// branch BN + relu + maxpool
// =====================================================================
__global__ void branch_apply(const float* msc,
                             const float* __restrict__ g_geo, const float* __restrict__ b_geo,
                             const float* __restrict__ g_fea, const float* __restrict__ b_fea)
{
    int m = blockIdx.x;
    int c = threadIdx.x;
    float mean = msc[c], istd = msc[CO + c];
    float ga = (c < 128) ? g_geo[c] : g_fea[c - 128];
    float be = (c < 128) ? b_geo[c] : b_fea[c - 128];
    float sc = istd * ga;
    float best = -FLT_MAX;
    const float* base = g_act + (size_t)m*KNB*CO + c;
#pragma unroll 3
    for (int k = 0; k < KNB; k++) {
        float zv = base[(size_t)k*CO];
        float y = (zv - mean) * sc + be;
        y = fmaxf(y, 0.0f);
        best = fmaxf(best, y);
    }
    g_featv[(size_t)m*CO + c] = best;
}

// =====================================================================
// BN apply variants
// =====================================================================
__global__ void bn_apply(const float* __restrict__ in, float* __restrict__ out,
                         const float* msc,
                         const float* __restrict__ gamma, const float* __restrict__ beta,
                         const float* __restrict__ res, int do_relu)
{
    size_t i = (size_t)blockIdx.x * blockDim.x + threadIdx.x;
    int c = (int)(i & (CO-1));
    float y = (in[i] - msc[c]) * msc[CO + c] * gamma[c] + beta[c];
    if (do_relu) y = fmaxf(y, 0.0f);
    if (res) y += res[i];
    out[i] = y;
}

__global__ void bn_apply_split(const float* __restrict__ in,
                               const float* msc,
                               const float* __restrict__ gamma, const float* __restrict__ beta,
                               int do_relu,
                               __nv_bfloat16* __restrict__ oh, __nv_bfloat16* __restrict__ ol)
{
    size_t i = (size_t)blockIdx.x * blockDim.x + threadIdx.x;
    int c = (int)(i & (CO-1));
    float y = (in[i] - msc[c]) * msc[CO + c] * gamma[c] + beta[c];
    if (do_relu) y = fmaxf(y, 0.0f);
    __nv_bfloat16 hb = __float2bfloat16(y);
    oh[i] = hb;
    ol[i] = __float2bfloat16(y - __bfloat162float(hb));
}

// merged q/k/v BN apply: grid (MTOT*CO/256, 3)
__global__ void bn_apply_qkv(const float* msc,
                             const float* __restrict__ gq, const float* __restrict__ bq,
                             const float* __restrict__ gk, const float* __restrict__ bk,
                             const float* __restrict__ gv, const float* __restrict__ bv)
{
    int y = blockIdx.y;
    size_t i = (size_t)blockIdx.x * 256 + threadIdx.x;
    int c = (int)(i & (CO-1));
    const float* in = (y==0) ? g_q : (y==1) ? g_k : g_v;
    const float* ga = (y==0) ? gq : (y==1) ? gk : gv;
    const float* be = (y==0) ? bq : (y==1) ? bk : bv;
    const float* ms = msc + (2+y)*512;
    float v = fmaxf((in[i] - ms[c]) * ms[CO + c] * ga[c] + be[c], 0.0f);
    if (y == 2) { g_v[i] = v; return; }
    __nv_bfloat16 hb = __float2bfloat16(v);
    __nv_bfloat16 lb = __float2bfloat16(v - __bfloat162float(hb));
    if (y == 0) { g_qh[i] = hb; g_ql[i] = lb; }
    else        { g_kh[i] = hb; g_kl[i] = lb; }
}

// =====================================================================
// fused weight splits (one launch)
// =====================================================================
__global__ void split_weights(const float* __restrict__ Wf, const float* __restrict__ Wq,
                              const float* __restrict__ Wk, const float* __restrict__ Wv,
                              const float* __restrict__ Wfus, const float* __restrict__ Wm)
{
    int i = blockIdx.x*256 + threadIdx.x;   // 393216 total
    const float* src; __nv_bfloat16 *dh, *dl; int off;
    if      (i < 16384)  { src = Wf;   dh = g_wfh;   dl = g_wfl;   off = i; }
    else if (i < 81920)  { src = Wq;   dh = g_wqh;   dl = g_wql;   off = i - 16384; }
    else if (i < 147456) { src = Wk;   dh = g_wkh;   dl = g_wkl;   off = i - 81920; }
    else if (i < 212992) { src = Wv;   dh = g_wvh;   dl = g_wvl;   off = i - 147456; }
    else if (i < 327680) { src = Wfus; dh = g_wfush; dl = g_wfusl; off = i - 212992; }
    else                 { src = Wm;   dh = g_wmh;   dl = g_wml;   off = i - 327680; }
    float v = src[off];
    __nv_bfloat16 hb = __float2bfloat16(v);
    dh[off] = hb;
    dl[off] = __float2bfloat16(v - __bfloat162float(hb));
}

// =====================================================================
// v -> per-head transposed bf16 split
// =====================================================================
__global__ void vt_convert()
{
    __shared__ float tile[32][33];
    int z  = blockIdx.z;
    int b  = z / HEADS, h = z - b*HEADS;
    int m0 = blockIdx.x * 32;
    int c0 = blockIdx.y * 32;
    int tx = threadIdx.x, ty = threadIdx.y;
#pragma unroll
    for (int i = 0; i < 32; i += 8)
        tile[ty+i][tx] = g_v[((size_t)(b*NN) + m0 + ty + i)*CO + h*32 + c0 + tx];
    __syncthreads();
#pragma unroll
    for (int i = 0; i < 32; i += 8) {
        int c = c0 + ty + i, m = m0 + tx;
        float v = tile[tx][ty+i];
        __nv_bfloat16 hb = __float2bfloat16(v);
        size_t o = (size_t)z*WCH*NN + (size_t)c*NN + m;
        g_vth[o] = hb;
        g_vtl[o] = __float2bfloat16(v - __bfloat162float(hb));
    }
}

// =====================================================================
// attn QK^T with fused per-tile softmax stats. grid (16,16,28), 256 thr
// =====================================================================
#define QK_SMEM (1024 + 4*16384 + 64)

__global__ void __launch_bounds__(256, 1)
attn_qk(float* __restrict__ S)
{
#if HAS_TC
    extern __shared__ char sm[];
    uint32_t raw = smem_u32(sm);
    uint32_t base = (raw + 1023) & ~1023u;
    char* sb = sm + (base - raw);
    uint32_t ctrl = base + 65536;
    uint32_t mbar = ctrl + 8;

    int t = threadIdx.x;
    int z = blockIdx.z;
    int b = z / HEADS, h = z - b*HEADS;
    int m0 = blockIdx.y * 128, n0 = blockIdx.x * 128;

    if (t == 0) MBARRIER_INIT(mbar, 1);
    if (t < 32) { TCGEN05_ALLOC(ctrl, 128); TCGEN05_RELINQ(); }
    __syncthreads();
    uint32_t tmem;
    asm volatile("ld.shared.b32 %0, [%1];" : "=r"(tmem) : "r"(ctrl));

    const __nv_bfloat16* pAh = g_qh + ((size_t)(b*NN) + m0)*CO + h*32;
    const __nv_bfloat16* pAl = g_ql + ((size_t)(b*NN) + m0)*CO + h*32;
    const __nv_bfloat16* pBh = g_kh + ((size_t)(b*NN) + n0)*CO + h*32;
    const __nv_bfloat16* pBl = g_kl + ((size_t)(b*NN) + n0)*CO + h*32;

    int rb = t >> 4, kq = t & 15;
#pragma unroll
    for (int i = 0; i < 8; i++) {
        int r = rb + i*16;
        uint32_t so = swz((uint32_t)(r*128 + kq*8));
        *(uint2*)(sb + 0*16384 + so) = *(const uint2*)(pAh + (size_t)r*CO + kq*4);
        *(uint2*)(sb + 1*16384 + so) = *(const uint2*)(pAl + (size_t)r*CO + kq*4);
        *(uint2*)(sb + 2*16384 + so) = *(const uint2*)(pBh + (size_t)r*CO + kq*4);
        *(uint2*)(sb + 3*16384 + so) = *(const uint2*)(pBl + (size_t)r*CO + kq*4);
    }
    __syncthreads();

    if (t < 32) {
        if (elect_one_pred()) {
            FENCE_ASYNC_SHARED();
            uint64_t dAh = make_desc(base + 0*16384);
            uint64_t dAl = make_desc(base + 1*16384);
            uint64_t dBh = make_desc(base + 2*16384);
            uint64_t dBl = make_desc(base + 3*16384);
            bool first = true;
#pragma unroll
            for (int kc = 0; kc < 4; kc++) {
                uint64_t off = kc*2;
                mma_f16_ss(tmem, dAh+off, dBh+off, IDESC_N128, first ? 0u : 1u);
                first = false;
                mma_f16_ss(tmem, dAh+off, dBl+off, IDESC_N128, 1u);
                mma_f16_ss(tmem, dAl+off, dBh+off, IDESC_N128, 1u);
            }
            TCGEN05_COMMIT(mbar);
        }
    }
    MBARRIER_WAIT_PARITY(mbar, 0);
    TCGEN05_FENCE_AFTER();

    int w = t >> 5, lane = t & 31;
    int sub = w & 3, half = w >> 2;
    int m = m0 + sub*32 + lane;
    float* Srow = S + (size_t)z*NN*NN + (size_t)m*NN + n0;
    float mx = -FLT_MAX, sum = 0.0f;
#pragma unroll
    for (int gi = 0; gi < 2; gi++) {
        int g = half*2 + gi;
        uint32_t r[32];
        TCGEN05_LD_X32(r, tmem + g*32);
        TCGEN05_WAIT_LD();
        TCGEN05_FENCE_BEFORE();
        float gm = -FLT_MAX;
#pragma unroll
        for (int j = 0; j < 32; j++) gm = fmaxf(gm, __uint_as_float(r[j]));
        float gs = 0.0f;
#pragma unroll
        for (int j = 0; j < 8; j++) {
            float v0 = __uint_as_float(r[j*4+0]);
            float v1 = __uint_as_float(r[j*4+1]);
            float v2 = __uint_as_float(r[j*4+2]);
            float v3 = __uint_as_float(r[j*4+3]);
            gs += __expf(v0-gm) + __expf(v1-gm) + __expf(v2-gm) + __expf(v3-gm);
            *(float4*)(Srow + g*32 + j*4) = make_float4(v0, v1, v2, v3);
        }
        if (gi == 0) { mx = gm; sum = gs; }
        else if (gm <= mx) sum += gs * __expf(gm - mx);
        else { sum = sum * __expf(mx - gm) + gs; mx = gm; }
    }
    size_t ti = ((size_t)(z*NN + m)*32 + blockIdx.x*2 + half)*2;
    g_tstat[ti] = mx; g_tstat[ti+1] = sum;
    __syncthreads();
    if (t < 32) TCGEN05_DEALLOC(tmem, 128);
#else
    int t = threadIdx.x;
    int z = blockIdx.z;
    int b = z / HEADS, h = z - b*HEADS;
    int m0 = blockIdx.y * 128, n0 = blockIdx.x * 128;
    if (t >= 128) return;
    int m = m0 + t;
    const float* qp = g_q + ((size_t)(b*NN) + m)*CO + h*32;
    for (int half = 0; half < 2; half++) {
        float mx = -FLT_MAX, sum = 0.0f;
        for (int n = half*64; n < half*64 + 64; n++) {
            const float* kp = g_k + ((size_t)(b*NN) + n0 + n)*CO + h*32;
            float acc = 0.0f;
            for (int k = 0; k < 64; k++) acc = fmaf(qp[k], kp[k], acc);
            S[(size_t)z*NN*NN + (size_t)m*NN + n0 + n] = acc;
            mx = fmaxf(mx, acc);
        }
        for (int n = half*64; n < half*64 + 64; n++)
            sum += __expf(S[(size_t)z*NN*NN + (size_t)m*NN + n0 + n] - mx);
        size_t ti = ((size_t)(z*NN + m)*32 + blockIdx.x*2 + half)*2;
        g_tstat[ti] = mx; g_tstat[ti+1] = sum;
    }
#endif
}

// =====================================================================
// combine per-tile stats -> per-row {max, 1/sum}
// =====================================================================
__global__ void softmax_combine()
{
    int row = blockIdx.x*256 + threadIdx.x;   // BB*HEADS*NN rows
    float mx = -FLT_MAX;
#pragma unroll 8
    for (int i = 0; i < 32; i++) mx = fmaxf(mx, g_tstat[((size_t)row*32 + i)*2]);
    float sum = 0.0f;
#pragma unroll 8
    for (int i = 0; i < 32; i++)
        sum += g_tstat[((size_t)row*32 + i)*2 + 1] * __expf(g_tstat[((size_t)row*32 + i)*2] - mx);
    g_rowstat[row*2]   = mx;
    g_rowstat[row*2+1] = 1.0f / sum;
}

// =====================================================================
// attn A·V with inline softmax; epilogue -> bf16 split O. 256 threads
// =====================================================================
#define AV_SMEM (1024 + 49152 + 64 + 1024)

__global__ void __launch_bounds__(256, 1)
attn_av(const float* __restrict__ S, const float* __restrict__ stat)
{
#if HAS_TC
    extern __shared__ char sm[];
    uint32_t raw = smem_u32(sm);
    uint32_t base = (raw + 1023) & ~1023u;
    char* sb = sm + (base - raw);
    uint32_t off_Ah = 0, off_Al = 16384, off_Bh = 32768, off_Bl = 40960;
    uint32_t ctrl = base + 49152;
    uint32_t mbar = ctrl + 8;
    float* sst = (float*)(sb + 49216);

    int t = threadIdx.x;
    int z = blockIdx.y;
    int b = z / HEADS, h = z - b*HEADS;
    int m0 = blockIdx.x * 128;

    if (t == 0) MBARRIER_INIT(mbar, 1);
    if (t < 32) { TCGEN05_ALLOC(ctrl, 64); TCGEN05_RELINQ(); }
    sst[t] = stat[(size_t)(z*NN + m0)*2 + t];
    __syncthreads();
    uint32_t tmem;
    asm volatile("ld.shared.b32 %0, [%1];" : "=r"(tmem) : "r"(ctrl));

    const float* Sp = S + (size_t)z*NN*NN + (size_t)m0*NN;
    const __nv_bfloat16* Vh = g_vth + (size_t)z*WCH*NN;
    const __nv_bfloat16* Vl = g_vtl + (size_t)z*WCH*NN;

    uint64_t dAh = make_desc(base + off_Ah);
    uint64_t dAl = make_desc(base + off_Al);
    uint64_t dBh = make_desc(base + off_Bh);
    uint64_t dBl = make_desc(base + off_Bl);

    int rb = t >> 4, kq = t & 15;

    for (int kc = 0; kc < 32; kc++) {
        if (kc > 0) MBARRIER_WAIT_PARITY(mbar, (kc-1) & 1);
#pragma unroll
        for (int i = 0; i < 8; i++) {
            int r = rb + i*16;
            float mxr = sst[r*2], invr = sst[r*2+1];
            float4 v = *(const float4*)(Sp + (size_t)r*NN + kc*64 + kq*4);
            v.x = __expf(v.x - mxr) * invr;
            v.y = __expf(v.y - mxr) * invr;
            v.z = __expf(v.z - mxr) * invr;
            v.w = __expf(v.w - mxr) * invr;
            __nv_bfloat16 h0 = __float2bfloat16(v.x);
            __nv_bfloat16 h1 = __float2bfloat16(v.y);
            __nv_bfloat16 h2 = __float2bfloat16(v.z);
            __nv_bfloat16 h3 = __float2bfloat16(v.w);
            uint32_t so = swz((uint32_t)(r*128 + kq*8));
            *(uint2*)(sb + off_Ah + so) = make_uint2(bpackh(h0,h1), bpackh(h2,h3));
            *(uint2*)(sb + off_Al + so) = make_uint2(
                bpackh(__float2bfloat16(v.x - __bfloat162float(h0)),
                       __float2bfloat16(v.y - __bfloat162float(h1))),
                bpackh(__float2bfloat16(v.z - __bfloat162float(h2)),
                       __float2bfloat16(v.w - __bfloat162float(h3))));
        }
#pragma unroll
        for (int i = 0; i < 4; i++) {
            int r = rb + i*16;
            uint32_t so = swz((uint32_t)(r*128 + kq*8));
            *(uint2*)(sb + off_Bh + so) = *(const uint2*)(Vh + (size_t)r*NN + kc*64 + kq*4);
            *(uint2*)(sb + off_Bl + so) = *(const uint2*)(Vl + (size_t)r*NN + kc*64 + kq*4);
        }
        __syncthreads();

        if (t < 32) {
            if (elect_one_pred()) {
                FENCE_ASYNC_SHARED();
#pragma unroll
                for (int ks = 0; ks < 4; ks++) {
                    uint64_t o = ks*2;
                    mma_f16_ss(tmem, dAh+o, dBh+o, IDESC_N64, (kc > 0 || ks > 0) ? 1u : 0u);
                    mma_f16_ss(tmem, dAh+o, dBl+o, IDESC_N64, 1u);
                    mma_f16_ss(tmem, dAl+o, dBh+o, IDESC_N64, 1u);
                }
                TCGEN05_COMMIT(mbar);
            }
        }
    }
    MBARRIER_WAIT_PARITY(mbar, 1);
    TCGEN05_FENCE_AFTER();

    int w = t >> 5, lane = t & 31;
    int sub = w & 3, half = w >> 2;
    size_t rbase = (size_t)(b*NN + m0 + sub*32 + lane)*FUSC + h*64 + half*32;
    {
        uint32_t r[32];
        TCGEN05_LD_X32(r, tmem + half*32);
        TCGEN05_WAIT_LD();
        TCGEN05_FENCE_BEFORE();
#pragma unroll
        for (int j = 0; j < 8; j++) {
            float v0 = __uint_as_float(r[j*4+0]);
            float v1 = __uint_as_float(r[j*4+1]);
            float v2 = __uint_as_float(r[j*4+2]);
            float v3 = __uint_as_float(r[j*4+3]);
            __nv_bfloat16 h0 = __float2bfloat16(v0);
            __nv_bfloat16 h1 = __float2bfloat16(v1);
            __nv_bfloat16 h2 = __float2bfloat16(v2);
            __nv_bfloat16 h3 = __float2bfloat16(v3);
            *(uint2*)(g_Oh + rbase + j*4) = make_uint2(bpackh(h0,h1), bpackh(h2,h3));
            *(uint2*)(g_Ol + rbase + j*4) = make_uint2(
                bpackh(__float2bfloat16(v0 - __bfloat162float(h0)),
                       __float2bfloat16(v1 - __bfloat162float(h1))),
                bpackh(__float2bfloat16(v2 - __bfloat162float(h2)),
                       __float2bfloat16(v3 - __bfloat162float(h3))));
        }
    }
    __syncthreads();
    if (t < 32) TCGEN05_DEALLOC(tmem, 64);
#else
    int t = threadIdx.x;
    int z = blockIdx.y;
    int b = z / HEADS, h = z - b*HEADS;
    int m0 = blockIdx.x * 128;
    if (t >= 128) return;
    int m = m0 + t;
    const float* Sp = S + (size_t)z*NN*NN + (size_t)m*NN;
    float mxr = stat[(size_t)(z*NN + m)*2], invr = stat[(size_t)(z*NN + m)*2+1];
    for (int c = 0; c < 64; c++) {
        const float* vp = g_v + (size_t)(b*NN)*CO + h*32 + c;
        float acc = 0.0f;
        for (int k = 0; k < NN; k++)
            acc = fmaf(__expf(Sp[k]-mxr)*invr, vp[(size_t)k*CO], acc);
        size_t o = (size_t)(b*NN + m)*FUSC + h*64 + c;
        __nv_bfloat16 hb = __float2bfloat16(acc);
        g_Oh[o] = hb;
        g_Ol[o] = __float2bfloat16(acc - __bfloat162float(hb));
    }
#endif
}

// =====================================================================
// LayerNorm -> bf16 split
// =====================================================================
__global__ void layernorm_kernel(const float* __restrict__ X,
                                 const float* __restrict__ g, const float* __restrict__ b)
{
    int m = blockIdx.x, c = threadIdx.x;
    __shared__ float red[256];
    float v = X[(size_t)m*CO + c];
    red[c] = v; __syncthreads();
    for (int s = 128; s; s >>= 1) { if (c < s) red[c] += red[c+s]; __syncthreads(); }
    float mean = red[0] * (1.0f/CO); __syncthreads();
    float d = v - mean;
    red[c] = d*d; __syncthreads();
    for (int s = 128; s; s >>= 1) { if (c < s) red[c] += red[c+s]; __syncthreads(); }
    float var = red[0] * (1.0f/CO);
    float y = d * rsqrtf(var + EPSB) * g[c] + b[c];
    __nv_bfloat16 hb = __float2bfloat16(y);
    size_t i = (size_t)m*CO + c;
    g_yh[i] = hb;
    g_yl[i] = __float2bfloat16(y - __bfloat162float(hb));
}

// =====================================================================
// final output (transposed)
// =====================================================================
__global__ void final_out(const float* __restrict__ bias, float* __restrict__ out)
{
    __shared__ float tile[32][33];
    int b  = blockIdx.z;
    int n0 = blockIdx.x * 32;
    int c0 = blockIdx.y * 32;
    int tx = threadIdx.x, ty = threadIdx.y;
#pragma unroll
    for (int i = 0; i < 32; i += 8) {
        int n = n0 + ty + i, c = c0 + tx;
        size_t src = ((size_t)b*NN + n)*CO + c;
        tile[ty+i][tx] = g_f2[src] + g_fp[src] + bias[c];
    }
    __syncthreads();
#pragma unroll
    for (int i = 0; i < 32; i += 8) {
        int c = c0 + ty + i, n = n0 + tx;
        out[((size_t)b*CO + c)*NN + n] = tile[tx][ty+i];
    }
}

// =====================================================================
// host
// =====================================================================
extern "C" void kernel_launch(void* const* d_in, const int* in_sizes, int n_in,
                              void* d_out, int out_size)
{
    const float* xyz    = (const float*)d_in[0];
    const float* f      = (const float*)d_in[1];
    const float* W_geo  = (const float*)d_in[2];
    const float* gg     = (const float*)d_in[3];
    const float* bg     = (const float*)d_in[4];
    const float* W_feat = (const float*)d_in[5];
    const float* gf     = (const float*)d_in[6];
    const float* bf     = (const float*)d_in[7];
    const float* g_bn   = (const float*)d_in[8];
    const float* b_bn   = (const float*)d_in[9];
    const float* W_q    = (const float*)d_in[10];
    const float* gq     = (const float*)d_in[11];
    const float* bq     = (const float*)d_in[12];
    const float* W_k    = (const float*)d_in[13];
    const float* gk     = (const float*)d_in[14];
    const float* bk     = (const float*)d_in[15];
    const float* W_v    = (const float*)d_in[16];
    const float* gv     = (const float*)d_in[17];
    const float* bv     = (const float*)d_in[18];
    const float* W_fus  = (const float*)d_in[19];
    /* d_in[20] bias_fus: cancels inside BN */
    const float* gfu    = (const float*)d_in[21];
    const float* bfu    = (const float*)d_in[22];
    const float* g_ln   = (const float*)d_in[23];
    const float* b_ln   = (const float*)d_in[24];
    const float* W_mlp  = (const float*)d_in[25];
    const float* b_mlp  = (const float*)d_in[26];
    float* out = (float*)d_out;

    float *p_act, *p_featv, *p_S, *p_stat, *p_fp, *p_f2, *p_msc;
    __nv_bfloat16 *p_ginh, *p_ginl, *p_xh, *p_xl, *p_yh, *p_yl, *p_Oh, *p_Ol;
    __nv_bfloat16 *p_wfh, *p_wfl, *p_wfush, *p_wfusl, *p_wmh, *p_wml;
    cudaGetSymbolAddress((void**)&p_act,   g_act);
    cudaGetSymbolAddress((void**)&p_featv, g_featv);
    cudaGetSymbolAddress((void**)&p_S,     g_S);
    cudaGetSymbolAddress((void**)&p_stat,  g_rowstat);
    cudaGetSymbolAddress((void**)&p_fp,    g_fp);
    cudaGetSymbolAddress((void**)&p_f2,    g_f2);
    cudaGetSymbolAddress((void**)&p_msc,   g_msc);
    cudaGetSymbolAddress((void**)&p_ginh,  g_ginh);
    cudaGetSymbolAddress((void**)&p_ginl,  g_ginl);
    cudaGetSymbolAddress((void**)&p_xh,    g_xh);
    cudaGetSymbolAddress((void**)&p_xl,    g_xl);
    cudaGetSymbolAddress((void**)&p_yh,    g_yh);
    cudaGetSymbolAddress((void**)&p_yl,    g_yl);
    cudaGetSymbolAddress((void**)&p_Oh,    g_Oh);
    cudaGetSymbolAddress((void**)&p_Ol,    g_Ol);
    cudaGetSymbolAddress((void**)&p_wfh,   g_wfh);
    cudaGetSymbolAddress((void**)&p_wfl,   g_wfl);
    cudaGetSymbolAddress((void**)&p_wfush, g_wfush);
    cudaGetSymbolAddress((void**)&p_wfusl, g_wfusl);
    cudaGetSymbolAddress((void**)&p_wmh,   g_wmh);
    cudaGetSymbolAddress((void**)&p_wml,   g_wml);

    cudaFuncSetAttribute(attn_qk,  cudaFuncAttributeMaxDynamicSharedMemorySize, QK_SMEM);
    cudaFuncSetAttribute(attn_av,  cudaFuncAttributeMaxDynamicSharedMemorySize, AV_SMEM);
    cudaFuncSetAttribute(tgemm,    cudaFuncAttributeMaxDynamicSharedMemorySize, TG_SMEM);
    cudaFuncSetAttribute(qkv_gemm, cudaFuncAttributeMaxDynamicSharedMemorySize, TG_SMEM);

    // ---- 0. weight splits (one launch)
    split_weights<<<1536, 256>>>(W_feat, W_q, W_k, W_v, W_fus, W_mlp);

    // ---- 1. KNN + transpose + gathers
    knn_kernel<<<MTOT, 256>>>(xyz);
    transpose_f<<<dim3(NN/32, CIN/32, BB), dim3(32,8)>>>(f);
    geo_pre<<<MTOT, 128>>>(xyz, W_geo);
    gather_feat<<<RTOT*32/256, 256>>>();

    // ---- 2. feat GEMM
    tgemm<<<dim3(1, RTOT/128), 256, TG_SMEM>>>(p_ginh, p_ginl, p_wfh, p_wfl,
                                               p_act + 128, 128, 128, CO, 2);

    // ---- 3. branch BN + maxpool
    bn_stats_partial<<<256, 256>>>(p_act, RTOT);
    bn_stats_final<<<1, 256>>>(256, RTOT, p_msc + 0*512);
    branch_apply<<<MTOT, 256>>>(p_msc + 0*512, gg, bg, gf, bf);

    // ---- 4. BatchNorm1d -> x split
    bn_stats_partial<<<32, 256>>>(p_featv, MTOT);
    bn_stats_final<<<1, 256>>>(32, MTOT, p_msc + 1*512);
    bn_apply_split<<<MTOT, 256>>>(p_featv, p_msc + 1*512, g_bn, b_bn, 0, p_xh, p_xl);

    // ---- 5. q/k/v merged GEMM + stats + apply
    qkv_gemm<<<dim3(2, MTOT/128, 3), 256, TG_SMEM>>>();
    bn_stats_qkv<<<dim3(64, 3), 256>>>();
    bn_final_qkv<<<3, 256>>>(p_msc);
    bn_apply_qkv<<<dim3(MTOT*CO/256, 3), 256>>>(p_msc, gq, bq, gk, bk, gv, bv);
    vt_convert<<<dim3(NN/32, 2, BB*HEADS), dim3(32,8)>>>();

    // ---- 6. attention with fused softmax stats
    attn_qk<<<dim3(16, 16, BB*HEADS), 256, QK_SMEM>>>(p_S);
    softmax_combine<<<BB*HEADS*NN/256, 256>>>();
    attn_av<<<dim3(16, BB*HEADS), 256, AV_SMEM>>>(p_S, p_stat);

    // ---- 7. fus + residual
    tgemm<<<dim3(2, MTOT/128), 256, TG_SMEM>>>(p_Oh, p_Ol, p_wfush, p_wfusl,
                                               p_fp, FUSC, FUSC, CO, 7);
    bn_stats_partial<<<32, 256>>>(p_fp, MTOT);
    bn_stats_final<<<1, 256>>>(32, MTOT, p_msc + 5*512);
    bn_apply<<<MTOT, 256>>>(p_fp, p_f2, p_msc + 5*512, gfu, bfu, p_featv, 1);

    // ---- 8. layernorm + mlp + out
    layernorm_kernel<<<MTOT, 256>>>(p_f2, g_ln, b_ln);
    tgemm<<<dim3(2, MTOT/128), 256, TG_SMEM>>>(p_yh, p_yl, p_wmh, p_wml, p_fp, CO, CO, CO, 4);
    final_out<<<dim3(NN/32, CO/32, BB), dim3(32,8)>>>(b_mlp, out);

    (void)in_sizes; (void)n_in; (void)out_size;
}

// round 9
// speedup vs baseline: 2.5405x; 1.0598x over previous
#include <cuda_runtime.h>
#include <cuda_bf16.h>
#include <cfloat>
#include <math.h>
#include <cstdint>

#if defined(__CUDA_ARCH__) && defined(__CUDA_ARCH_FEAT_SM103_ALL)
#define HAS_TC 1
#else
#define HAS_TC 0
#endif

// ---------------- problem constants ----------------
#define BB    4
#define NN    2048
#define KNB   21
#define CIN   64
#define CO    256
#define HEADS 7
#define WCH   64
#define FUSC  (HEADS*WCH)          /* 448 */
#define MTOT  (BB*NN)              /* 8192 */
#define RTOT  (MTOT*KNB)           /* 172032 */
#define EPSB  1e-5f

// ---------------- scratch ----------------
__device__ int    g_idx[RTOT];
__device__ float  g_ft[MTOT*CIN];
__device__ float  g_act[(size_t)RTOT*CO];
__device__ float  g_featv[MTOT*CO];
__device__ float  g_q[MTOT*CO];
__device__ float  g_k[MTOT*CO];
__device__ float  g_v[MTOT*CO];
__device__ float  g_rowstat[BB*HEADS*NN*2];
__device__ float  g_fp[MTOT*CO];
__device__ float  g_f2[MTOT*CO];
__device__ float  g_partf[256*2*CO];
__device__ float  g_msc[6*2*CO];
// bf16 hi/lo splits
__device__ __nv_bfloat16 g_ginh[(size_t)RTOT*128], g_ginl[(size_t)RTOT*128];
__device__ __nv_bfloat16 g_xh[MTOT*CO],  g_xl[MTOT*CO];
__device__ __nv_bfloat16 g_qh[MTOT*CO],  g_ql[MTOT*CO];
__device__ __nv_bfloat16 g_kh[MTOT*CO],  g_kl[MTOT*CO];
__device__ __nv_bfloat16 g_yh[MTOT*CO],  g_yl[MTOT*CO];
__device__ __nv_bfloat16 g_Oh[MTOT*FUSC], g_Ol[MTOT*FUSC];
__device__ __nv_bfloat16 g_vth[(size_t)BB*HEADS*WCH*NN], g_vtl[(size_t)BB*HEADS*WCH*NN];
__device__ __nv_bfloat16 g_wfh[128*128],  g_wfl[128*128];
__device__ __nv_bfloat16 g_wqh[CO*CO],    g_wql[CO*CO];
__device__ __nv_bfloat16 g_wkh[CO*CO],    g_wkl[CO*CO];
__device__ __nv_bfloat16 g_wvh[CO*CO],    g_wvl[CO*CO];
__device__ __nv_bfloat16 g_wfush[CO*FUSC],g_wfusl[CO*FUSC];
__device__ __nv_bfloat16 g_wmh[CO*CO],    g_wml[CO*CO];

// ---------------- helpers ----------------
__device__ __forceinline__ uint32_t smem_u32(const void* p) {
    uint32_t a;
    asm("{ .reg .u64 t; cvta.to.shared.u64 t, %1; cvt.u32.u64 %0, t; }" : "=r"(a) : "l"(p));
    return a;
}
__device__ __forceinline__ uint32_t swz(uint32_t o) { return o ^ ((o >> 3) & 0x70); }
__device__ __forceinline__ uint32_t bpackh(__nv_bfloat16 a, __nv_bfloat16 b) {
    __nv_bfloat162 t = __halves2bfloat162(a, b);
    return *reinterpret_cast<uint32_t*>(&t);
}

#if HAS_TC
__device__ __forceinline__ uint32_t elect_one_pred() {
    uint32_t pred;
    asm volatile("{\n\t.reg .pred p;\n\telect.sync _|p, 0xFFFFFFFF;\n\tselp.b32 %0, 1, 0, p;\n\t}" : "=r"(pred));
    return pred;
}

#define MBARRIER_INIT(addr, cnt) \
    asm volatile("mbarrier.init.shared.b64 [%0], %1;" :: "r"((uint32_t)(addr)), "r"((uint32_t)(cnt)) : "memory")

#define MBARRIER_WAIT_PARITY(mbar_smem_addr, phase_parity) do { \
    uint32_t _mbar = (uint32_t)(mbar_smem_addr); \
    uint32_t _parity = (uint32_t)(phase_parity); \
    uint32_t _done; \
    asm volatile("{\n\t.reg .pred p;\n\t" \
        "mbarrier.try_wait.parity.acquire.cta.shared::cta.b64 p, [%1], %2;\n\t" \
        "selp.b32 %0, 1, 0, p;\n\t}" : "=r"(_done) : "r"(_mbar), "r"(_parity) : "memory"); \
    if (!_done) { \
        asm volatile("{\n\t.reg .pred P1;\n\t" \
            "WAIT_LOOP_%=:\n\t" \
            "mbarrier.try_wait.parity.acquire.cta.shared::cta.b64 P1, [%0], %1, 0x989680;\n\t" \
            "@P1 bra.uni WAIT_DONE_%=;\n\t" \
            "bra.uni WAIT_LOOP_%=;\n\t" \
            "WAIT_DONE_%=:\n\t}" :: "r"(_mbar), "r"(_parity) : "memory"); \
    } \
} while(0)

#define TCGEN05_ALLOC(sm, n) \
    asm volatile("tcgen05.alloc.cta_group::1.sync.aligned.shared::cta.b32 [%0], %1;" \
                 :: "r"((uint32_t)(sm)), "r"((uint32_t)(n)) : "memory")
#define TCGEN05_RELINQ() \
    asm volatile("tcgen05.relinquish_alloc_permit.cta_group::1.sync.aligned;")
#define TCGEN05_DEALLOC(t, n) \
    asm volatile("tcgen05.dealloc.cta_group::1.sync.aligned.b32 %0, %1;" :: "r"(t), "r"(n))
#define TCGEN05_COMMIT(mbar) \
    asm volatile("tcgen05.commit.cta_group::1.mbarrier::arrive::one.shared::cluster.b64 [%0];" \
                 :: "r"((uint32_t)(mbar)) : "memory")
#define TCGEN05_FENCE_AFTER()  asm volatile("tcgen05.fence::after_thread_sync;" ::: "memory")
#define TCGEN05_FENCE_BEFORE() asm volatile("tcgen05.fence::before_thread_sync;" ::: "memory")
#define TCGEN05_WAIT_LD()      asm volatile("tcgen05.wait::ld.sync.aligned;" ::: "memory")
#define FENCE_ASYNC_SHARED()   asm volatile("fence.proxy.async.shared::cta;" ::: "memory")

#define TCGEN05_LD_X32(r, addr) \
    asm volatile("tcgen05.ld.sync.aligned.32x32b.x32.b32 " \
        "{%0, %1, %2, %3, %4, %5, %6, %7, %8, %9, %10, %11, %12, %13, %14, %15, " \
        " %16, %17, %18, %19, %20, %21, %22, %23, %24, %25, %26, %27, %28, %29, %30, %31}, [%32];" \
        : "=r"((r)[0]),  "=r"((r)[1]),  "=r"((r)[2]),  "=r"((r)[3]), \
          "=r"((r)[4]),  "=r"((r)[5]),  "=r"((r)[6]),  "=r"((r)[7]), \
          "=r"((r)[8]),  "=r"((r)[9]),  "=r"((r)[10]), "=r"((r)[11]), \
          "=r"((r)[12]), "=r"((r)[13]), "=r"((r)[14]), "=r"((r)[15]), \
          "=r"((r)[16]), "=r"((r)[17]), "=r"((r)[18]), "=r"((r)[19]), \
          "=r"((r)[20]), "=r"((r)[21]), "=r"((r)[22]), "=r"((r)[23]), \
          "=r"((r)[24]), "=r"((r)[25]), "=r"((r)[26]), "=r"((r)[27]), \
          "=r"((r)[28]), "=r"((r)[29]), "=r"((r)[30]), "=r"((r)[31]) \
        : "r"(addr))

static __device__ __forceinline__ uint64_t make_desc(uint32_t addr) {
    const uint64_t base =
        (uint64_t(2) << 61) | (uint64_t(1) << 46) | (uint64_t(64) << 32) | (uint64_t(1) << 16);
    return base | ((uint64_t)(addr >> 4) & 0x3FFF);
}

__device__ __forceinline__ void mma_f16_ss(uint32_t d, uint64_t a, uint64_t b,
                                           uint32_t idesc, uint32_t en) {
    asm volatile(
        "{\n\t.reg .pred p;\n\tsetp.ne.u32 p, %5, 0;\n\t"
        "tcgen05.mma.cta_group::1.kind::f16 [%0], %1, %2, %3, {%4, %4, %4, %4}, p;\n\t}"
        :: "r"(d), "l"(a), "l"(b), "r"(idesc), "r"(0u), "r"(en) : "memory");
}

#define IDESC_N128 ((1u<<4)|(1u<<7)|(1u<<10)|((128u/8)<<17)|((128u/16)<<24))
#define IDESC_N64  ((1u<<4)|(1u<<7)|(1u<<10)|(( 64u/8)<<17)|((128u/16)<<24))

// ---- shared tensor-GEMM core: 128x128 out, K chunks of 64, 256 threads ----
__device__ __forceinline__ void tgemm_core(char* sb, uint32_t base,
    const __nv_bfloat16* __restrict__ Ah, const __nv_bfloat16* __restrict__ Al,
    const __nv_bfloat16* __restrict__ Bh, const __nv_bfloat16* __restrict__ Bl,
    float* __restrict__ C, int lda, int ldb, int ldc, int nkc, int m0, int n0)
{
    uint32_t ctrl = base + 65536;
    uint32_t mbar = ctrl + 8;
    int t = threadIdx.x;

    if (t == 0) MBARRIER_INIT(mbar, 1);
    if (t < 32) { TCGEN05_ALLOC(ctrl, 128); TCGEN05_RELINQ(); }
    __syncthreads();
    uint32_t tmem;
    asm volatile("ld.shared.b32 %0, [%1];" : "=r"(tmem) : "r"(ctrl));

    Ah += (size_t)m0 * lda; Al += (size_t)m0 * lda;
    Bh += (size_t)n0 * ldb; Bl += (size_t)n0 * ldb;

    uint64_t dAh = make_desc(base + 0*16384);
    uint64_t dAl = make_desc(base + 1*16384);
    uint64_t dBh = make_desc(base + 2*16384);
    uint64_t dBl = make_desc(base + 3*16384);

    int rb = t >> 4, kq = t & 15;

    for (int kc = 0; kc < nkc; kc++) {
        if (kc > 0) MBARRIER_WAIT_PARITY(mbar, (kc-1) & 1);
        int k0 = kc*64;
#pragma unroll
        for (int i = 0; i < 8; i++) {
            int r = rb + i*16;
            uint32_t so = swz((uint32_t)(r*128 + kq*8));
            *(uint2*)(sb + 0*16384 + so) = *(const uint2*)(Ah + (size_t)r*lda + k0 + kq*4);
            *(uint2*)(sb + 1*16384 + so) = *(const uint2*)(Al + (size_t)r*lda + k0 + kq*4);
            *(uint2*)(sb + 2*16384 + so) = *(const uint2*)(Bh + (size_t)r*ldb + k0 + kq*4);
            *(uint2*)(sb + 3*16384 + so) = *(const uint2*)(Bl + (size_t)r*ldb + k0 + kq*4);
        }
        __syncthreads();
        if (t < 32) {
            if (elect_one_pred()) {
                FENCE_ASYNC_SHARED();
#pragma unroll
                for (int ks = 0; ks < 4; ks++) {
                    uint64_t o = ks*2;
                    mma_f16_ss(tmem, dAh+o, dBh+o, IDESC_N128, (kc > 0 || ks > 0) ? 1u : 0u);
                    mma_f16_ss(tmem, dAh+o, dBl+o, IDESC_N128, 1u);
                    mma_f16_ss(tmem, dAl+o, dBh+o, IDESC_N128, 1u);
                }
                TCGEN05_COMMIT(mbar);
            }
        }
    }
    MBARRIER_WAIT_PARITY(mbar, (nkc-1) & 1);
    TCGEN05_FENCE_AFTER();

    int w = t >> 5, lane = t & 31;
    int sub = w & 3, half = w >> 2;
    float* Crow = C + (size_t)(m0 + sub*32 + lane)*ldc + n0;
#pragma unroll
    for (int gi = 0; gi < 2; gi++) {
        int g = half*2 + gi;
        uint32_t r[32];
        TCGEN05_LD_X32(r, tmem + g*32);
        TCGEN05_WAIT_LD();
        TCGEN05_FENCE_BEFORE();
#pragma unroll
        for (int j = 0; j < 8; j++)
            *(float4*)(Crow + g*32 + j*4) = make_float4(
                __uint_as_float(r[j*4+0]), __uint_as_float(r[j*4+1]),
                __uint_as_float(r[j*4+2]), __uint_as_float(r[j*4+3]));
    }
    __syncthreads();
    if (t < 32) TCGEN05_DEALLOC(tmem, 128);
}
#else
// SIMT fallback core (generic compute_103 pass; never runs on GB300)
__device__ __forceinline__ void tgemm_core_simt(
    const __nv_bfloat16* Ah, const __nv_bfloat16* Al,
    const __nv_bfloat16* Bh, const __nv_bfloat16* Bl,
    float* C, int lda, int ldb, int ldc, int nkc, int m0, int n0)
{
    int t = threadIdx.x;
    int m = m0 + (t >> 1);
    int nb = (t & 1) * 64;
    for (int n = nb; n < nb + 64; n++) {
        float acc = 0.0f;
        for (int k = 0; k < nkc*64; k++) {
            float a = __bfloat162float(Ah[(size_t)m*lda+k]) + __bfloat162float(Al[(size_t)m*lda+k]);
            float b = __bfloat162float(Bh[(size_t)(n0+n)*ldb+k]) + __bfloat162float(Bl[(size_t)(n0+n)*ldb+k]);
            acc = fmaf(a, b, acc);
        }
        C[(size_t)m*ldc + n0 + n] = acc;
    }
}
#endif // HAS_TC

#define TG_SMEM (1024 + 4*16384 + 64)

// =====================================================================
// KNN
// =====================================================================
__global__ void knn_kernel(const float* __restrict__ xyz)
{
    __shared__ float d2s[NN];
    __shared__ float rv[256];
    __shared__ int   ri[256];
    int m = blockIdx.x;
    int b = m >> 11;
    int t = threadIdx.x;
    const float* base = xyz + (size_t)(b << 11) * 3;

    float qx = xyz[m*3+0], qy = xyz[m*3+1], qz = xyz[m*3+2];
    float sqq = qx*qx + qy*qy + qz*qz;

    for (int j = t; j < NN; j += 256) {
        float px = base[j*3+0], py = base[j*3+1], pz = base[j*3+2];
        float sqp = px*px + py*py + pz*pz;
        float dot = qx*px + qy*py + qz*pz;
        d2s[j] = sqq + sqp - 2.0f*dot;
    }
    __syncthreads();

    for (int it = 0; it < KNB; it++) {
        float bv = FLT_MAX; int bi = 0x3fffffff;
        for (int j = t; j < NN; j += 256) {
            float v = d2s[j];
            if (v < bv) { bv = v; bi = j; }
        }
        rv[t] = bv; ri[t] = bi;
        __syncthreads();
        for (int s = 128; s; s >>= 1) {
            if (t < s) {
                float ov = rv[t+s]; int oi = ri[t+s];
                if (ov < rv[t] || (ov == rv[t] && oi < ri[t])) { rv[t] = ov; ri[t] = oi; }
            }
            __syncthreads();
        }
        if (t == 0) { g_idx[(size_t)m*KNB + it] = ri[0]; d2s[ri[0]] = FLT_MAX; }
        __syncthreads();
    }
}

// =====================================================================
// transpose f
// =====================================================================
__global__ void transpose_f(const float* __restrict__ f)
{
    __shared__ float tile[32][33];
    int b  = blockIdx.z;
    int n0 = blockIdx.x * 32;
    int c0 = blockIdx.y * 32;
    int tx = threadIdx.x, ty = threadIdx.y;
#pragma unroll
    for (int i = 0; i < 32; i += 8)
        tile[ty+i][tx] = f[((size_t)b*CIN + c0 + ty + i)*NN + n0 + tx];
    __syncthreads();
#pragma unroll
    for (int i = 0; i < 32; i += 8)
        g_ft[((size_t)b*NN + n0 + ty + i)*CIN + c0 + tx] = tile[tx][ty+i];
}

// =====================================================================
// geo branch pre-activation
// =====================================================================
__global__ void geo_pre(const float* __restrict__ xyz, const float* __restrict__ Wg)
{
    int m = blockIdx.x;
    int c = threadIdx.x;
    int b = m >> 11;
    float w0 = Wg[c*6+0], w1 = Wg[c*6+1], w2 = Wg[c*6+2];
    float w3 = Wg[c*6+3], w4 = Wg[c*6+4], w5 = Wg[c*6+5];
    float cx = xyz[m*3+0], cy = xyz[m*3+1], cz = xyz[m*3+2];
    float base = w0*cx + w1*cy + w2*cz;
    for (int k = 0; k < KNB; k++) {
        int nb = g_idx[(size_t)m*KNB + k];
        const float* pp = xyz + (size_t)((b << 11) + nb)*3;
        float dx = pp[0]-cx, dy = pp[1]-cy, dz = pp[2]-cz;
        g_act[((size_t)m*KNB + k)*CO + c] = base + w3*dx + w4*dy + w5*dz;
    }
}

// =====================================================================
// gather feat_in -> bf16 split (vectorized, 32-bit index math)
// =====================================================================
__global__ void gather_feat()
{
    uint32_t tid = blockIdx.x*256u + threadIdx.x;  // RTOT*32 threads
    uint32_t r = tid >> 5;
    uint32_t c4 = (tid & 31u) * 4u;
    uint32_t m = r / KNB;
    uint32_t b = m >> 11;
    float4 v;
    if (c4 < 64u) {
        uint32_t nb = (uint32_t)g_idx[r];
        v = *(const float4*)(g_ft + (size_t)((b << 11) + nb)*CIN + c4);
    } else {
        v = *(const float4*)(g_ft + (size_t)m*CIN + (c4 - 64u));
    }
    __nv_bfloat16 h0 = __float2bfloat16(v.x);
    __nv_bfloat16 h1 = __float2bfloat16(v.y);
    __nv_bfloat16 h2 = __float2bfloat16(v.z);
    __nv_bfloat16 h3 = __float2bfloat16(v.w);
    size_t o = (size_t)r*128 + c4;
    *(uint2*)(g_ginh + o) = make_uint2(bpackh(h0,h1), bpackh(h2,h3));
    *(uint2*)(g_ginl + o) = make_uint2(
        bpackh(__float2bfloat16(v.x - __bfloat162float(h0)),
               __float2bfloat16(v.y - __bfloat162float(h1))),
        bpackh(__float2bfloat16(v.z - __bfloat162float(h2)),
               __float2bfloat16(v.w - __bfloat162float(h3))));
}

// =====================================================================
// tensor GEMM wrappers
// =====================================================================
__global__ void __launch_bounds__(256, 1)
tgemm(const __nv_bfloat16* __restrict__ Ah, const __nv_bfloat16* __restrict__ Al,
      const __nv_bfloat16* __restrict__ Bh, const __nv_bfloat16* __restrict__ Bl,
      float* __restrict__ C, int lda, int ldb, int ldc, int nkc)
{
#if HAS_TC
    extern __shared__ char sm[];
    uint32_t raw = smem_u32(sm);
    uint32_t base = (raw + 1023) & ~1023u;
    tgemm_core(sm + (base - raw), base, Ah, Al, Bh, Bl, C, lda, ldb, ldc, nkc,
               blockIdx.y*128, blockIdx.x*128);
#else
    tgemm_core_simt(Ah, Al, Bh, Bl, C, lda, ldb, ldc, nkc, blockIdx.y*128, blockIdx.x*128);
#endif
}

__global__ void __launch_bounds__(256, 1)
qkv_gemm()
{
    int z = blockIdx.z;
    const __nv_bfloat16* Bh = (z==0) ? g_wqh : (z==1) ? g_wkh : g_wvh;
    const __nv_bfloat16* Bl = (z==0) ? g_wql : (z==1) ? g_wkl : g_wvl;
    float* C = (z==0) ? g_q : (z==1) ? g_k : g_v;
#if HAS_TC
    extern __shared__ char sm[];
    uint32_t raw = smem_u32(sm);
    uint32_t base = (raw + 1023) & ~1023u;
    tgemm_core(sm + (base - raw), base, g_xh, g_xl, Bh, Bl, C, CO, CO, CO, 4,
               blockIdx.y*128, blockIdx.x*128);
#else
    tgemm_core_simt(g_xh, g_xl, Bh, Bl, C, CO, CO, CO, 4, blockIdx.y*128, blockIdx.x*128);
#endif
}

// =====================================================================
// BN stats: fp32 partials (4 accumulators, fixed order), double combine
// =====================================================================
__device__ __forceinline__ void bn_partial_region(const float* X, long rows,
                                                  int nblk, int blk, int region)
{
    int c = threadIdx.x;
    long per = (rows + nblk - 1) / nblk;
    long r0 = (long)blk * per;
    long r1 = r0 + per; if (r1 > rows) r1 = rows;
    float a0=0,a1=0,a2=0,a3=0, q0=0,q1=0,q2=0,q3=0;
    long r = r0;
    for (; r + 4 <= r1; r += 4) {
        float v0 = X[(r+0)*CO + c], v1 = X[(r+1)*CO + c];
        float v2 = X[(r+2)*CO + c], v3 = X[(r+3)*CO + c];
        a0 += v0; q0 = fmaf(v0,v0,q0);
        a1 += v1; q1 = fmaf(v1,v1,q1);
        a2 += v2; q2 = fmaf(v2,v2,q2);
        a3 += v3; q3 = fmaf(v3,v3,q3);
    }
    for (; r < r1; r++) { float v = X[r*CO + c]; a0 += v; q0 = fmaf(v,v,q0); }
    g_partf[((size_t)region*2 + 0)*CO + c] = (a0+a1) + (a2+a3);
    g_partf[((size_t)region*2 + 1)*CO + c] = (q0+q1) + (q2+q3);
}

__global__ void bn_stats_partial(const float* __restrict__ X, long rows)
{
    bn_partial_region(X, rows, gridDim.x, blockIdx.x, blockIdx.x);
}

__global__ void bn_stats_final(int nblocks, long rows, float* msc)
{
    int c = threadIdx.x;
    double s = 0.0, s2 = 0.0;
    for (int i = 0; i < nblocks; i++) {
        s  += (double)g_partf[((size_t)i*2 + 0)*CO + c];
        s2 += (double)g_partf[((size_t)i*2 + 1)*CO + c];
    }
    double mean = s / (double)rows;
    double var  = s2 / (double)rows - mean*mean;
    msc[c]      = (float)mean;
    msc[CO + c] = (float)(1.0 / sqrt(var + (double)EPSB));
}

// merged q/k/v stats: grid (64,3); regions y*64+x
__global__ void bn_stats_qkv()
{
    const float* X = (blockIdx.y==0) ? g_q : (blockIdx.y==1) ? g_k : g_v;
    bn_partial_region(X, MTOT, 64, blockIdx.x, blockIdx.y*64 + blockIdx.x);
}
__global__ void bn_final_qkv(float* msc)
{
    int y = blockIdx.x;   // 0..2
    int c = threadIdx.x;
    double s = 0.0, s2 = 0.0;
    for (int i = y*64; i < y*64 + 64; i++) {
        s  += (double)g_partf[((size_t)i*2 + 0)*CO + c];
        s2 += (double)g_partf[((size_t)i*2 + 1)*CO + c];
    }
    double mean = s / (double)MTOT;
    double var  = s2 / (double)MTOT - mean*mean;
    msc[(2+y)*512 + c]      = (float)mean;
    msc[(2+y)*512 + CO + c] = (float)(1.0 / sqrt(var + (double)EPSB));
}

// =====================================================================
// branch BN + relu + maxpool
// =====================================================================
__global__ void branch_apply(const float* msc,
                             const float* __restrict__ g_geo, const float* __restrict__ b_geo,
                             const float* __restrict__ g_fea, const float* __restrict__ b_fea)
{
    int m = blockIdx.x;
    int c = threadIdx.x;
    float mean = msc[c], istd = msc[CO + c];
    float ga = (c < 128) ? g_geo[c] : g_fea[c - 128];
    float be = (c < 128) ? b_geo[c] : b_fea[c - 128];
    float sc = istd * ga;
    float best = -FLT_MAX;
    const float* base = g_act + (size_t)m*KNB*CO + c;
#pragma unroll 3
    for (int k = 0; k < KNB; k++) {
        float zv = base[(size_t)k*CO];
        float y = (zv - mean) * sc + be;
        y = fmaxf(y, 0.0f);
        best = fmaxf(best, y);
    }
    g_featv[(size_t)m*CO + c] = best;
}

// =====================================================================
// BN apply variants
// =====================================================================
__global__ void bn_apply(const float* __restrict__ in, float* __restrict__ out,
                         const float* msc,
                         const float* __restrict__ gamma, const float* __restrict__ beta,
                         const float* __restrict__ res, int do_relu)
{
    size_t i = (size_t)blockIdx.x * blockDim.x + threadIdx.x;
    int c = (int)(i & (CO-1));
    float y = (in[i] - msc[c]) * msc[CO + c] * gamma[c] + beta[c];
    if (do_relu) y = fmaxf(y, 0.0f);
    if (res) y += res[i];
    out[i] = y;
}

__global__ void bn_apply_split(const float* __restrict__ in,
                               const float* msc,
                               const float* __restrict__ gamma, const float* __restrict__ beta,
                               int do_relu,
                               __nv_bfloat16* __restrict__ oh, __nv_bfloat16* __restrict__ ol)
{
    size_t i = (size_t)blockIdx.x * blockDim.x + threadIdx.x;
    int c = (int)(i & (CO-1));
    float y = (in[i] - msc[c]) * msc[CO + c] * gamma[c] + beta[c];
    if (do_relu) y = fmaxf(y, 0.0f);
    __nv_bfloat16 hb = __float2bfloat16(y);
    oh[i] = hb;
    ol[i] = __float2bfloat16(y - __bfloat162float(hb));
}

// merged q/k/v BN apply: grid (MTOT*CO/256, 3)
__global__ void bn_apply_qkv(const float* msc,
                             const float* __restrict__ gq, const float* __restrict__ bq,
                             const float* __restrict__ gk, const float* __restrict__ bk,
                             const float* __restrict__ gv, const float* __restrict__ bv)
{
    int y = blockIdx.y;
    size_t i = (size_t)blockIdx.x * 256 + threadIdx.x;
    int c = (int)(i & (CO-1));
    const float* in = (y==0) ? g_q : (y==1) ? g_k : g_v;
    const float* ga = (y==0) ? gq : (y==1) ? gk : gv;
    const float* be = (y==0) ? bq : (y==1) ? bk : bv;
    const float* ms = msc + (2+y)*512;
    float v = fmaxf((in[i] - ms[c]) * ms[CO + c] * ga[c] + be[c], 0.0f);
    if (y == 2) { g_v[i] = v; return; }
    __nv_bfloat16 hb = __float2bfloat16(v);
    __nv_bfloat16 lb = __float2bfloat16(v - __bfloat162float(hb));
    if (y == 0) { g_qh[i] = hb; g_ql[i] = lb; }
    else        { g_kh[i] = hb; g_kl[i] = lb; }
}

// =====================================================================
// fused weight splits (one launch)
// =====================================================================
__global__ void split_weights(const float* __restrict__ Wf, const float* __restrict__ Wq,
                              const float* __restrict__ Wk, const float* __restrict__ Wv,
                              const float* __restrict__ Wfus, const float* __restrict__ Wm)
{
    int i = blockIdx.x*256 + threadIdx.x;   // 393216 total
    const float* src; __nv_bfloat16 *dh, *dl; int off;
    if      (i < 16384)  { src = Wf;   dh = g_wfh;   dl = g_wfl;   off = i; }
    else if (i < 81920)  { src = Wq;   dh = g_wqh;   dl = g_wql;   off = i - 16384; }
    else if (i < 147456) { src = Wk;   dh = g_wkh;   dl = g_wkl;   off = i - 81920; }
    else if (i < 212992) { src = Wv;   dh = g_wvh;   dl = g_wvl;   off = i - 147456; }
    else if (i < 327680) { src = Wfus; dh = g_wfush; dl = g_wfusl; off = i - 212992; }
    else                 { src = Wm;   dh = g_wmh;   dl = g_wml;   off = i - 327680; }
    float v = src[off];
    __nv_bfloat16 hb = __float2bfloat16(v);
    dh[off] = hb;
    dl[off] = __float2bfloat16(v - __bfloat162float(hb));
}

// =====================================================================
// v -> per-head transposed bf16 split
// =====================================================================
__global__ void vt_convert()
{
    __shared__ float tile[32][33];
    int z  = blockIdx.z;
    int b  = z / HEADS, h = z - b*HEADS;
    int m0 = blockIdx.x * 32;
    int c0 = blockIdx.y * 32;
    int tx = threadIdx.x, ty = threadIdx.y;
#pragma unroll
    for (int i = 0; i < 32; i += 8)
        tile[ty+i][tx] = g_v[((size_t)(b*NN) + m0 + ty + i)*CO + h*32 + c0 + tx];
    __syncthreads();
#pragma unroll
    for (int i = 0; i < 32; i += 8) {
        int c = c0 + ty + i, m = m0 + tx;
        float v = tile[tx][ty+i];
        __nv_bfloat16 hb = __float2bfloat16(v);
        size_t o = (size_t)z*WCH*NN + (size_t)c*NN + m;
        g_vth[o] = hb;
        g_vtl[o] = __float2bfloat16(v - __bfloat162float(hb));
    }
}

// =====================================================================
// FLASH pass 1: per-row softmax stats, S never stored.
// grid (16 m-tiles, 28 z), 256 threads.
// smem: Qh@0 Ql@16K Kh@32K Kl@48K, ctrl@64K, merge@64K+64
// =====================================================================
#define ST_SMEM (1024 + 65536 + 64 + 1088)

__global__ void __launch_bounds__(256, 1)
attn_stats()
{
#if HAS_TC
    extern __shared__ char sm[];
    uint32_t raw = smem_u32(sm);
    uint32_t base = (raw + 1023) & ~1023u;
    char* sb = sm + (base - raw);
    uint32_t ctrl = base + 65536;
    uint32_t mbar = ctrl + 8;
    float* mrg = (float*)(sb + 65536 + 64);   // 128 x {mx,sum}

    int t = threadIdx.x;
    int z = blockIdx.y;
    int b = z / HEADS, h = z - b*HEADS;
    int m0 = blockIdx.x * 128;

    if (t == 0) MBARRIER_INIT(mbar, 1);
    if (t < 32) { TCGEN05_ALLOC(ctrl, 128); TCGEN05_RELINQ(); }
    __syncthreads();
    uint32_t tmem;
    asm volatile("ld.shared.b32 %0, [%1];" : "=r"(tmem) : "r"(ctrl));

    const __nv_bfloat16* pQh = g_qh + ((size_t)(b*NN) + m0)*CO + h*32;
    const __nv_bfloat16* pQl = g_ql + ((size_t)(b*NN) + m0)*CO + h*32;
    const __nv_bfloat16* pKh = g_kh + ((size_t)b*NN)*CO + h*32;
    const __nv_bfloat16* pKl = g_kl + ((size_t)b*NN)*CO + h*32;

    int rb = t >> 4, kq = t & 15;
    // load Q once
#pragma unroll
    for (int i = 0; i < 8; i++) {
        int r = rb + i*16;
        uint32_t so = swz((uint32_t)(r*128 + kq*8));
        *(uint2*)(sb + 0*16384 + so) = *(const uint2*)(pQh + (size_t)r*CO + kq*4);
        *(uint2*)(sb + 1*16384 + so) = *(const uint2*)(pQl + (size_t)r*CO + kq*4);
    }

    uint64_t dQh = make_desc(base + 0*16384);
    uint64_t dQl = make_desc(base + 1*16384);
    uint64_t dKh = make_desc(base + 2*16384);
    uint64_t dKl = make_desc(base + 3*16384);

    int w = t >> 5, lane = t & 31;
    int sub = w & 3, half = w >> 2;
    int rrow = sub*32 + lane;

    float mx = -FLT_MAX, sum = 0.0f;

    for (int nc = 0; nc < 16; nc++) {
        int n0 = nc*128;
#pragma unroll
        for (int i = 0; i < 8; i++) {
            int r = rb + i*16;
            uint32_t so = swz((uint32_t)(r*128 + kq*8));
            *(uint2*)(sb + 2*16384 + so) = *(const uint2*)(pKh + (size_t)(n0+r)*CO + kq*4);
            *(uint2*)(sb + 3*16384 + so) = *(const uint2*)(pKl + (size_t)(n0+r)*CO + kq*4);
        }
        __syncthreads();
        if (t < 32) {
            if (elect_one_pred()) {
                FENCE_ASYNC_SHARED();
#pragma unroll
                for (int ks = 0; ks < 4; ks++) {
                    uint64_t o = ks*2;
                    mma_f16_ss(tmem, dQh+o, dKh+o, IDESC_N128, (ks > 0) ? 1u : 0u);
                    mma_f16_ss(tmem, dQh+o, dKl+o, IDESC_N128, 1u);
                    mma_f16_ss(tmem, dQl+o, dKh+o, IDESC_N128, 1u);
                }
                TCGEN05_COMMIT(mbar);
            }
        }
        MBARRIER_WAIT_PARITY(mbar, nc & 1);
        TCGEN05_FENCE_AFTER();
#pragma unroll
        for (int gi = 0; gi < 2; gi++) {
            int g = half*2 + gi;
            uint32_t r[32];
            TCGEN05_LD_X32(r, tmem + g*32);
            TCGEN05_WAIT_LD();
            float gm = -FLT_MAX;
#pragma unroll
            for (int j = 0; j < 32; j++) gm = fmaxf(gm, __uint_as_float(r[j]));
            float gs = 0.0f;
#pragma unroll
            for (int j = 0; j < 32; j++) gs += __expf(__uint_as_float(r[j]) - gm);
            if (gm <= mx) sum += gs * __expf(gm - mx);
            else { sum = sum * __expf(mx - gm) + gs; mx = gm; }
        }
        __syncthreads();   // all LDTMs done before next MMA overwrites S
    }

    if (half == 0) { mrg[rrow*2] = mx; mrg[rrow*2+1] = sum; }
    __syncthreads();
    if (half == 1) {
        float m2 = mrg[rrow*2], s2 = mrg[rrow*2+1];
        float M = fmaxf(mx, m2);
        float S = s2 * __expf(m2 - M) + sum * __expf(mx - M);
        size_t row = (size_t)z*NN + m0 + rrow;
        g_rowstat[row*2]   = M;
        g_rowstat[row*2+1] = 1.0f / S;
    }
    __syncthreads();
    if (t < 32) TCGEN05_DEALLOC(tmem, 128);
#else
    int t = threadIdx.x;
    int z = blockIdx.y;
    int b = z / HEADS, h = z - b*HEADS;
    int m0 = blockIdx.x * 128;
    if (t >= 128) return;
    int m = m0 + t;
    const float* qp = g_q + ((size_t)(b*NN) + m)*CO + h*32;
    float mx = -FLT_MAX;
    for (int n = 0; n < NN; n++) {
        const float* kp = g_k + ((size_t)(b*NN) + n)*CO + h*32;
        float acc = 0.0f;
        for (int k = 0; k < 64; k++) acc = fmaf(qp[k], kp[k], acc);
        mx = fmaxf(mx, acc);
    }
    float sum = 0.0f;
    for (int n = 0; n < NN; n++) {
        const float* kp = g_k + ((size_t)(b*NN) + n)*CO + h*32;
        float acc = 0.0f;
        for (int k = 0; k < 64; k++) acc = fmaf(qp[k], kp[k], acc);
        sum += __expf(acc - mx);
    }
    size_t row = (size_t)z*NN + m;
    g_rowstat[row*2] = mx; g_rowstat[row*2+1] = 1.0f / sum;
#endif
}

// =====================================================================
// FLASH pass 2: recompute S tile, softmax-apply, P·V accumulate in TMEM.
// grid (16 m-tiles, 28 z), 256 threads.
// smem layout (from aligned base):
//  Qh@0 Ql@16K Kh@32K Kl@48K Vh@64K(2x8K) Vl@80K Ph@96K(2x16K) Pl@128K
//  ctrl@160K mbar_s@+8 mbar_o@+16, sst@160K+64 (1KB)
// TMEM: S cols 0..127, O cols 128..191 (alloc 256)
// =====================================================================
#define FL_SMEM (1024 + 163840 + 64 + 1088)

__global__ void __launch_bounds__(256, 1)
attn_flash()
{
#if HAS_TC
    extern __shared__ char sm[];
    uint32_t raw = smem_u32(sm);
    uint32_t base = (raw + 1023) & ~1023u;
    char* sb = sm + (base - raw);
    const uint32_t off_Qh = 0, off_Ql = 16384, off_Kh = 32768, off_Kl = 49152;
    const uint32_t off_Vh = 65536, off_Vl = 81920, off_Ph = 98304, off_Pl = 131072;
    uint32_t ctrl = base + 163840;
    uint32_t mbar_s = ctrl + 8;
    uint32_t mbar_o = ctrl + 16;
    float* sst = (float*)(sb + 163840 + 64);

    int t = threadIdx.x;
    int z = blockIdx.y;
    int b = z / HEADS, h = z - b*HEADS;
    int m0 = blockIdx.x * 128;

    if (t == 0) { MBARRIER_INIT(mbar_s, 1); MBARRIER_INIT(mbar_o, 1); }
    if (t < 32) { TCGEN05_ALLOC(ctrl, 256); TCGEN05_RELINQ(); }
    sst[t] = g_rowstat[(size_t)(z*NN + m0)*2 + t];
    __syncthreads();
    uint32_t tmem;
    asm volatile("ld.shared.b32 %0, [%1];" : "=r"(tmem) : "r"(ctrl));
    uint32_t tmemO = tmem + 128;

    const __nv_bfloat16* pQh = g_qh + ((size_t)(b*NN) + m0)*CO + h*32;
    const __nv_bfloat16* pQl = g_ql + ((size_t)(b*NN) + m0)*CO + h*32;
    const __nv_bfloat16* pKh = g_kh + ((size_t)b*NN)*CO + h*32;
    const __nv_bfloat16* pKl = g_kl + ((size_t)b*NN)*CO + h*32;
    const __nv_bfloat16* Vh = g_vth + (size_t)z*WCH*NN;
    const __nv_bfloat16* Vl = g_vtl + (size_t)z*WCH*NN;

    int rb = t >> 4, kq = t & 15;
    // load Q once
#pragma unroll
    for (int i = 0; i < 8; i++) {
        int r = rb + i*16;
        uint32_t so = swz((uint32_t)(r*128 + kq*8));
        *(uint2*)(sb + off_Qh + so) = *(const uint2*)(pQh + (size_t)r*CO + kq*4);
        *(uint2*)(sb + off_Ql + so) = *(const uint2*)(pQl + (size_t)r*CO + kq*4);
    }

    uint64_t dQh = make_desc(base + off_Qh);
    uint64_t dQl = make_desc(base + off_Ql);
    uint64_t dKh = make_desc(base + off_Kh);
    uint64_t dKl = make_desc(base + off_Kl);

    int w = t >> 5, lane = t & 31;
    int sub = w & 3, half = w >> 2;
    int rrow = sub*32 + lane;
    float mxr = sst[rrow*2], invr = sst[rrow*2+1];

    for (int nc = 0; nc < 16; nc++) {
        int n0 = nc*128;
        // P/O backpressure: PV MMA of previous chunk must be done before P rewrite
        if (nc > 0) MBARRIER_WAIT_PARITY(mbar_o, (nc-1) & 1);

        // load K chunk [128 x 64] and V chunk [64 x 128] (2 subtiles of 64k)
#pragma unroll
        for (int i = 0; i < 8; i++) {
            int r = rb + i*16;
            uint32_t so = swz((uint32_t)(r*128 + kq*8));
            *(uint2*)(sb + off_Kh + so) = *(const uint2*)(pKh + (size_t)(n0+r)*CO + kq*4);
            *(uint2*)(sb + off_Kl + so) = *(const uint2*)(pKl + (size_t)(n0+r)*CO + kq*4);
        }
#pragma unroll
        for (int i = 0; i < 4; i++) {
            int r = rb + i*16;                       // V row (c) 0..63
            uint32_t so = swz((uint32_t)(r*128 + kq*8));
#pragma unroll
            for (int j = 0; j < 2; j++) {            // k-subtile
                size_t gk = (size_t)r*NN + n0 + j*64 + kq*4;
                *(uint2*)(sb + off_Vh + j*8192 + so) = *(const uint2*)(Vh + gk);
                *(uint2*)(sb + off_Vl + j*8192 + so) = *(const uint2*)(Vl + gk);
            }
        }
        __syncthreads();

        // S = Q K^T  (overwrite S each chunk)
        if (t < 32) {
            if (elect_one_pred()) {
                FENCE_ASYNC_SHARED();
#pragma unroll
                for (int ks = 0; ks < 4; ks++) {
                    uint64_t o = ks*2;
                    mma_f16_ss(tmem, dQh+o, dKh+o, IDESC_N128, (ks > 0) ? 1u : 0u);
                    mma_f16_ss(tmem, dQh+o, dKl+o, IDESC_N128, 1u);
                    mma_f16_ss(tmem, dQl+o, dKh+o, IDESC_N128, 1u);
                }
                TCGEN05_COMMIT(mbar_s);
            }
        }
        MBARRIER_WAIT_PARITY(mbar_s, nc & 1);
        TCGEN05_FENCE_AFTER();

        // read S tile, softmax apply, write P (bf16 split) to smem
#pragma unroll
        for (int gi = 0; gi < 2; gi++) {
            int g = half*2 + gi;
            uint32_t r[32];
            TCGEN05_LD_X32(r, tmem + g*32);
            TCGEN05_WAIT_LD();
#pragma unroll
            for (int j = 0; j < 8; j++) {
                float v0 = __expf(__uint_as_float(r[j*4+0]) - mxr) * invr;
                float v1 = __expf(__uint_as_float(r[j*4+1]) - mxr) * invr;
                float v2 = __expf(__uint_as_float(r[j*4+2]) - mxr) * invr;
                float v3 = __expf(__uint_as_float(r[j*4+3]) - mxr) * invr;
                __nv_bfloat16 h0 = __float2bfloat16(v0);
                __nv_bfloat16 h1 = __float2bfloat16(v1);
                __nv_bfloat16 h2 = __float2bfloat16(v2);
                __nv_bfloat16 h3 = __float2bfloat16(v3);
                uint32_t so = swz((uint32_t)(rrow*128 + (gi*32 + j*4)*2));
                *(uint2*)(sb + off_Ph + half*16384 + so) = make_uint2(bpackh(h0,h1), bpackh(h2,h3));
                *(uint2*)(sb + off_Pl + half*16384 + so) = make_uint2(
                    bpackh(__float2bfloat16(v0 - __bfloat162float(h0)),
                           __float2bfloat16(v1 - __bfloat162float(h1))),
                    bpackh(__float2bfloat16(v2 - __bfloat162float(h2)),
                           __float2bfloat16(v3 - __bfloat162float(h3))));
            }
        }
        __syncthreads();

        // O += P V^T
        if (t < 32) {
            if (elect_one_pred()) {
                FENCE_ASYNC_SHARED();
#pragma unroll
                for (int kch = 0; kch < 2; kch++) {
                    uint64_t dPh = make_desc(base + off_Ph + kch*16384);
                    uint64_t dPl = make_desc(base + off_Pl + kch*16384);
                    uint64_t dVh = make_desc(base + off_Vh + kch*8192);
                    uint64_t dVl = make_desc(base + off_Vl + kch*8192);
#pragma unroll
                    for (int ks = 0; ks < 4; ks++) {
                        uint64_t o = ks*2;
                        mma_f16_ss(tmemO, dPh+o, dVh+o, IDESC_N64,
                                   (nc > 0 || kch > 0 || ks > 0) ? 1u : 0u);
                        mma_f16_ss(tmemO, dPh+o, dVl+o, IDESC_N64, 1u);
                        mma_f16_ss(tmemO, dPl+o, dVh+o, IDESC_N64, 1u);
                    }
                }
                TCGEN05_COMMIT(mbar_o);
            }
        }
    }
    MBARRIER_WAIT_PARITY(mbar_o, 15 & 1);
    TCGEN05_FENCE_AFTER();

    // epilogue: O (64 cols) -> bf16 split global
    size_t rbase = (size_t)(b*NN + m0 + rrow)*FUSC + h*64 + half*32;
    {
        uint32_t r[32];
        TCGEN05_LD_X32(r, tmemO + half*32);
        TCGEN05_WAIT_LD();
        TCGEN05_FENCE_BEFORE();
#pragma unroll
        for (int j = 0; j < 8; j++) {
            float v0 = __uint_as_float(r[j*4+0]);
            float v1 = __uint_as_float(r[j*4+1]);
            float v2 = __uint_as_float(r[j*4+2]);
            float v3 = __uint_as_float(r[j*4+3]);
            __nv_bfloat16 h0 = __float2bfloat16(v0);
            __nv_bfloat16 h1 = __float2bfloat16(v1);
            __nv_bfloat16 h2 = __float2bfloat16(v2);
            __nv_bfloat16 h3 = __float2bfloat16(v3);
            *(uint2*)(g_Oh + rbase + j*4) = make_uint2(bpackh(h0,h1), bpackh(h2,h3));
            *(uint2*)(g_Ol + rbase + j*4) = make_uint2(
                bpackh(__float2bfloat16(v0 - __bfloat162float(h0)),
                       __float2bfloat16(v1 - __bfloat162float(h1))),
                bpackh(__float2bfloat16(v2 - __bfloat162float(h2)),
                       __float2bfloat16(v3 - __bfloat162float(h3))));
        }
    }
    __syncthreads();
    if (t < 32) TCGEN05_DEALLOC(tmem, 256);
#else
    int t = threadIdx.x;
    int z = blockIdx.y;
    int b = z / HEADS, h = z - b*HEADS;
    int m0 = blockIdx.x * 128;
    if (t >= 128) return;
    int m = m0 + t;
    const float* qp = g_q + ((size_t)(b*NN) + m)*CO + h*32;
    float mxr = g_rowstat[(size_t)(z*NN + m)*2], invr = g_rowstat[(size_t)(z*NN + m)*2+1];
    for (int c = 0; c < 64; c++) {
        float acc = 0.0f;
        for (int n = 0; n < NN; n++) {
            const float* kp = g_k + ((size_t)(b*NN) + n)*CO + h*32;
            float s = 0.0f;
            for (int k = 0; k < 64; k++) s = fmaf(qp[k], kp[k], s);
            acc = fmaf(__expf(s - mxr)*invr, g_v[((size_t)(b*NN) + n)*CO + h*32 + c], acc);
        }
        size_t o = (size_t)(b*NN + m)*FUSC + h*64 + c;
        __nv_bfloat16 hb = __float2bfloat16(acc);
        g_Oh[o] = hb;
        g_Ol[o] = __float2bfloat16(acc - __bfloat162float(hb));
    }
#endif
}

// =====================================================================
// LayerNorm -> bf16 split
// =====================================================================
__global__ void layernorm_kernel(const float* __restrict__ X,
                                 const float* __restrict__ g, const float* __restrict__ b)
{
    int m = blockIdx.x, c = threadIdx.x;
    __shared__ float red[256];
    float v = X[(size_t)m*CO + c];
    red[c] = v; __syncthreads();
    for (int s = 128; s; s >>= 1) { if (c < s) red[c] += red[c+s]; __syncthreads(); }
    float mean = red[0] * (1.0f/CO); __syncthreads();
    float d = v - mean;
    red[c] = d*d; __syncthreads();
    for (int s = 128; s; s >>= 1) { if (c < s) red[c] += red[c+s]; __syncthreads(); }
    float var = red[0] * (1.0f/CO);
    float y = d * rsqrtf(var + EPSB) * g[c] + b[c];
    __nv_bfloat16 hb = __float2bfloat16(y);
    size_t i = (size_t)m*CO + c;
    g_yh[i] = hb;
    g_yl[i] = __float2bfloat16(y - __bfloat162float(hb));
}

// =====================================================================
// final output (transposed)
// =====================================================================
__global__ void final_out(const float* __restrict__ bias, float* __restrict__ out)
{
    __shared__ float tile[32][33];
    int b  = blockIdx.z;
    int n0 = blockIdx.x * 32;
    int c0 = blockIdx.y * 32;
    int tx = threadIdx.x, ty = threadIdx.y;
#pragma unroll
    for (int i = 0; i < 32; i += 8) {
        int n = n0 + ty + i, c = c0 + tx;
        size_t src = ((size_t)b*NN + n)*CO + c;
        tile[ty+i][tx] = g_f2[src] + g_fp[src] + bias[c];
    }
    __syncthreads();
#pragma unroll
    for (int i = 0; i < 32; i += 8) {
        int c = c0 + ty + i, n = n0 + tx;
        out[((size_t)b*CO + c)*NN + n] = tile[tx][ty+i];
    }
}

// =====================================================================
// host
// =====================================================================
extern "C" void kernel_launch(void* const* d_in, const int* in_sizes, int n_in,
                              void* d_out, int out_size)
{
    const float* xyz    = (const float*)d_in[0];
    const float* f      = (const float*)d_in[1];
    const float* W_geo  = (const float*)d_in[2];
    const float* gg     = (const float*)d_in[3];
    const float* bg     = (const float*)d_in[4];
    const float* W_feat = (const float*)d_in[5];
    const float* gf     = (const float*)d_in[6];
    const float* bf     = (const float*)d_in[7];
    const float* g_bn   = (const float*)d_in[8];
    const float* b_bn   = (const float*)d_in[9];
    const float* W_q    = (const float*)d_in[10];
    const float* gq     = (const float*)d_in[11];
    const float* bq     = (const float*)d_in[12];
    const float* W_k    = (const float*)d_in[13];
    const float* gk     = (const float*)d_in[14];
    const float* bk     = (const float*)d_in[15];
    const float* W_v    = (const float*)d_in[16];
    const float* gv     = (const float*)d_in[17];
    const float* bv     = (const float*)d_in[18];
    const float* W_fus  = (const float*)d_in[19];
    /* d_in[20] bias_fus: cancels inside BN */
    const float* gfu    = (const float*)d_in[21];
    const float* bfu    = (const float*)d_in[22];
    const float* g_ln   = (const float*)d_in[23];
    const float* b_ln   = (const float*)d_in[24];
    const float* W_mlp  = (const float*)d_in[25];
    const float* b_mlp  = (const float*)d_in[26];
    float* out = (float*)d_out;

    float *p_act, *p_featv, *p_fp, *p_f2, *p_msc;
    __nv_bfloat16 *p_ginh, *p_ginl, *p_xh, *p_xl, *p_yh, *p_yl, *p_Oh, *p_Ol;
    __nv_bfloat16 *p_wfh, *p_wfl, *p_wfush, *p_wfusl, *p_wmh, *p_wml;
    cudaGetSymbolAddress((void**)&p_act,   g_act);
    cudaGetSymbolAddress((void**)&p_featv, g_featv);
    cudaGetSymbolAddress((void**)&p_fp,    g_fp);
    cudaGetSymbolAddress((void**)&p_f2,    g_f2);
    cudaGetSymbolAddress((void**)&p_msc,   g_msc);
    cudaGetSymbolAddress((void**)&p_ginh,  g_ginh);
    cudaGetSymbolAddress((void**)&p_ginl,  g_ginl);
    cudaGetSymbolAddress((void**)&p_xh,    g_xh);
    cudaGetSymbolAddress((void**)&p_xl,    g_xl);
    cudaGetSymbolAddress((void**)&p_yh,    g_yh);
    cudaGetSymbolAddress((void**)&p_yl,    g_yl);
    cudaGetSymbolAddress((void**)&p_Oh,    g_Oh);
    cudaGetSymbolAddress((void**)&p_Ol,    g_Ol);
    cudaGetSymbolAddress((void**)&p_wfh,   g_wfh);
    cudaGetSymbolAddress((void**)&p_wfl,   g_wfl);
    cudaGetSymbolAddress((void**)&p_wfush, g_wfush);
    cudaGetSymbolAddress((void**)&p_wfusl, g_wfusl);
    cudaGetSymbolAddress((void**)&p_wmh,   g_wmh);
    cudaGetSymbolAddress((void**)&p_wml,   g_wml);

    cudaFuncSetAttribute(attn_stats, cudaFuncAttributeMaxDynamicSharedMemorySize, ST_SMEM);
    cudaFuncSetAttribute(attn_flash, cudaFuncAttributeMaxDynamicSharedMemorySize, FL_SMEM);
    cudaFuncSetAttribute(tgemm,      cudaFuncAttributeMaxDynamicSharedMemorySize, TG_SMEM);
    cudaFuncSetAttribute(qkv_gemm,   cudaFuncAttributeMaxDynamicSharedMemorySize, TG_SMEM);

    // ---- 0. weight splits (one launch)
    split_weights<<<1536, 256>>>(W_feat, W_q, W_k, W_v, W_fus, W_mlp);

    // ---- 1. KNN + transpose + gathers
    knn_kernel<<<MTOT, 256>>>(xyz);
    transpose_f<<<dim3(NN/32, CIN/32, BB), dim3(32,8)>>>(f);
    geo_pre<<<MTOT, 128>>>(xyz, W_geo);
    gather_feat<<<RTOT*32/256, 256>>>();

    // ---- 2. feat GEMM
    tgemm<<<dim3(1, RTOT/128), 256, TG_SMEM>>>(p_ginh, p_ginl, p_wfh, p_wfl,
                                               p_act + 128, 128, 128, CO, 2);

    // ---- 3. branch BN + maxpool
    bn_stats_partial<<<256, 256>>>(p_act, RTOT);
    bn_stats_final<<<1, 256>>>(256, RTOT, p_msc + 0*512);
    branch_apply<<<MTOT, 256>>>(p_msc + 0*512, gg, bg, gf, bf);

    // ---- 4. BatchNorm1d -> x split
    bn_stats_partial<<<32, 256>>>(p_featv, MTOT);
    bn_stats_final<<<1, 256>>>(32, MTOT, p_msc + 1*512);
    bn_apply_split<<<MTOT, 256>>>(p_featv, p_msc + 1*512, g_bn, b_bn, 0, p_xh, p_xl);

    // ---- 5. q/k/v merged GEMM + stats + apply
    qkv_gemm<<<dim3(2, MTOT/128, 3), 256, TG_SMEM>>>();
    bn_stats_qkv<<<dim3(64, 3), 256>>>();
    bn_final_qkv<<<3, 256>>>(p_msc);
    bn_apply_qkv<<<dim3(MTOT*CO/256, 3), 256>>>(p_msc, gq, bq, gk, bk, gv, bv);
    vt_convert<<<dim3(NN/32, 2, BB*HEADS), dim3(32,8)>>>();

    // ---- 6. flash attention (no S materialization)
    attn_stats<<<dim3(16, BB*HEADS), 256, ST_SMEM>>>();
    attn_flash<<<dim3(16, BB*HEADS), 256, FL_SMEM>>>();

    // ---- 7. fus + residual
    tgemm<<<dim3(2, MTOT/128), 256, TG_SMEM>>>(p_Oh, p_Ol, p_wfush, p_wfusl,
                                               p_fp, FUSC, FUSC, CO, 7);
    bn_stats_partial<<<32, 256>>>(p_fp, MTOT);
    bn_stats_final<<<1, 256>>>(32, MTOT, p_msc + 5*512);
    bn_apply<<<MTOT, 256>>>(p_fp, p_f2, p_msc + 5*512, gfu, bfu, p_featv, 1);

    // ---- 8. layernorm + mlp + out
    layernorm_kernel<<<MTOT, 256>>>(p_f2, g_ln, b_ln);
    tgemm<<<dim3(2, MTOT/128), 256, TG_SMEM>>>(p_yh, p_yl, p_wmh, p_wml, p_fp, CO, CO, CO, 4);
    final_out<<<dim3(NN/32, CO/32, BB), dim3(32,8)>>>(b_mlp, out);

    (void)in_sizes; (void)n_in; (void)out_size;
}